// round 6
// baseline (speedup 1.0000x reference)
#include <cuda_runtime.h>
#include <cuda_bf16.h>
#include <math.h>

#define B_ 32
#define T_ 256
#define V_ 10000
#define E_ 256
#define H_ 512
#define N_ 128
#define WD_ 64
#define R_ 4
#define IFACE_ 471
#define G4H 2048          // 4*H
#define KU 768            // H + R*WD
#define BT_ (B_*T_)       // 8192
#define EPSF 1e-6f
#define NBLK 128
#define THR 512

typedef unsigned long long ull;

// ---------------- f32x2 helpers ----------------
__device__ __forceinline__ ull pack2(float x, float y){
    ull r; asm("mov.b64 %0, {%1,%2};" : "=l"(r) : "r"(__float_as_uint(x)), "r"(__float_as_uint(y))); return r;
}
__device__ __forceinline__ ull splat2f(float x){ return pack2(x, x); }
__device__ __forceinline__ float2 unpack2(ull v){
    unsigned lo, hi;
    asm("mov.b64 {%0,%1}, %2;" : "=r"(lo), "=r"(hi) : "l"(v));
    return make_float2(__uint_as_float(lo), __uint_as_float(hi));
}
__device__ __forceinline__ void ffma2(ull& d, ull a, ull b){
    asm("fma.rn.f32x2 %0, %1, %2, %0;" : "+l"(d) : "l"(a), "l"(b));
}
__device__ __forceinline__ void fadd2(ull& d, ull a){
    asm("add.rn.f32x2 %0, %0, %1;" : "+l"(d) : "l"(a));
}
__device__ __forceinline__ unsigned smem_u32p(const void* p){
    return (unsigned)__cvta_generic_to_shared(p);
}
__device__ __forceinline__ void cpasync16(unsigned dst, const void* src){
    asm volatile("cp.async.cg.shared.global [%0], [%1], 16;" :: "r"(dst), "l"(src));
}

// ---------------- device scratch ----------------
__device__ __align__(128) float g_X[BT_*E_];
__device__ __align__(128) float g_G0[(size_t)BT_*G4H];
__device__ __align__(128) float g_WihT[E_*G4H];               // permuted cols
__device__ __align__(128) float g_Wt[KU*G4H];                 // permuted cols: [rv ; h]
__device__ __align__(128) float g_bl[G4H];                    // permuted bias
__device__ __align__(128) float g_WifT[IFACE_*H_];            // W_iface transposed [col][k]
__device__ __align__(128) __nv_bfloat16 g_Whi[(size_t)KU*V_];
__device__ __align__(128) __nv_bfloat16 g_Wlo[(size_t)KU*V_];
__device__ __align__(128) __nv_bfloat16 g_Uhi[(size_t)BT_*KU];
__device__ __align__(128) __nv_bfloat16 g_Ulo[(size_t)BT_*KU];
__device__ __align__(128) float g_in[2][KU*B_];               // rows 0-255: rv, 256-767: h
__device__ volatile unsigned g_flags[NBLK*32];                // padded to 128B
__device__ volatile unsigned g_gen;

__device__ __forceinline__ float sigf(float x){ return 1.f/(1.f + expf(-x)); }
__device__ __forceinline__ float splusf(float x){ return fmaxf(x,0.f) + log1pf(expf(-fabsf(x))); }

// ---------------- flag-based grid barrier ----------------
__device__ __forceinline__ void gridbar(unsigned ep){
    __syncthreads();
    const int tid = threadIdx.x;
    const int bx  = blockIdx.x;
    if (tid == 0){
        __threadfence();
        g_flags[bx*32] = ep;
    }
    if (bx == 0){
        if (tid < NBLK){
            while (g_flags[tid*32] < ep) { }
        }
        __syncthreads();
        if (tid == 0){
            __threadfence();
            g_gen = ep;
        }
    } else {
        if (tid == 0){
            while (g_gen < ep) { }
            __threadfence();
        }
    }
    __syncthreads();
}

// ---------------- prep kernels ----------------
__global__ void embed_kernel(const int* __restrict__ tok, const float* __restrict__ emb){
    int i = blockIdx.x*256 + threadIdx.x;
    if (i >= BT_*E_) return;
    int bt = i / E_, e = i % E_;
    g_X[i] = tanhf(emb[(size_t)tok[bt]*E_ + e]);
}

__global__ void prep_w(const float* __restrict__ w_ih, const float* __restrict__ w_hh,
                       const float* __restrict__ b_lstm, const float* __restrict__ W_iface){
    int i = blockIdx.x*256 + threadIdx.x;
    if (i < KU*G4H){
        int k = i >> 11, col = i & 2047;
        int jj = col >> 2, g = col & 3;
        int j = g*H_ + jj;
        g_Wt[i] = (k < R_*WD_) ? w_ih[(size_t)j*(E_+R_*WD_) + E_ + k]
                               : w_hh[(size_t)j*H_ + (k - R_*WD_)];
    }
    if (i < E_*G4H){
        int e = i >> 11, col = i & 2047;
        int jj = col >> 2, g = col & 3;
        int j = g*H_ + jj;
        g_WihT[i] = w_ih[(size_t)j*(E_+R_*WD_) + e];
    }
    if (i < G4H){
        int jj = i >> 2, g = i & 3;
        g_bl[i] = b_lstm[g*H_ + jj];
    }
    if (i < IFACE_*H_){
        int c = i >> 9, k = i & 511;
        g_WifT[i] = W_iface[(size_t)k*IFACE_ + c];
    }
}

__global__ void prep_out(const float* __restrict__ W_out){
    int i = blockIdx.x*256 + threadIdx.x;
    if (i >= KU*V_) return;
    float v = W_out[i];
    __nv_bfloat16 h = __float2bfloat16(v);
    g_Whi[i] = h;
    g_Wlo[i] = __float2bfloat16(v - __bfloat162float(h));
}

__global__ void zero_state(){
    int i0 = blockIdx.x*blockDim.x + threadIdx.x;
    int stride = gridDim.x*blockDim.x;
    for (int k=i0;k<2*KU*B_;k+=stride) g_in[0][k] = 0.f;
    for (int k=i0;k<NBLK*32;k+=stride) g_flags[k] = 0u;
    if (i0 == 0) g_gen = 0u;
}

// ---------------- pipelined fp32 SGEMM (R4 version): C = A(MxK)@B(KxN) (+bias) ----------------
__global__ __launch_bounds__(256) void sgemm128(const float* __restrict__ A,
                         const float* __restrict__ Bm,
                         const float* __restrict__ bias, float* __restrict__ C,
                         int M, int Nn, int K){
    __shared__ float As[2][8][128];
    __shared__ float Bs[2][8][128];
    int tid = threadIdx.x;
    int row0 = blockIdx.y*128, col0 = blockIdx.x*128;
    int trow = (tid >> 4) * 8;
    int tcol = (tid & 15) * 8;
    float acc[8][8];
    #pragma unroll
    for (int i=0;i<8;i++)
        #pragma unroll
        for (int j=0;j<8;j++) acc[i][j]=0.f;

    int arow = tid >> 1, ak = (tid & 1)*4;
    int bk = tid >> 5,  bn = (tid & 31)*4;
    const float* Aptr = A + (size_t)(row0 + arow)*K + ak;
    int gn = col0 + bn;

    float4 av = *(const float4*)(Aptr);
    float4 bv = make_float4(0.f,0.f,0.f,0.f);
    if (gn < Nn) bv = *(const float4*)(Bm + (size_t)bk*Nn + gn);
    As[0][ak+0][arow]=av.x; As[0][ak+1][arow]=av.y; As[0][ak+2][arow]=av.z; As[0][ak+3][arow]=av.w;
    *(float4*)(&Bs[0][bk][bn]) = bv;
    __syncthreads();

    int buf = 0;
    for (int k0=0;k0<K;k0+=8){
        bool more = (k0 + 8) < K;
        if (more){
            av = *(const float4*)(Aptr + k0 + 8);
            bv = make_float4(0.f,0.f,0.f,0.f);
            if (gn < Nn) bv = *(const float4*)(Bm + (size_t)(k0+8+bk)*Nn + gn);
        }
        #pragma unroll
        for (int kk=0;kk<8;kk++){
            float ar[8], br[8];
            *(float4*)(ar)   = *(const float4*)(&As[buf][kk][trow]);
            *(float4*)(ar+4) = *(const float4*)(&As[buf][kk][trow+4]);
            *(float4*)(br)   = *(const float4*)(&Bs[buf][kk][tcol]);
            *(float4*)(br+4) = *(const float4*)(&Bs[buf][kk][tcol+4]);
            #pragma unroll
            for (int i=0;i<8;i++)
                #pragma unroll
                for (int j=0;j<8;j++) acc[i][j] += ar[i]*br[j];
        }
        if (more){
            int nb = buf ^ 1;
            As[nb][ak+0][arow]=av.x; As[nb][ak+1][arow]=av.y; As[nb][ak+2][arow]=av.z; As[nb][ak+3][arow]=av.w;
            *(float4*)(&Bs[nb][bk][bn]) = bv;
            __syncthreads();
            buf = nb;
        }
    }
    #pragma unroll
    for (int i=0;i<8;i++){
        size_t gm = (size_t)(row0 + trow + i);
        #pragma unroll
        for (int j=0;j<8;j+=4){
            int gnn = col0 + tcol + j;
            if (gnn < Nn){
                float4 v = make_float4(acc[i][j],acc[i][j+1],acc[i][j+2],acc[i][j+3]);
                if (bias){ v.x+=bias[gnn]; v.y+=bias[gnn+1]; v.z+=bias[gnn+2]; v.w+=bias[gnn+3]; }
                *(float4*)(C + gm*Nn + gnn) = v;
            }
        }
    }
}

// ---------------- bf16-split tensor-core GEMM: out = U@W_out + b ----------------
// C(8192x10000) = Uhi*Whi + Uhi*Wlo + Ulo*Whi, fp32 accum. 128x128x32 tiles.
#define PITCH 40   // bf16 elems per smem row (80B, 16B-aligned, conflict-free frags)
#define TILE_BF (128*PITCH)

__device__ __forceinline__ void mma_bf16(float* c, unsigned a0,unsigned a1,unsigned a2,unsigned a3,
                                         unsigned b0, unsigned b1){
    asm volatile("mma.sync.aligned.m16n8k16.row.col.f32.bf16.bf16.f32 "
        "{%0,%1,%2,%3}, {%4,%5,%6,%7}, {%8,%9}, {%0,%1,%2,%3};"
        : "+f"(c[0]),"+f"(c[1]),"+f"(c[2]),"+f"(c[3])
        : "r"(a0),"r"(a1),"r"(a2),"r"(a3),"r"(b0),"r"(b1));
}

__global__ __launch_bounds__(256) void gemm_out(const float* __restrict__ bias,
                                                float* __restrict__ C){
    extern __shared__ __align__(16) char smraw[];
    __nv_bfloat16* AsHi = (__nv_bfloat16*)smraw;
    __nv_bfloat16* AsLo = AsHi + 2*TILE_BF;
    __nv_bfloat16* BsHi = AsLo + 2*TILE_BF;
    __nv_bfloat16* BsLo = BsHi + 2*TILE_BF;

    const int tid = threadIdx.x, lane = tid & 31, wid = tid >> 5;
    const int warp_m = wid >> 2, warp_n = wid & 3;
    const int gid = lane >> 2, tig = lane & 3;
    const int m0 = blockIdx.y*128, n0 = blockIdx.x*128;

    float acc[4][4][4];
    #pragma unroll
    for (int i=0;i<4;i++)
        #pragma unroll
        for (int j=0;j<4;j++)
            #pragma unroll
            for (int q=0;q<4;q++) acc[i][j][q]=0.f;

    unsigned sAhi = smem_u32p(AsHi), sAlo = smem_u32p(AsLo);

    uint4 rbh[2], rbl[2];
    const uint4 z4 = make_uint4(0u,0u,0u,0u);

    // --- stage loaders ---
    auto loadA = [&](int s, int kt){
        #pragma unroll
        for (int it=0; it<2; it++){
            int idx = it*256 + tid;
            int row = idx>>2, seg = idx&3;
            size_t goff = (size_t)(m0+row)*KU + kt*32 + seg*8;
            unsigned doff = (unsigned)((s*TILE_BF + row*PITCH + seg*8)*2);
            cpasync16(sAhi + doff, g_Uhi + goff);
            cpasync16(sAlo + doff, g_Ulo + goff);
        }
        asm volatile("cp.async.commit_group;");
    };
    auto loadBregs = [&](int kt){
        #pragma unroll
        for (int it=0; it<2; it++){
            int idx = it*256 + tid;
            int krow = idx>>4, seg = idx&15;
            int gnb = n0 + seg*8;
            size_t goff = (size_t)(kt*32+krow)*V_ + gnb;
            bool ok = gnb < V_;
            rbh[it] = ok ? *(const uint4*)(g_Whi + goff) : z4;
            rbl[it] = ok ? *(const uint4*)(g_Wlo + goff) : z4;
        }
    };
    auto stsB = [&](int s){
        #pragma unroll
        for (int it=0; it<2; it++){
            int idx = it*256 + tid;
            int krow = idx>>4, seg = idx&15;
            __nv_bfloat16 th[8], tl[8];
            *(uint4*)th = rbh[it];
            *(uint4*)tl = rbl[it];
            #pragma unroll
            for (int q=0;q<8;q++){
                BsHi[s*TILE_BF + (seg*8+q)*PITCH + krow] = th[q];
                BsLo[s*TILE_BF + (seg*8+q)*PITCH + krow] = tl[q];
            }
        }
    };
    auto compute = [&](int s){
        #pragma unroll
        for (int kk=0;kk<2;kk++){
            const int kb = kk*16 + tig*2;
            unsigned bh[4][2], bl[4][2];
            #pragma unroll
            for (int j=0;j<4;j++){
                int nl = warp_n*32 + j*8 + gid;
                const __nv_bfloat16* bp  = BsHi + s*TILE_BF + nl*PITCH + kb;
                const __nv_bfloat16* bp2 = BsLo + s*TILE_BF + nl*PITCH + kb;
                bh[j][0] = *(const unsigned*)bp;   bh[j][1] = *(const unsigned*)(bp+8);
                bl[j][0] = *(const unsigned*)bp2;  bl[j][1] = *(const unsigned*)(bp2+8);
            }
            #pragma unroll
            for (int i=0;i<4;i++){
                int mr = warp_m*64 + i*16;
                const __nv_bfloat16* ap  = AsHi + s*TILE_BF + (mr+gid)*PITCH + kb;
                const __nv_bfloat16* ap2 = AsLo + s*TILE_BF + (mr+gid)*PITCH + kb;
                unsigned ah0 = *(const unsigned*)ap;
                unsigned ah1 = *(const unsigned*)(ap + 8*PITCH);
                unsigned ah2 = *(const unsigned*)(ap + 8);
                unsigned ah3 = *(const unsigned*)(ap + 8*PITCH + 8);
                unsigned al0 = *(const unsigned*)ap2;
                unsigned al1 = *(const unsigned*)(ap2 + 8*PITCH);
                unsigned al2 = *(const unsigned*)(ap2 + 8);
                unsigned al3 = *(const unsigned*)(ap2 + 8*PITCH + 8);
                #pragma unroll
                for (int j=0;j<4;j++){
                    mma_bf16(acc[i][j], ah0,ah1,ah2,ah3, bh[j][0],bh[j][1]);
                    mma_bf16(acc[i][j], ah0,ah1,ah2,ah3, bl[j][0],bl[j][1]);
                    mma_bf16(acc[i][j], al0,al1,al2,al3, bh[j][0],bh[j][1]);
                }
            }
        }
    };

    // --- pipeline ---
    loadA(0, 0);
    loadBregs(0);
    stsB(0);
    asm volatile("cp.async.wait_group 0;");
    __syncthreads();

    const int KT = KU/32;   // 24
    for (int kt=0; kt<KT; kt++){
        int buf = kt & 1;
        if (kt+1 < KT){
            loadA(buf^1, kt+1);
            loadBregs(kt+1);
        }
        compute(buf);
        if (kt+1 < KT){
            stsB(buf^1);
            asm volatile("cp.async.wait_group 0;");
        }
        __syncthreads();
    }

    // --- epilogue ---
    #pragma unroll
    for (int i=0;i<4;i++){
        int gm = m0 + warp_m*64 + i*16 + gid;
        #pragma unroll
        for (int j=0;j<4;j++){
            int gn = n0 + warp_n*32 + j*8 + tig*2;
            if (gn < V_){
                float b0 = bias[gn], b1 = bias[gn+1];
                *(float2*)(C + (size_t)gm*V_ + gn) = make_float2(acc[i][j][0]+b0, acc[i][j][1]+b1);
                *(float2*)(C + (size_t)(gm+8)*V_ + gn) = make_float2(acc[i][j][2]+b0, acc[i][j][3]+b1);
            }
        }
    }
}

// ---------------- persistent sequential loop ----------------
// smem floats: W_A 12288 | scr 8192 | hb 512 | DNC 29064  = 50056 floats = 200224 B
#define LOOP_SMEM_FLOATS (12288 + 8192 + 512 + 29064)

__global__ __launch_bounds__(THR) void loop_kernel(const float* __restrict__ b_iface){
    extern __shared__ float sm[];
    float* W_A  = sm;                  // 768*16
    float* scr  = W_A + 12288;         // 8192
    float* hb   = scr + 8192;          // 512
    float* M_s  = hb + 512;            // 128*65
    float* L_s  = M_s + 8320;          // 128*129
    float* wr_s = L_s + 16512;         // 512
    float* u_s  = wr_s + 512;          // 128
    float* p_s  = u_s + 128;           // 128
    float* ww_s = p_s + 128;           // 128
    float* xi   = ww_s + 128;          // 472
    float* fwdw = xi + 472;            // 512
    float* bwdw = fwdw + 512;          // 512
    float* crs  = bwdw + 512;          // 512
    float* unew = crs + 512;           // 128
    float* srt  = unew + 128;          // 128
    float* incl = srt + 128;           // 128
    float* cpex = incl + 128;          // 128
    float* a_s  = cpex + 128;          // 128
    float* wwn  = a_s + 128;           // 128
    float* Mn   = wwn + 128;           // 128
    float* red  = Mn + 128;            // 128
    float* act  = red + 128;           // 176
    int* rank_s = (int*)(act + 176);   // 128

    const int tid  = threadIdx.x;
    const int bx   = blockIdx.x;
    const int wid  = tid >> 5;         // 0..15
    const int lane = tid & 31;
    const int b    = bx;

    // ---- stage LSTM weights into smem (once) ----
    for (int i=tid;i<768*16;i+=THR){
        int k = i >> 4, c = i & 15;
        W_A[i] = g_Wt[(size_t)k*G4H + bx*16 + c];
    }
    // ---- init persistent DNC state ----
    if (bx < B_){
        for (int i=tid;i<128*65;i+=THR)  M_s[i]=0.f;
        for (int i=tid;i<128*129;i+=THR) L_s[i]=0.f;
        for (int i=tid;i<512;i+=THR)     wr_s[i]=0.f;
        if (tid < N_){ u_s[tid]=0.f; p_s[tid]=0.f; ww_s[tid]=0.f; }
    }
    __syncthreads();

    float c_reg = 0.f;   // LSTM cell state: threads tid<128 own (unit=tid>>5, batch=lane)
    unsigned ep = 0;
    ull* scr2 = (ull*)scr;

    for (int t=0;t<T_;t++){
        const int rd = t & 1, wrb = rd ^ 1;
        const float* in_rd = g_in[rd];
        float* in_wr = g_in[wrb];

        // ================= Phase A: LSTM gemm (split-K over 16 warps, f32x2) =================
        {
            const int kbeg = wid*48;
            float a_loc[48];
            #pragma unroll
            for (int k=0;k<48;k++) a_loc[k] = in_rd[(kbeg+k)*B_ + lane];
            ull acc2[8];
            #pragma unroll
            for (int c=0;c<8;c++) acc2[c]=0ull;
            #pragma unroll 4
            for (int k=0;k<48;k++){
                ull as = splat2f(a_loc[k]);
                const ulonglong2* wp = (const ulonglong2*)(W_A + (kbeg+k)*16);
                ulonglong2 w01 = wp[0], w23 = wp[1], w45 = wp[2], w67 = wp[3];
                ffma2(acc2[0], as, w01.x); ffma2(acc2[1], as, w01.y);
                ffma2(acc2[2], as, w23.x); ffma2(acc2[3], as, w23.y);
                ffma2(acc2[4], as, w45.x); ffma2(acc2[5], as, w45.y);
                ffma2(acc2[6], as, w67.x); ffma2(acc2[7], as, w67.y);
            }
            #pragma unroll
            for (int c=0;c<8;c++) scr2[wid*256 + c*32 + lane] = acc2[c];
        }
        __syncthreads();
        if (tid < 128){
            int uu = tid >> 5;
            float4 s = *(const float4*)(g_G0 + ((size_t)lane*T_ + t)*G4H + bx*16 + uu*4);
            ull s01 = pack2(s.x, s.y), s23 = pack2(s.z, s.w);
            #pragma unroll
            for (int w16=0;w16<16;w16++){
                fadd2(s01, scr2[w16*256 + (2*uu  )*32 + lane]);
                fadd2(s23, scr2[w16*256 + (2*uu+1)*32 + lane]);
            }
            float2 g01 = unpack2(s01), g23 = unpack2(s23);
            float c = sigf(g01.y)*c_reg + sigf(g01.x)*tanhf(g23.x);
            float h = sigf(g23.y)*tanhf(c);
            c_reg = c;
            int jj = bx*4 + uu;
            in_wr[(256 + jj)*B_ + lane] = h;
            size_t btrow = (size_t)lane*T_ + t;
            __nv_bfloat16 hh = __float2bfloat16(h);
            g_Uhi[btrow*KU + jj] = hh;
            g_Ulo[btrow*KU + jj] = __float2bfloat16(h - __bfloat162float(hh));
        }
        gridbar(++ep);

        // ================= Phase D: iface + DNC memory step (blocks 0..31) =================
        if (bx < B_){
            // stage h for this batch
            hb[tid] = in_wr[(256 + tid)*B_ + b];
            __syncthreads();

            // xi = h @ W_iface + b_iface (one col per thread, weights from L2)
            if (tid < IFACE_){
                float acc0 = b_iface[tid], acc1=0.f, acc2v=0.f, acc3=0.f;
                const float4* wp = (const float4*)(g_WifT + (size_t)tid*H_);
                const float4* hb4 = (const float4*)hb;
                #pragma unroll 4
                for (int k4=0;k4<H_/4;k4++){
                    float4 w = wp[k4];
                    float4 hv = hb4[k4];
                    acc0 += hv.x*w.x; acc1 += hv.y*w.y; acc2v += hv.z*w.z; acc3 += hv.w*w.w;
                }
                xi[tid] = (acc0+acc1) + (acc2v+acc3);
            }
            __syncthreads();

            // activations
            if (tid < 64){
                act[8+tid]  = sigf(xi[325+tid]);   // er
                act[72+tid] = xi[389+tid];         // wv
            } else if (tid < 68){
                act[tid-64] = 1.f + splusf(xi[256 + (tid-64)]);  // rb
            } else if (tid == 68){
                act[4] = 1.f + splusf(xi[324]);                  // wb
            } else if (tid < 73){
                act[136 + (tid-69)] = sigf(xi[453 + (tid-69)]);  // fg
            } else if (tid == 73){
                act[140] = sigf(xi[457]);                        // ga
            } else if (tid == 74){
                act[141] = sigf(xi[458]);                        // gw
            } else if (tid < 79){                                // pi softmax
                int r = tid - 75;
                float q0=xi[459+r*3], q1=xi[459+r*3+1], q2=xi[459+r*3+2];
                float m = fmaxf(q0, fmaxf(q1,q2));
                float e0=expf(q0-m), e1=expf(q1-m), e2=expf(q2-m);
                float s = e0+e1+e2;
                act[144+r*3]=e0/s; act[145+r*3]=e1/s; act[146+r*3]=e2/s;
            } else if (tid < 83){                                // ||rk[r]||
                int r = tid - 79; float s = 0.f;
                #pragma unroll 8
                for (int w=0;w<WD_;w++){ float v = xi[r*WD_+w]; s += v*v; }
                act[156+r] = sqrtf(s);
            } else if (tid == 83){                               // ||wk||
                float s = 0.f;
                #pragma unroll 8
                for (int w=0;w<WD_;w++){ float v = xi[260+w]; s += v*v; }
                act[160] = sqrtf(s);
            }
            __syncthreads();

            // retention / usage
            if (tid < N_){
                float psi = 1.f;
                #pragma unroll
                for (int r=0;r<R_;r++) psi *= (1.f - act[136+r]*wr_s[r*N_+tid]);
                float uo=u_s[tid], wo=ww_s[tid];
                unew[tid] = (uo + wo - uo*wo)*psi;
            }
            __syncthreads();

            // stable ascending argsort via ranks
            if (tid < N_){
                float ui = unew[tid]; int rk = 0;
                #pragma unroll 8
                for (int j=0;j<N_;j++){
                    float uj = unew[j];
                    rk += (uj < ui) || (uj == ui && j < tid);
                }
                rank_s[tid] = rk;
                srt[rk] = ui;
            }
            __syncthreads();

            // parallel cumprod of srt (exclusive) -> cpex
            float cp_p = 1.f;
            if (tid < N_){
                int w4 = tid >> 5, ln = tid & 31;
                cp_p = srt[tid];
                #pragma unroll
                for (int off=1;off<32;off<<=1){
                    float o = __shfl_up_sync(0xffffffffu, cp_p, off);
                    if (ln >= off) cp_p *= o;
                }
                if (ln == 31) red[w4] = cp_p;
            }
            __syncthreads();
            if (tid < N_){
                int w4 = tid >> 5;
                float pre = 1.f;
                #pragma unroll
                for (int j=0;j<3;j++) if (j < w4) pre *= red[j];
                incl[tid] = cp_p * pre;
            }
            __syncthreads();
            if (tid < N_) cpex[tid] = (tid == 0) ? 1.f : incl[tid-1];
            __syncthreads();

            // allocation + write content score (old M)
            float score_w = 0.f, ew = 0.f;
            if (tid < N_){
                a_s[tid] = (1.f - unew[tid]) * cpex[rank_s[tid]];
                float s2=0.f, dot=0.f;
                #pragma unroll 8
                for (int w=0;w<WD_;w++){ float m = M_s[tid*65+w]; s2 += m*m; dot += m*xi[260+w]; }
                score_w = act[4] * (dot / (act[160]*sqrtf(s2) + EPSF));
                float v = score_w;
                #pragma unroll
                for (int o=16;o;o>>=1) v = fmaxf(v, __shfl_xor_sync(0xffffffffu, v, o));
                if ((tid&31)==0) red[tid>>5] = v;
            }
            __syncthreads();
            float mxw = fmaxf(fmaxf(red[0],red[1]), fmaxf(red[2],red[3]));
            if (tid < N_){
                ew = expf(score_w - mxw);
                float s = ew;
                #pragma unroll
                for (int o=16;o;o>>=1) s += __shfl_xor_sync(0xffffffffu, s, o);
                if ((tid&31)==0) red[4 + (tid>>5)] = s;
            }
            __syncthreads();
            float sden = red[4]+red[5]+red[6]+red[7];
            if (tid < N_){
                float wv = act[141]*(act[140]*a_s[tid] + (1.f-act[140])*(ew/sden));
                wwn[tid] = wv;
                float s = wv;
                #pragma unroll
                for (int o=16;o;o>>=1) s += __shfl_xor_sync(0xffffffffu, s, o);
                if ((tid&31)==0) red[8 + (tid>>5)] = s;
            }
            __syncthreads();
            float sumww = red[8]+red[9]+red[10]+red[11];

            // memory write (new M)
            for (int i=tid;i<N_*WD_;i+=THR){
                int n=i>>6, w=i&63;
                float wwv = wwn[n];
                M_s[n*65+w] = M_s[n*65+w]*(1.f - wwv*act[8+w]) + wwv*act[72+w];
            }
            // temporal link update (old p)
            for (int i=tid;i<N_*N_;i+=THR){
                int n=i>>7, m=i&127;
                float v = (n==m) ? 0.f
                         : (1.f - wwn[n] - wwn[m])*L_s[n*129+m] + wwn[n]*p_s[m];
                L_s[n*129+m] = v;
            }
            __syncthreads();
            if (tid < N_) p_s[tid] = (1.f - sumww)*p_s[tid] + wwn[tid];

            // forward/backward weights (new L, old wr): one output per thread
            {
                int r = tid>>7, n = tid&127;
                float f=0.f, bw=0.f;
                const float* wrr = wr_s + r*N_;
                #pragma unroll 8
                for (int m=0;m<N_;m++){
                    float wv = wrr[m];
                    f  += L_s[n*129+m]*wv;
                    bw += L_s[m*129+n]*wv;
                }
                fwdw[tid]=f; bwdw[tid]=bw;
            }
            // read content scores (new M)
            if (tid < N_){
                float s2=0.f;
                #pragma unroll 8
                for (int w=0;w<WD_;w++){ float m=M_s[tid*65+w]; s2 += m*m; }
                Mn[tid] = sqrtf(s2);
            }
            __syncthreads();
            if (tid < N_){
                #pragma unroll
                for (int r=0;r<R_;r++){
                    float dot=0.f;
                    #pragma unroll 8
                    for (int w=0;w<WD_;w++) dot += M_s[tid*65+w]*xi[r*WD_+w];
                    crs[r*N_+tid] = act[r]*(dot/(act[156+r]*Mn[tid] + EPSF));
                }
            }
            __syncthreads();
            if (tid < 128){
                int r = tid>>5, ln = tid&31;
                float v = fmaxf(fmaxf(crs[r*N_+ln],crs[r*N_+ln+32]),
                                fmaxf(crs[r*N_+ln+64],crs[r*N_+ln+96]));
                #pragma unroll
                for (int o=16;o;o>>=1) v = fmaxf(v, __shfl_xor_sync(0xffffffffu, v, o));
                if (ln==0) act[164+r]=v;
            }
            __syncthreads();
            if (tid < 128){
                int r = tid>>5, ln = tid&31;
                float m = act[164+r];
                float e0=expf(crs[r*N_+ln   ]-m);
                float e1=expf(crs[r*N_+ln+32]-m);
                float e2=expf(crs[r*N_+ln+64]-m);
                float e3=expf(crs[r*N_+ln+96]-m);
                crs[r*N_+ln]=e0; crs[r*N_+ln+32]=e1; crs[r*N_+ln+64]=e2; crs[r*N_+ln+96]=e3;
                float s = e0+e1+e2+e3;
                #pragma unroll
                for (int o=16;o;o>>=1) s += __shfl_xor_sync(0xffffffffu, s, o);
                if (ln==0) act[168+r]=s;
            }
            __syncthreads();
            // new read weights
            for (int i=tid;i<R_*N_;i+=THR){
                int r = i>>7;
                float w = act[144+r*3]*bwdw[i] + act[145+r*3]*(crs[i]/act[168+r]) + act[146+r*3]*fwdw[i];
                crs[i] = w;
            }
            __syncthreads();
            // read vectors rv = wr @ M
            if (tid < R_*WD_){
                int r = tid>>6, w = tid&63;
                float s=0.f;
                #pragma unroll 8
                for (int n=0;n<N_;n++) s += crs[r*N_+n]*M_s[n*65+w];
                in_wr[tid*B_ + b] = s;
                size_t btrow = (size_t)b*T_ + t;
                __nv_bfloat16 sh = __float2bfloat16(s);
                g_Uhi[btrow*KU + H_ + tid] = sh;
                g_Ulo[btrow*KU + H_ + tid] = __float2bfloat16(s - __bfloat162float(sh));
            }
            __syncthreads();
            // persist state
            for (int i=tid;i<R_*N_;i+=THR) wr_s[i] = crs[i];
            if (tid < N_){ u_s[tid]=unew[tid]; ww_s[tid]=wwn[tid]; }
        }
        gridbar(++ep);
    }
}

// ---------------- launcher ----------------
extern "C" void kernel_launch(void* const* d_in, const int* in_sizes, int n_in,
                              void* d_out, int out_size){
    const int*   tokens  = (const int*)  d_in[0];
    const float* emb     = (const float*)d_in[1];
    const float* w_ih    = (const float*)d_in[2];
    const float* w_hh    = (const float*)d_in[3];
    const float* b_lstm  = (const float*)d_in[4];
    const float* W_iface = (const float*)d_in[5];
    const float* b_iface = (const float*)d_in[6];
    const float* W_out   = (const float*)d_in[7];
    const float* b_out   = (const float*)d_in[8];
    float* out = (float*)d_out;

    const int loop_smem = LOOP_SMEM_FLOATS * (int)sizeof(float);
    cudaFuncSetAttribute(loop_kernel, cudaFuncAttributeMaxDynamicSharedMemorySize, loop_smem);
    const int gout_smem = 8 * TILE_BF * (int)sizeof(__nv_bfloat16);
    cudaFuncSetAttribute(gemm_out, cudaFuncAttributeMaxDynamicSharedMemorySize, gout_smem);

    void *pX, *pG0, *pWihT, *pBl;
    cudaGetSymbolAddress(&pX, g_X);
    cudaGetSymbolAddress(&pG0, g_G0);
    cudaGetSymbolAddress(&pWihT, g_WihT);
    cudaGetSymbolAddress(&pBl, g_bl);

    embed_kernel<<<(BT_*E_ + 255)/256, 256>>>(tokens, emb);
    prep_w<<<(KU*G4H + 255)/256, 256>>>(w_ih, w_hh, b_lstm, W_iface);
    prep_out<<<(KU*V_ + 255)/256, 256>>>(W_out);
    zero_state<<<64, 256>>>();

    // G0 = X (8192x256) @ WihT (256x2048) + permuted bias
    sgemm128<<<dim3(G4H/128, BT_/128), 256>>>((const float*)pX, (const float*)pWihT,
                                              (const float*)pBl, (float*)pG0, BT_, G4H, E_);

    loop_kernel<<<NBLK, THR, loop_smem>>>(b_iface);

    // out = U (8192x768) @ W_out (768x10000) + b_out   [bf16-split tensor cores]
    gemm_out<<<dim3((V_+127)/128, BT_/128), 256, gout_smem>>>(b_out, out);
}

// round 7
// speedup vs baseline: 1.6909x; 1.6909x over previous
#include <cuda_runtime.h>
#include <cuda_bf16.h>
#include <math.h>

#define B_ 32
#define T_ 256
#define V_ 10000
#define VPAD 10112
#define E_ 256
#define H_ 512
#define N_ 128
#define WD_ 64
#define R_ 4
#define IFACE_ 471
#define G4H 2048          // 4*H
#define KU 768            // H + R*WD
#define BT_ (B_*T_)       // 8192
#define EPSF 1e-6f
#define NBLK 128
#define THR 512

typedef unsigned long long ull;

// ---------------- f32x2 helpers ----------------
__device__ __forceinline__ ull pack2(float x, float y){
    ull r; asm("mov.b64 %0, {%1,%2};" : "=l"(r) : "r"(__float_as_uint(x)), "r"(__float_as_uint(y))); return r;
}
__device__ __forceinline__ ull splat2f(float x){ return pack2(x, x); }
__device__ __forceinline__ float2 unpack2(ull v){
    unsigned lo, hi;
    asm("mov.b64 {%0,%1}, %2;" : "=r"(lo), "=r"(hi) : "l"(v));
    return make_float2(__uint_as_float(lo), __uint_as_float(hi));
}
__device__ __forceinline__ void ffma2(ull& d, ull a, ull b){
    asm("fma.rn.f32x2 %0, %1, %2, %0;" : "+l"(d) : "l"(a), "l"(b));
}
__device__ __forceinline__ void fadd2(ull& d, ull a){
    asm("add.rn.f32x2 %0, %0, %1;" : "+l"(d) : "l"(a));
}
__device__ __forceinline__ void cpasync16(unsigned dst, const void* src){
    asm volatile("cp.async.cg.shared.global [%0], [%1], 16;" :: "r"(dst), "l"(src));
}

// ---------------- device scratch ----------------
__device__ __align__(128) float g_X[BT_*E_];
__device__ __align__(128) float g_G0[(size_t)BT_*G4H];
__device__ __align__(128) float g_WihT[E_*G4H];               // permuted cols
__device__ __align__(128) float g_Wt[KU*G4H];                 // permuted cols: [rv ; h]
__device__ __align__(128) float g_bl[G4H];                    // permuted bias
__device__ __align__(128) __nv_bfloat16 g_WhiT[(size_t)VPAD*KU];  // W_out^T hi
__device__ __align__(128) __nv_bfloat16 g_WloT[(size_t)VPAD*KU];  // W_out^T lo
__device__ __align__(128) __nv_bfloat16 g_Uhi[(size_t)BT_*KU];
__device__ __align__(128) __nv_bfloat16 g_Ulo[(size_t)BT_*KU];
__device__ __align__(128) float g_hT[2][H_*B_];               // double-buffered [feat][batch]
__device__ __align__(128) float g_rvT[R_*WD_*B_];
__device__ __align__(128) float g_xiT[IFACE_*B_];
__device__ volatile unsigned g_flags[NBLK*32];                // padded
__device__ volatile unsigned g_gen;

__device__ __forceinline__ float sigf(float x){ return 1.f/(1.f + expf(-x)); }
__device__ __forceinline__ float splusf(float x){ return fmaxf(x,0.f) + log1pf(expf(-fabsf(x))); }

// ---------------- flag-based grid barrier ----------------
__device__ __forceinline__ void gridbar(unsigned ep){
    __syncthreads();
    const int tid = threadIdx.x;
    const int bx  = blockIdx.x;
    if (tid == 0){
        __threadfence();
        g_flags[bx*32] = ep;
    }
    if (bx == 0){
        if (tid < NBLK){
            while (g_flags[tid*32] < ep) { }
        }
        __syncthreads();
        if (tid == 0){
            __threadfence();
            g_gen = ep;
        }
    } else {
        if (tid == 0){
            while (g_gen < ep) { }
            __threadfence();
        }
    }
    __syncthreads();
}

// ---------------- prep kernels ----------------
__global__ void embed_kernel(const int* __restrict__ tok, const float* __restrict__ emb){
    int i = blockIdx.x*256 + threadIdx.x;
    if (i >= BT_*E_) return;
    int bt = i / E_, e = i % E_;
    g_X[i] = tanhf(emb[(size_t)tok[bt]*E_ + e]);
}

// column permutation: new col 4*jj+g  <-  original gate col g*H_+jj
__global__ void prep_w(const float* __restrict__ w_ih, const float* __restrict__ w_hh,
                       const float* __restrict__ b_lstm){
    int i = blockIdx.x*256 + threadIdx.x;
    if (i < KU*G4H){
        int k = i >> 11, col = i & 2047;
        int jj = col >> 2, g = col & 3;
        int j = g*H_ + jj;
        g_Wt[i] = (k < R_*WD_) ? w_ih[(size_t)j*(E_+R_*WD_) + E_ + k]
                               : w_hh[(size_t)j*H_ + (k - R_*WD_)];
    }
    if (i < E_*G4H){
        int e = i >> 11, col = i & 2047;
        int jj = col >> 2, g = col & 3;
        int j = g*H_ + jj;
        g_WihT[i] = w_ih[(size_t)j*(E_+R_*WD_) + e];
    }
    if (i < G4H){
        int jj = i >> 2, g = i & 3;
        g_bl[i] = b_lstm[g*H_ + jj];
    }
}

// tiled transpose + bf16 hi/lo split: g_W{hi,lo}T[n][k] = split(W_out[k][n])
__global__ void prep_outT(const float* __restrict__ W_out){
    __shared__ float tile[32][33];
    int n0 = blockIdx.x*32, k0 = blockIdx.y*32;
    int tx = threadIdx.x, ty = threadIdx.y;   // 32 x 8
    #pragma unroll
    for (int dy=0;dy<32;dy+=8){
        int k = k0+ty+dy, n = n0+tx;
        tile[ty+dy][tx] = (n < V_) ? W_out[(size_t)k*V_+n] : 0.f;
    }
    __syncthreads();
    #pragma unroll
    for (int dy=0;dy<32;dy+=8){
        int n = n0+ty+dy, k = k0+tx;
        float v = tile[tx][ty+dy];
        __nv_bfloat16 h = __float2bfloat16(v);
        g_WhiT[(size_t)n*KU+k] = h;
        g_WloT[(size_t)n*KU+k] = __float2bfloat16(v - __bfloat162float(h));
    }
}

__global__ void zero_state(){
    int i0 = blockIdx.x*blockDim.x + threadIdx.x;
    int stride = gridDim.x*blockDim.x;
    for (int k=i0;k<2*H_*B_;k+=stride) g_hT[0][k] = 0.f;
    for (int k=i0;k<R_*WD_*B_;k+=stride) g_rvT[k]=0.f;
    for (int k=i0;k<NBLK*32;k+=stride) g_flags[k] = 0u;
    if (i0 == 0) g_gen = 0u;
}

// ---------------- pipelined fp32 SGEMM (R4): C = A(MxK)@B(KxN) (+bias) ----------------
__global__ __launch_bounds__(256) void sgemm128(const float* __restrict__ A,
                         const float* __restrict__ Bm,
                         const float* __restrict__ bias, float* __restrict__ C,
                         int M, int Nn, int K){
    __shared__ float As[2][8][128];
    __shared__ float Bs[2][8][128];
    int tid = threadIdx.x;
    int row0 = blockIdx.y*128, col0 = blockIdx.x*128;
    int trow = (tid >> 4) * 8;
    int tcol = (tid & 15) * 8;
    float acc[8][8];
    #pragma unroll
    for (int i=0;i<8;i++)
        #pragma unroll
        for (int j=0;j<8;j++) acc[i][j]=0.f;

    int arow = tid >> 1, ak = (tid & 1)*4;
    int bk = tid >> 5,  bn = (tid & 31)*4;
    const float* Aptr = A + (size_t)(row0 + arow)*K + ak;
    int gn = col0 + bn;

    float4 av = *(const float4*)(Aptr);
    float4 bv = make_float4(0.f,0.f,0.f,0.f);
    if (gn < Nn) bv = *(const float4*)(Bm + (size_t)bk*Nn + gn);
    As[0][ak+0][arow]=av.x; As[0][ak+1][arow]=av.y; As[0][ak+2][arow]=av.z; As[0][ak+3][arow]=av.w;
    *(float4*)(&Bs[0][bk][bn]) = bv;
    __syncthreads();

    int buf = 0;
    for (int k0=0;k0<K;k0+=8){
        bool more = (k0 + 8) < K;
        if (more){
            av = *(const float4*)(Aptr + k0 + 8);
            bv = make_float4(0.f,0.f,0.f,0.f);
            if (gn < Nn) bv = *(const float4*)(Bm + (size_t)(k0+8+bk)*Nn + gn);
        }
        #pragma unroll
        for (int kk=0;kk<8;kk++){
            float ar[8], br[8];
            *(float4*)(ar)   = *(const float4*)(&As[buf][kk][trow]);
            *(float4*)(ar+4) = *(const float4*)(&As[buf][kk][trow+4]);
            *(float4*)(br)   = *(const float4*)(&Bs[buf][kk][tcol]);
            *(float4*)(br+4) = *(const float4*)(&Bs[buf][kk][tcol+4]);
            #pragma unroll
            for (int i=0;i<8;i++)
                #pragma unroll
                for (int j=0;j<8;j++) acc[i][j] += ar[i]*br[j];
        }
        if (more){
            int nb = buf ^ 1;
            As[nb][ak+0][arow]=av.x; As[nb][ak+1][arow]=av.y; As[nb][ak+2][arow]=av.z; As[nb][ak+3][arow]=av.w;
            *(float4*)(&Bs[nb][bk][bn]) = bv;
            __syncthreads();
            buf = nb;
        }
    }
    #pragma unroll
    for (int i=0;i<8;i++){
        size_t gm = (size_t)(row0 + trow + i);
        #pragma unroll
        for (int j=0;j<8;j+=4){
            int gnn = col0 + tcol + j;
            if (gnn < Nn){
                float4 v = make_float4(acc[i][j],acc[i][j+1],acc[i][j+2],acc[i][j+3]);
                if (bias){ v.x+=bias[gnn]; v.y+=bias[gnn+1]; v.z+=bias[gnn+2]; v.w+=bias[gnn+3]; }
                *(float4*)(C + gm*Nn + gnn) = v;
            }
        }
    }
}

// ---------------- bf16-split tensor-core GEMM: out = U@W_out + b ----------------
// C = Uhi*Whi + Uhi*Wlo + Ulo*Whi (fp32 accum). A and B both k-major in smem.
#define PITCH 40   // bf16 elems per smem row (80B, conflict-free fragment loads)
#define TILE_BF (128*PITCH)

__device__ __forceinline__ void mma_bf16(float* c, unsigned a0,unsigned a1,unsigned a2,unsigned a3,
                                         unsigned b0, unsigned b1){
    asm volatile("mma.sync.aligned.m16n8k16.row.col.f32.bf16.bf16.f32 "
        "{%0,%1,%2,%3}, {%4,%5,%6,%7}, {%8,%9}, {%0,%1,%2,%3};"
        : "+f"(c[0]),"+f"(c[1]),"+f"(c[2]),"+f"(c[3])
        : "r"(a0),"r"(a1),"r"(a2),"r"(a3),"r"(b0),"r"(b1));
}

__global__ __launch_bounds__(256) void gemm_out(const float* __restrict__ bias,
                                                float* __restrict__ C){
    extern __shared__ __align__(16) char smraw[];
    __nv_bfloat16* AsHi = (__nv_bfloat16*)smraw;
    __nv_bfloat16* AsLo = AsHi + 2*TILE_BF;
    __nv_bfloat16* BsHi = AsLo + 2*TILE_BF;
    __nv_bfloat16* BsLo = BsHi + 2*TILE_BF;

    const int tid = threadIdx.x, lane = tid & 31, wid = tid >> 5;
    const int warp_m = wid >> 2, warp_n = wid & 3;
    const int gid = lane >> 2, tig = lane & 3;
    const int m0 = blockIdx.y*128, n0 = blockIdx.x*128;

    float acc[4][4][4];
    #pragma unroll
    for (int i=0;i<4;i++)
        #pragma unroll
        for (int j=0;j<4;j++)
            #pragma unroll
            for (int q=0;q<4;q++) acc[i][j][q]=0.f;

    unsigned sAhi = (unsigned)__cvta_generic_to_shared(AsHi);
    unsigned sAlo = (unsigned)__cvta_generic_to_shared(AsLo);
    unsigned sBhi = (unsigned)__cvta_generic_to_shared(BsHi);
    unsigned sBlo = (unsigned)__cvta_generic_to_shared(BsLo);

    auto loadA = [&](int s, int kt){
        #pragma unroll
        for (int it=0; it<2; it++){
            int idx = it*256 + tid;
            int row = idx>>2, seg = idx&3;
            size_t goff = (size_t)(m0+row)*KU + kt*32 + seg*8;
            unsigned doff = (unsigned)((s*TILE_BF + row*PITCH + seg*8)*2);
            cpasync16(sAhi + doff, g_Uhi + goff);
            cpasync16(sAlo + doff, g_Ulo + goff);
        }
    };
    auto loadB = [&](int s, int kt){
        #pragma unroll
        for (int it=0; it<2; it++){
            int idx = it*256 + tid;
            int row = idx>>2, seg = idx&3;
            size_t goff = (size_t)(n0+row)*KU + kt*32 + seg*8;
            unsigned doff = (unsigned)((s*TILE_BF + row*PITCH + seg*8)*2);
            cpasync16(sBhi + doff, g_WhiT + goff);
            cpasync16(sBlo + doff, g_WloT + goff);
        }
    };
    auto compute = [&](int s){
        #pragma unroll
        for (int kk=0;kk<2;kk++){
            const int kb = kk*16 + tig*2;
            unsigned bh[4][2], bl[4][2];
            #pragma unroll
            for (int j=0;j<4;j++){
                int nl = warp_n*32 + j*8 + gid;
                const __nv_bfloat16* bp  = BsHi + s*TILE_BF + nl*PITCH + kb;
                const __nv_bfloat16* bp2 = BsLo + s*TILE_BF + nl*PITCH + kb;
                bh[j][0] = *(const unsigned*)bp;   bh[j][1] = *(const unsigned*)(bp+8);
                bl[j][0] = *(const unsigned*)bp2;  bl[j][1] = *(const unsigned*)(bp2+8);
            }
            #pragma unroll
            for (int i=0;i<4;i++){
                int mr = warp_m*64 + i*16;
                const __nv_bfloat16* ap  = AsHi + s*TILE_BF + (mr+gid)*PITCH + kb;
                const __nv_bfloat16* ap2 = AsLo + s*TILE_BF + (mr+gid)*PITCH + kb;
                unsigned ah0 = *(const unsigned*)ap;
                unsigned ah1 = *(const unsigned*)(ap + 8*PITCH);
                unsigned ah2 = *(const unsigned*)(ap + 8);
                unsigned ah3 = *(const unsigned*)(ap + 8*PITCH + 8);
                unsigned al0 = *(const unsigned*)ap2;
                unsigned al1 = *(const unsigned*)(ap2 + 8*PITCH);
                unsigned al2 = *(const unsigned*)(ap2 + 8);
                unsigned al3 = *(const unsigned*)(ap2 + 8*PITCH + 8);
                #pragma unroll
                for (int j=0;j<4;j++){
                    mma_bf16(acc[i][j], ah0,ah1,ah2,ah3, bh[j][0],bh[j][1]);
                    mma_bf16(acc[i][j], ah0,ah1,ah2,ah3, bl[j][0],bl[j][1]);
                    mma_bf16(acc[i][j], al0,al1,al2,al3, bh[j][0],bh[j][1]);
                }
            }
        }
    };

    loadA(0, 0); loadB(0, 0);
    asm volatile("cp.async.commit_group;");
    asm volatile("cp.async.wait_group 0;");
    __syncthreads();

    const int KT = KU/32;   // 24
    for (int kt=0; kt<KT; kt++){
        int buf = kt & 1;
        if (kt+1 < KT){
            loadA(buf^1, kt+1);
            loadB(buf^1, kt+1);
            asm volatile("cp.async.commit_group;");
        }
        compute(buf);
        if (kt+1 < KT){
            asm volatile("cp.async.wait_group 0;");
        }
        __syncthreads();
    }

    #pragma unroll
    for (int i=0;i<4;i++){
        int gm = m0 + warp_m*64 + i*16 + gid;
        #pragma unroll
        for (int j=0;j<4;j++){
            int gn = n0 + warp_n*32 + j*8 + tig*2;
            if (gn < V_){
                float b0 = bias[gn], b1 = bias[gn+1];
                *(float2*)(C + (size_t)gm*V_ + gn) = make_float2(acc[i][j][0]+b0, acc[i][j][1]+b1);
                *(float2*)(C + (size_t)(gm+8)*V_ + gn) = make_float2(acc[i][j][2]+b0, acc[i][j][3]+b1);
            }
        }
    }
}

// ---------------- persistent sequential loop (R5 structure) ----------------
#define LOOP_SMEM_FLOATS (12288 + 2048 + 8192 + 29192)

__global__ __launch_bounds__(THR) void loop_kernel(const float* __restrict__ W_iface,
                                                   const float* __restrict__ b_iface){
    extern __shared__ float sm[];
    float* W_A  = sm;                  // 768*16
    float* W_C  = W_A + 12288;         // 512*4
    float* scr  = W_C + 2048;          // 8192
    float* M_s  = scr + 8192;          // 128*65
    float* L_s  = M_s + 8320;          // 128*129
    float* wr_s = L_s + 16512;         // 512
    float* u_s  = wr_s + 512;          // 128
    float* p_s  = u_s + 128;           // 128
    float* ww_s = p_s + 128;           // 128
    float* xi   = ww_s + 128;          // 472
    float* fwdw = xi + 472;            // 512
    float* bwdw = fwdw + 512;          // 512
    float* crs  = bwdw + 512;          // 512
    float* unew = crs + 512;           // 128
    float* srt  = unew + 128;          // 128
    float* incl = srt + 128;           // 128
    float* cpex = incl + 128;          // 128
    float* a_s  = cpex + 128;          // 128
    float* wwn  = a_s + 128;           // 128
    float* Mn   = wwn + 128;           // 128
    float* red  = Mn + 128;            // 128
    float* xtra = red + 128;           // 128 (spare)
    float* act  = xtra + 128;          // 176
    int* rank_s = (int*)(act + 176);   // 128
    (void)xtra;

    const int tid  = threadIdx.x;
    const int bx   = blockIdx.x;
    const int wid  = tid >> 5;         // 0..15
    const int lane = tid & 31;
    const int b    = bx;

    for (int i=tid;i<768*16;i+=THR){
        int k = i >> 4, c = i & 15;
        W_A[i] = g_Wt[(size_t)k*G4H + bx*16 + c];
    }
    for (int i=tid;i<512*4;i+=THR){
        int k = i >> 2, c = i & 3;
        int col = bx*4 + c;
        W_C[i] = (col < IFACE_) ? W_iface[(size_t)k*IFACE_ + col] : 0.f;
    }
    if (bx < B_){
        for (int i=tid;i<128*65;i+=THR)  M_s[i]=0.f;
        for (int i=tid;i<128*129;i+=THR) L_s[i]=0.f;
        for (int i=tid;i<512;i+=THR)     wr_s[i]=0.f;
        if (tid < N_){ u_s[tid]=0.f; p_s[tid]=0.f; ww_s[tid]=0.f; }
    }
    __syncthreads();

    float c_reg = 0.f;
    unsigned ep = 0;
    ull* scr2 = (ull*)scr;

    for (int t=0;t<T_;t++){
        const int rd = t & 1, wrb = rd ^ 1;

        // ============ Phase A: LSTM gemm (split-K over 16 warps, f32x2) ============
        {
            const int kbeg = wid*48;
            ull acc2[8];
            #pragma unroll
            for (int c=0;c<8;c++) acc2[c]=0ull;
            const float* hrd = g_hT[rd];
            #pragma unroll 4
            for (int k=kbeg;k<kbeg+48;k++){
                const float* ap = (k < 256) ? (g_rvT + k*B_) : (hrd + (k-256)*B_);
                ull as = splat2f(ap[lane]);
                const ulonglong2* wp = (const ulonglong2*)(W_A + k*16);
                ulonglong2 w01 = wp[0], w23 = wp[1], w45 = wp[2], w67 = wp[3];
                ffma2(acc2[0], as, w01.x); ffma2(acc2[1], as, w01.y);
                ffma2(acc2[2], as, w23.x); ffma2(acc2[3], as, w23.y);
                ffma2(acc2[4], as, w45.x); ffma2(acc2[5], as, w45.y);
                ffma2(acc2[6], as, w67.x); ffma2(acc2[7], as, w67.y);
            }
            #pragma unroll
            for (int c=0;c<8;c++) scr2[wid*256 + c*32 + lane] = acc2[c];
        }
        __syncthreads();
        if (tid < 128){
            int uu = tid >> 5;
            float4 s = *(const float4*)(g_G0 + ((size_t)lane*T_ + t)*G4H + bx*16 + uu*4);
            ull s01 = pack2(s.x, s.y), s23 = pack2(s.z, s.w);
            #pragma unroll
            for (int w16=0;w16<16;w16++){
                fadd2(s01, scr2[w16*256 + (2*uu  )*32 + lane]);
                fadd2(s23, scr2[w16*256 + (2*uu+1)*32 + lane]);
            }
            float2 g01 = unpack2(s01), g23 = unpack2(s23);
            float c = sigf(g01.y)*c_reg + sigf(g01.x)*tanhf(g23.x);
            float h = sigf(g23.y)*tanhf(c);
            c_reg = c;
            int jj = bx*4 + uu;
            g_hT[wrb][jj*B_ + lane] = h;
            size_t btrow = (size_t)lane*T_ + t;
            __nv_bfloat16 hh = __float2bfloat16(h);
            g_Uhi[btrow*KU + jj] = hh;
            g_Ulo[btrow*KU + jj] = __float2bfloat16(h - __bfloat162float(hh));
        }
        gridbar(++ep);

        // ============ Phase C: iface gemm (split-K over 16 warps) ============
        if (bx < 118){
            const int kbeg = wid*32;
            float a0=0.f,a1=0.f,a2=0.f,a3=0.f;
            const float* hsrc = g_hT[wrb];
            #pragma unroll 4
            for (int k=kbeg;k<kbeg+32;k++){
                float a = hsrc[k*B_ + lane];
                float4 wv = *(const float4*)(W_C + k*4);
                a0 += a*wv.x; a1 += a*wv.y; a2 += a*wv.z; a3 += a*wv.w;
            }
            scr[wid*128 +       lane] = a0;
            scr[wid*128 +  32 + lane] = a1;
            scr[wid*128 +  64 + lane] = a2;
            scr[wid*128 +  96 + lane] = a3;
            __syncthreads();
            if (tid < 128){
                int c = tid >> 5, col = bx*4 + c;
                if (col < IFACE_){
                    float s = b_iface[col];
                    #pragma unroll
                    for (int w16=0;w16<16;w16++) s += scr[w16*128 + c*32 + lane];
                    g_xiT[col*B_ + lane] = s;
                }
            }
        }
        gridbar(++ep);

        // ============ Phase D: DNC memory step (blocks 0..31) ============
        if (bx < B_){
            for (int i=tid;i<IFACE_;i+=THR) xi[i] = g_xiT[i*B_ + b];
            __syncthreads();

            if (tid < 64){
                act[8+tid]  = sigf(xi[325+tid]);
                act[72+tid] = xi[389+tid];
            } else if (tid < 68){
                act[tid-64] = 1.f + splusf(xi[256 + (tid-64)]);
            } else if (tid == 68){
                act[4] = 1.f + splusf(xi[324]);
            } else if (tid < 73){
                act[136 + (tid-69)] = sigf(xi[453 + (tid-69)]);
            } else if (tid == 73){
                act[140] = sigf(xi[457]);
            } else if (tid == 74){
                act[141] = sigf(xi[458]);
            } else if (tid < 79){
                int r = tid - 75;
                float q0=xi[459+r*3], q1=xi[459+r*3+1], q2=xi[459+r*3+2];
                float m = fmaxf(q0, fmaxf(q1,q2));
                float e0=expf(q0-m), e1=expf(q1-m), e2=expf(q2-m);
                float s = e0+e1+e2;
                act[144+r*3]=e0/s; act[145+r*3]=e1/s; act[146+r*3]=e2/s;
            } else if (tid < 83){
                int r = tid - 79; float s = 0.f;
                #pragma unroll 8
                for (int w=0;w<WD_;w++){ float v = xi[r*WD_+w]; s += v*v; }
                act[156+r] = sqrtf(s);
            } else if (tid == 83){
                float s = 0.f;
                #pragma unroll 8
                for (int w=0;w<WD_;w++){ float v = xi[260+w]; s += v*v; }
                act[160] = sqrtf(s);
            }
            __syncthreads();

            if (tid < N_){
                float psi = 1.f;
                #pragma unroll
                for (int r=0;r<R_;r++) psi *= (1.f - act[136+r]*wr_s[r*N_+tid]);
                float uo=u_s[tid], wo=ww_s[tid];
                unew[tid] = (uo + wo - uo*wo)*psi;
            }
            __syncthreads();

            if (tid < N_){
                float ui = unew[tid]; int rk = 0;
                #pragma unroll 8
                for (int j=0;j<N_;j++){
                    float uj = unew[j];
                    rk += (uj < ui) || (uj == ui && j < tid);
                }
                rank_s[tid] = rk;
                srt[rk] = ui;
            }
            __syncthreads();

            float cp_p = 1.f;
            if (tid < N_){
                int w4 = tid >> 5, ln = tid & 31;
                cp_p = srt[tid];
                #pragma unroll
                for (int off=1;off<32;off<<=1){
                    float o = __shfl_up_sync(0xffffffffu, cp_p, off);
                    if (ln >= off) cp_p *= o;
                }
                if (ln == 31) red[w4] = cp_p;
            }
            __syncthreads();
            if (tid < N_){
                int w4 = tid >> 5;
                float pre = 1.f;
                #pragma unroll
                for (int j=0;j<3;j++) if (j < w4) pre *= red[j];
                incl[tid] = cp_p * pre;
            }
            __syncthreads();
            if (tid < N_) cpex[tid] = (tid == 0) ? 1.f : incl[tid-1];
            __syncthreads();

            float score_w = 0.f, ew = 0.f;
            if (tid < N_){
                a_s[tid] = (1.f - unew[tid]) * cpex[rank_s[tid]];
                float s2=0.f, dot=0.f;
                #pragma unroll 8
                for (int w=0;w<WD_;w++){ float m = M_s[tid*65+w]; s2 += m*m; dot += m*xi[260+w]; }
                score_w = act[4] * (dot / (act[160]*sqrtf(s2) + EPSF));
                float v = score_w;
                #pragma unroll
                for (int o=16;o;o>>=1) v = fmaxf(v, __shfl_xor_sync(0xffffffffu, v, o));
                if ((tid&31)==0) red[tid>>5] = v;
            }
            __syncthreads();
            float mxw = fmaxf(fmaxf(red[0],red[1]), fmaxf(red[2],red[3]));
            if (tid < N_){
                ew = expf(score_w - mxw);
                float s = ew;
                #pragma unroll
                for (int o=16;o;o>>=1) s += __shfl_xor_sync(0xffffffffu, s, o);
                if ((tid&31)==0) red[4 + (tid>>5)] = s;
            }
            __syncthreads();
            float sden = red[4]+red[5]+red[6]+red[7];
            if (tid < N_){
                float wv = act[141]*(act[140]*a_s[tid] + (1.f-act[140])*(ew/sden));
                wwn[tid] = wv;
                float s = wv;
                #pragma unroll
                for (int o=16;o;o>>=1) s += __shfl_xor_sync(0xffffffffu, s, o);
                if ((tid&31)==0) red[8 + (tid>>5)] = s;
            }
            __syncthreads();
            float sumww = red[8]+red[9]+red[10]+red[11];

            for (int i=tid;i<N_*WD_;i+=THR){
                int n=i>>6, w=i&63;
                float wwv = wwn[n];
                M_s[n*65+w] = M_s[n*65+w]*(1.f - wwv*act[8+w]) + wwv*act[72+w];
            }
            for (int i=tid;i<N_*N_;i+=THR){
                int n=i>>7, m=i&127;
                float v = (n==m) ? 0.f
                         : (1.f - wwn[n] - wwn[m])*L_s[n*129+m] + wwn[n]*p_s[m];
                L_s[n*129+m] = v;
            }
            __syncthreads();
            if (tid < N_) p_s[tid] = (1.f - sumww)*p_s[tid] + wwn[tid];

            {
                int r = tid>>7, n = tid&127;
                float f=0.f, bw=0.f;
                const float* wrr = wr_s + r*N_;
                #pragma unroll 8
                for (int m=0;m<N_;m++){
                    float wv = wrr[m];
                    f  += L_s[n*129+m]*wv;
                    bw += L_s[m*129+n]*wv;
                }
                fwdw[tid]=f; bwdw[tid]=bw;
            }
            if (tid < N_){
                float s2=0.f;
                #pragma unroll 8
                for (int w=0;w<WD_;w++){ float m=M_s[tid*65+w]; s2 += m*m; }
                Mn[tid] = sqrtf(s2);
            }
            __syncthreads();
            if (tid < N_){
                #pragma unroll
                for (int r=0;r<R_;r++){
                    float dot=0.f;
                    #pragma unroll 8
                    for (int w=0;w<WD_;w++) dot += M_s[tid*65+w]*xi[r*WD_+w];
                    crs[r*N_+tid] = act[r]*(dot/(act[156+r]*Mn[tid] + EPSF));
                }
            }
            __syncthreads();
            if (tid < 128){
                int r = tid>>5, ln = tid&31;
                float v = fmaxf(fmaxf(crs[r*N_+ln],crs[r*N_+ln+32]),
                                fmaxf(crs[r*N_+ln+64],crs[r*N_+ln+96]));
                #pragma unroll
                for (int o=16;o;o>>=1) v = fmaxf(v, __shfl_xor_sync(0xffffffffu, v, o));
                if (ln==0) act[164+r]=v;
            }
            __syncthreads();
            if (tid < 128){
                int r = tid>>5, ln = tid&31;
                float m = act[164+r];
                float e0=expf(crs[r*N_+ln   ]-m);
                float e1=expf(crs[r*N_+ln+32]-m);
                float e2=expf(crs[r*N_+ln+64]-m);
                float e3=expf(crs[r*N_+ln+96]-m);
                crs[r*N_+ln]=e0; crs[r*N_+ln+32]=e1; crs[r*N_+ln+64]=e2; crs[r*N_+ln+96]=e3;
                float s = e0+e1+e2+e3;
                #pragma unroll
                for (int o=16;o;o>>=1) s += __shfl_xor_sync(0xffffffffu, s, o);
                if (ln==0) act[168+r]=s;
            }
            __syncthreads();
            for (int i=tid;i<R_*N_;i+=THR){
                int r = i>>7;
                float w = act[144+r*3]*bwdw[i] + act[145+r*3]*(crs[i]/act[168+r]) + act[146+r*3]*fwdw[i];
                crs[i] = w;
            }
            __syncthreads();
            if (tid < R_*WD_){
                int r = tid>>6, w = tid&63;
                float s=0.f;
                #pragma unroll 8
                for (int n=0;n<N_;n++) s += crs[r*N_+n]*M_s[n*65+w];
                g_rvT[tid*B_ + b] = s;
                size_t btrow = (size_t)b*T_ + t;
                __nv_bfloat16 sh = __float2bfloat16(s);
                g_Uhi[btrow*KU + H_ + tid] = sh;
                g_Ulo[btrow*KU + H_ + tid] = __float2bfloat16(s - __bfloat162float(sh));
            }
            __syncthreads();
            for (int i=tid;i<R_*N_;i+=THR) wr_s[i] = crs[i];
            if (tid < N_){ u_s[tid]=unew[tid]; ww_s[tid]=wwn[tid]; }
        }
        gridbar(++ep);
    }
}

// ---------------- launcher ----------------
extern "C" void kernel_launch(void* const* d_in, const int* in_sizes, int n_in,
                              void* d_out, int out_size){
    const int*   tokens  = (const int*)  d_in[0];
    const float* emb     = (const float*)d_in[1];
    const float* w_ih    = (const float*)d_in[2];
    const float* w_hh    = (const float*)d_in[3];
    const float* b_lstm  = (const float*)d_in[4];
    const float* W_iface = (const float*)d_in[5];
    const float* b_iface = (const float*)d_in[6];
    const float* W_out   = (const float*)d_in[7];
    const float* b_out   = (const float*)d_in[8];
    float* out = (float*)d_out;

    const int loop_smem = LOOP_SMEM_FLOATS * (int)sizeof(float);
    cudaFuncSetAttribute(loop_kernel, cudaFuncAttributeMaxDynamicSharedMemorySize, loop_smem);
    const int gout_smem = 8 * TILE_BF * (int)sizeof(__nv_bfloat16);
    cudaFuncSetAttribute(gemm_out, cudaFuncAttributeMaxDynamicSharedMemorySize, gout_smem);

    void *pX, *pG0, *pWihT, *pBl;
    cudaGetSymbolAddress(&pX, g_X);
    cudaGetSymbolAddress(&pG0, g_G0);
    cudaGetSymbolAddress(&pWihT, g_WihT);
    cudaGetSymbolAddress(&pBl, g_bl);

    embed_kernel<<<(BT_*E_ + 255)/256, 256>>>(tokens, emb);
    prep_w<<<(KU*G4H + 255)/256, 256>>>(w_ih, w_hh, b_lstm);
    prep_outT<<<dim3(VPAD/32, KU/32), dim3(32,8)>>>(W_out);
    zero_state<<<64, 256>>>();

    // G0 = X (8192x256) @ WihT (256x2048) + permuted bias
    sgemm128<<<dim3(G4H/128, BT_/128), 256>>>((const float*)pX, (const float*)pWihT,
                                              (const float*)pBl, (float*)pG0, BT_, G4H, E_);

    loop_kernel<<<NBLK, THR, loop_smem>>>(W_iface, b_iface);

    // out = U (8192x768) @ W_out (768x10000) + b_out   [bf16-split tensor cores]
    gemm_out<<<dim3((V_+127)/128, BT_/128), 256, gout_smem>>>(b_out, out);
}

// round 8
// speedup vs baseline: 1.8129x; 1.0722x over previous
#include <cuda_runtime.h>
#include <cuda_bf16.h>
#include <math.h>

#define B_ 32
#define T_ 256
#define V_ 10000
#define VPAD 10112
#define E_ 256
#define H_ 512
#define N_ 128
#define WD_ 64
#define R_ 4
#define IFACE_ 471
#define G4H 2048          // 4*H
#define KU 768            // H + R*WD
#define BT_ (B_*T_)       // 8192
#define EPSF 1e-6f
#define NBLK 128
#define THR 512

typedef unsigned long long ull;

// ---------------- f32x2 helpers ----------------
__device__ __forceinline__ ull pack2(float x, float y){
    ull r; asm("mov.b64 %0, {%1,%2};" : "=l"(r) : "r"(__float_as_uint(x)), "r"(__float_as_uint(y))); return r;
}
__device__ __forceinline__ ull splat2f(float x){ return pack2(x, x); }
__device__ __forceinline__ float2 unpack2(ull v){
    unsigned lo, hi;
    asm("mov.b64 {%0,%1}, %2;" : "=r"(lo), "=r"(hi) : "l"(v));
    return make_float2(__uint_as_float(lo), __uint_as_float(hi));
}
__device__ __forceinline__ void ffma2(ull& d, ull a, ull b){
    asm("fma.rn.f32x2 %0, %1, %2, %0;" : "+l"(d) : "l"(a), "l"(b));
}
__device__ __forceinline__ void fadd2(ull& d, ull a){
    asm("add.rn.f32x2 %0, %0, %1;" : "+l"(d) : "l"(a));
}
__device__ __forceinline__ void cpasync16(unsigned dst, const void* src){
    asm volatile("cp.async.cg.shared.global [%0], [%1], 16;" :: "r"(dst), "l"(src));
}

// ---------------- GPU-scope relaxed flag ops (NOT volatile/sys!) ----------------
__device__ __forceinline__ unsigned ld_rlx(const unsigned* p){
    unsigned v;
    asm volatile("ld.relaxed.gpu.global.u32 %0, [%1];" : "=r"(v) : "l"(p) : "memory");
    return v;
}
__device__ __forceinline__ void st_rlx(unsigned* p, unsigned v){
    asm volatile("st.relaxed.gpu.global.u32 [%0], %1;" :: "l"(p), "r"(v) : "memory");
}

// ---------------- device scratch ----------------
__device__ __align__(128) float g_X[BT_*E_];
__device__ __align__(128) float g_G0[(size_t)BT_*G4H];
__device__ __align__(128) float g_WihT[E_*G4H];               // permuted cols
__device__ __align__(128) float g_Wt[KU*G4H];                 // permuted cols: [rv ; h]
__device__ __align__(128) float g_bl[G4H];                    // permuted bias
__device__ __align__(128) __nv_bfloat16 g_WhiT[(size_t)VPAD*KU];  // W_out^T hi
__device__ __align__(128) __nv_bfloat16 g_WloT[(size_t)VPAD*KU];  // W_out^T lo
__device__ __align__(128) __nv_bfloat16 g_Uhi[(size_t)BT_*KU];
__device__ __align__(128) __nv_bfloat16 g_Ulo[(size_t)BT_*KU];
__device__ __align__(128) float g_hT[2][H_*B_];               // double-buffered [feat][batch]
__device__ __align__(128) float g_rvT[R_*WD_*B_];
__device__ __align__(128) float g_xiT[IFACE_*B_];
__device__ __align__(128) unsigned g_flags[NBLK*32];          // padded to 128B lines
__device__ unsigned g_gen;

__device__ __forceinline__ float sigf(float x){ return 1.f/(1.f + expf(-x)); }
__device__ __forceinline__ float splusf(float x){ return fmaxf(x,0.f) + log1pf(expf(-fabsf(x))); }

// ---------------- flag-based grid barrier (gpu-scope relaxed + IVALL fence) ----------------
__device__ __forceinline__ void gridbar(unsigned ep){
    __syncthreads();
    const int tid = threadIdx.x;
    const int bx  = blockIdx.x;
    if (tid == 0){
        __threadfence();                       // order this block's writes (gpu scope)
        st_rlx(&g_flags[bx*32], ep);
    }
    if (bx == 0){
        if (tid < NBLK){
            while (ld_rlx(&g_flags[tid*32]) < ep) { }
        }
        __syncthreads();
        if (tid == 0) st_rlx((unsigned*)&g_gen, ep);
    } else {
        if (tid == 0){
            while (ld_rlx((const unsigned*)&g_gen) < ep) { }
        }
    }
    if (tid == 0) __threadfence();             // CCTL.IVALL: invalidate stale L1 lines
    __syncthreads();
}

// ---------------- prep kernels ----------------
__global__ void embed_kernel(const int* __restrict__ tok, const float* __restrict__ emb){
    int i = blockIdx.x*256 + threadIdx.x;
    if (i >= BT_*E_) return;
    int bt = i / E_, e = i % E_;
    g_X[i] = tanhf(emb[(size_t)tok[bt]*E_ + e]);
}

// column permutation: new col 4*jj+g  <-  original gate col g*H_+jj
__global__ void prep_w(const float* __restrict__ w_ih, const float* __restrict__ w_hh,
                       const float* __restrict__ b_lstm){
    int i = blockIdx.x*256 + threadIdx.x;
    if (i < KU*G4H){
        int k = i >> 11, col = i & 2047;
        int jj = col >> 2, g = col & 3;
        int j = g*H_ + jj;
        g_Wt[i] = (k < R_*WD_) ? w_ih[(size_t)j*(E_+R_*WD_) + E_ + k]
                               : w_hh[(size_t)j*H_ + (k - R_*WD_)];
    }
    if (i < E_*G4H){
        int e = i >> 11, col = i & 2047;
        int jj = col >> 2, g = col & 3;
        int j = g*H_ + jj;
        g_WihT[i] = w_ih[(size_t)j*(E_+R_*WD_) + e];
    }
    if (i < G4H){
        int jj = i >> 2, g = i & 3;
        g_bl[i] = b_lstm[g*H_ + jj];
    }
}

// tiled transpose + bf16 hi/lo split: g_W{hi,lo}T[n][k] = split(W_out[k][n])
__global__ void prep_outT(const float* __restrict__ W_out){
    __shared__ float tile[32][33];
    int n0 = blockIdx.x*32, k0 = blockIdx.y*32;
    int tx = threadIdx.x, ty = threadIdx.y;   // 32 x 8
    #pragma unroll
    for (int dy=0;dy<32;dy+=8){
        int k = k0+ty+dy, n = n0+tx;
        tile[ty+dy][tx] = (n < V_) ? W_out[(size_t)k*V_+n] : 0.f;
    }
    __syncthreads();
    #pragma unroll
    for (int dy=0;dy<32;dy+=8){
        int n = n0+ty+dy, k = k0+tx;
        float v = tile[tx][ty+dy];
        __nv_bfloat16 h = __float2bfloat16(v);
        g_WhiT[(size_t)n*KU+k] = h;
        g_WloT[(size_t)n*KU+k] = __float2bfloat16(v - __bfloat162float(h));
    }
}

__global__ void zero_state(){
    int i0 = blockIdx.x*blockDim.x + threadIdx.x;
    int stride = gridDim.x*blockDim.x;
    for (int k=i0;k<2*H_*B_;k+=stride) g_hT[0][k] = 0.f;
    for (int k=i0;k<R_*WD_*B_;k+=stride) g_rvT[k]=0.f;
    for (int k=i0;k<NBLK*32;k+=stride) g_flags[k] = 0u;
    if (i0 == 0) g_gen = 0u;
}

// ---------------- pipelined fp32 SGEMM (R4): C = A(MxK)@B(KxN) (+bias) ----------------
__global__ __launch_bounds__(256) void sgemm128(const float* __restrict__ A,
                         const float* __restrict__ Bm,
                         const float* __restrict__ bias, float* __restrict__ C,
                         int M, int Nn, int K){
    __shared__ float As[2][8][128];
    __shared__ float Bs[2][8][128];
    int tid = threadIdx.x;
    int row0 = blockIdx.y*128, col0 = blockIdx.x*128;
    int trow = (tid >> 4) * 8;
    int tcol = (tid & 15) * 8;
    float acc[8][8];
    #pragma unroll
    for (int i=0;i<8;i++)
        #pragma unroll
        for (int j=0;j<8;j++) acc[i][j]=0.f;

    int arow = tid >> 1, ak = (tid & 1)*4;
    int bk = tid >> 5,  bn = (tid & 31)*4;
    const float* Aptr = A + (size_t)(row0 + arow)*K + ak;
    int gn = col0 + bn;

    float4 av = *(const float4*)(Aptr);
    float4 bv = make_float4(0.f,0.f,0.f,0.f);
    if (gn < Nn) bv = *(const float4*)(Bm + (size_t)bk*Nn + gn);
    As[0][ak+0][arow]=av.x; As[0][ak+1][arow]=av.y; As[0][ak+2][arow]=av.z; As[0][ak+3][arow]=av.w;
    *(float4*)(&Bs[0][bk][bn]) = bv;
    __syncthreads();

    int buf = 0;
    for (int k0=0;k0<K;k0+=8){
        bool more = (k0 + 8) < K;
        if (more){
            av = *(const float4*)(Aptr + k0 + 8);
            bv = make_float4(0.f,0.f,0.f,0.f);
            if (gn < Nn) bv = *(const float4*)(Bm + (size_t)(k0+8+bk)*Nn + gn);
        }
        #pragma unroll
        for (int kk=0;kk<8;kk++){
            float ar[8], br[8];
            *(float4*)(ar)   = *(const float4*)(&As[buf][kk][trow]);
            *(float4*)(ar+4) = *(const float4*)(&As[buf][kk][trow+4]);
            *(float4*)(br)   = *(const float4*)(&Bs[buf][kk][tcol]);
            *(float4*)(br+4) = *(const float4*)(&Bs[buf][kk][tcol+4]);
            #pragma unroll
            for (int i=0;i<8;i++)
                #pragma unroll
                for (int j=0;j<8;j++) acc[i][j] += ar[i]*br[j];
        }
        if (more){
            int nb = buf ^ 1;
            As[nb][ak+0][arow]=av.x; As[nb][ak+1][arow]=av.y; As[nb][ak+2][arow]=av.z; As[nb][ak+3][arow]=av.w;
            *(float4*)(&Bs[nb][bk][bn]) = bv;
            __syncthreads();
            buf = nb;
        }
    }
    #pragma unroll
    for (int i=0;i<8;i++){
        size_t gm = (size_t)(row0 + trow + i);
        #pragma unroll
        for (int j=0;j<8;j+=4){
            int gnn = col0 + tcol + j;
            if (gnn < Nn){
                float4 v = make_float4(acc[i][j],acc[i][j+1],acc[i][j+2],acc[i][j+3]);
                if (bias){ v.x+=bias[gnn]; v.y+=bias[gnn+1]; v.z+=bias[gnn+2]; v.w+=bias[gnn+3]; }
                *(float4*)(C + gm*Nn + gnn) = v;
            }
        }
    }
}

// ---------------- bf16-split tensor-core GEMM: out = U@W_out + b ----------------
#define PITCH 40
#define TILE_BF (128*PITCH)

__device__ __forceinline__ void mma_bf16(float* c, unsigned a0,unsigned a1,unsigned a2,unsigned a3,
                                         unsigned b0, unsigned b1){
    asm volatile("mma.sync.aligned.m16n8k16.row.col.f32.bf16.bf16.f32 "
        "{%0,%1,%2,%3}, {%4,%5,%6,%7}, {%8,%9}, {%0,%1,%2,%3};"
        : "+f"(c[0]),"+f"(c[1]),"+f"(c[2]),"+f"(c[3])
        : "r"(a0),"r"(a1),"r"(a2),"r"(a3),"r"(b0),"r"(b1));
}

__global__ __launch_bounds__(256) void gemm_out(const float* __restrict__ bias,
                                                float* __restrict__ C){
    extern __shared__ __align__(16) char smraw[];
    __nv_bfloat16* AsHi = (__nv_bfloat16*)smraw;
    __nv_bfloat16* AsLo = AsHi + 2*TILE_BF;
    __nv_bfloat16* BsHi = AsLo + 2*TILE_BF;
    __nv_bfloat16* BsLo = BsHi + 2*TILE_BF;

    const int tid = threadIdx.x, lane = tid & 31, wid = tid >> 5;
    const int warp_m = wid >> 2, warp_n = wid & 3;
    const int gid = lane >> 2, tig = lane & 3;
    const int m0 = blockIdx.y*128, n0 = blockIdx.x*128;

    float acc[4][4][4];
    #pragma unroll
    for (int i=0;i<4;i++)
        #pragma unroll
        for (int j=0;j<4;j++)
            #pragma unroll
            for (int q=0;q<4;q++) acc[i][j][q]=0.f;

    unsigned sAhi = (unsigned)__cvta_generic_to_shared(AsHi);
    unsigned sAlo = (unsigned)__cvta_generic_to_shared(AsLo);
    unsigned sBhi = (unsigned)__cvta_generic_to_shared(BsHi);
    unsigned sBlo = (unsigned)__cvta_generic_to_shared(BsLo);

    auto loadA = [&](int s, int kt){
        #pragma unroll
        for (int it=0; it<2; it++){
            int idx = it*256 + tid;
            int row = idx>>2, seg = idx&3;
            size_t goff = (size_t)(m0+row)*KU + kt*32 + seg*8;
            unsigned doff = (unsigned)((s*TILE_BF + row*PITCH + seg*8)*2);
            cpasync16(sAhi + doff, g_Uhi + goff);
            cpasync16(sAlo + doff, g_Ulo + goff);
        }
    };
    auto loadB = [&](int s, int kt){
        #pragma unroll
        for (int it=0; it<2; it++){
            int idx = it*256 + tid;
            int row = idx>>2, seg = idx&3;
            size_t goff = (size_t)(n0+row)*KU + kt*32 + seg*8;
            unsigned doff = (unsigned)((s*TILE_BF + row*PITCH + seg*8)*2);
            cpasync16(sBhi + doff, g_WhiT + goff);
            cpasync16(sBlo + doff, g_WloT + goff);
        }
    };
    auto compute = [&](int s){
        #pragma unroll
        for (int kk=0;kk<2;kk++){
            const int kb = kk*16 + tig*2;
            unsigned bh[4][2], bl[4][2];
            #pragma unroll
            for (int j=0;j<4;j++){
                int nl = warp_n*32 + j*8 + gid;
                const __nv_bfloat16* bp  = BsHi + s*TILE_BF + nl*PITCH + kb;
                const __nv_bfloat16* bp2 = BsLo + s*TILE_BF + nl*PITCH + kb;
                bh[j][0] = *(const unsigned*)bp;   bh[j][1] = *(const unsigned*)(bp+8);
                bl[j][0] = *(const unsigned*)bp2;  bl[j][1] = *(const unsigned*)(bp2+8);
            }
            #pragma unroll
            for (int i=0;i<4;i++){
                int mr = warp_m*64 + i*16;
                const __nv_bfloat16* ap  = AsHi + s*TILE_BF + (mr+gid)*PITCH + kb;
                const __nv_bfloat16* ap2 = AsLo + s*TILE_BF + (mr+gid)*PITCH + kb;
                unsigned ah0 = *(const unsigned*)ap;
                unsigned ah1 = *(const unsigned*)(ap + 8*PITCH);
                unsigned ah2 = *(const unsigned*)(ap + 8);
                unsigned ah3 = *(const unsigned*)(ap + 8*PITCH + 8);
                unsigned al0 = *(const unsigned*)ap2;
                unsigned al1 = *(const unsigned*)(ap2 + 8*PITCH);
                unsigned al2 = *(const unsigned*)(ap2 + 8);
                unsigned al3 = *(const unsigned*)(ap2 + 8*PITCH + 8);
                #pragma unroll
                for (int j=0;j<4;j++){
                    mma_bf16(acc[i][j], ah0,ah1,ah2,ah3, bh[j][0],bh[j][1]);
                    mma_bf16(acc[i][j], ah0,ah1,ah2,ah3, bl[j][0],bl[j][1]);
                    mma_bf16(acc[i][j], al0,al1,al2,al3, bh[j][0],bh[j][1]);
                }
            }
        }
    };

    loadA(0, 0); loadB(0, 0);
    asm volatile("cp.async.commit_group;");
    asm volatile("cp.async.wait_group 0;");
    __syncthreads();

    const int KT = KU/32;   // 24
    for (int kt=0; kt<KT; kt++){
        int buf = kt & 1;
        if (kt+1 < KT){
            loadA(buf^1, kt+1);
            loadB(buf^1, kt+1);
            asm volatile("cp.async.commit_group;");
        }
        compute(buf);
        if (kt+1 < KT){
            asm volatile("cp.async.wait_group 0;");
        }
        __syncthreads();
    }

    #pragma unroll
    for (int i=0;i<4;i++){
        int gm = m0 + warp_m*64 + i*16 + gid;
        #pragma unroll
        for (int j=0;j<4;j++){
            int gn = n0 + warp_n*32 + j*8 + tig*2;
            if (gn < V_){
                float b0 = bias[gn], b1 = bias[gn+1];
                *(float2*)(C + (size_t)gm*V_ + gn) = make_float2(acc[i][j][0]+b0, acc[i][j][1]+b1);
                *(float2*)(C + (size_t)(gm+8)*V_ + gn) = make_float2(acc[i][j][2]+b0, acc[i][j][3]+b1);
            }
        }
    }
}

// ---------------- persistent sequential loop ----------------
#define LOOP_SMEM_FLOATS (12288 + 2048 + 8192 + 29192)

__global__ __launch_bounds__(THR) void loop_kernel(const float* __restrict__ W_iface,
                                                   const float* __restrict__ b_iface){
    extern __shared__ float sm[];
    float* W_A  = sm;                  // 768*16
    float* W_C  = W_A + 12288;         // 512*4
    float* scr  = W_C + 2048;          // 8192 (phases A/C; reused in D for packed tables)
    float* M_s  = scr + 8192;          // 128*65
    float* L_s  = M_s + 8320;          // 128*129
    float* wr_s = L_s + 16512;         // 512
    float* u_s  = wr_s + 512;          // 128
    float* p_s  = u_s + 128;           // 128
    float* ww_s = p_s + 128;           // 128
    float* xi   = ww_s + 128;          // 472
    float* fwdw = xi + 472;            // 512
    float* bwdw = fwdw + 512;          // 512
    float* crs  = bwdw + 512;          // 512
    float* unew = crs + 512;           // 128
    float* srt  = unew + 128;          // 128
    float* incl = srt + 128;           // 128
    float* cpex = incl + 128;          // 128
    float* a_s  = cpex + 128;          // 128
    float* wwn  = a_s + 128;           // 128
    float* Mn   = wwn + 128;           // 128 (kept for layout, unused)
    float* red  = Mn + 128;            // 128
    float* xtra = red + 128;           // 128 (spare)
    float* act  = xtra + 128;          // 176
    int* rank_s = (int*)(act + 176);   // 128
    (void)xtra; (void)Mn;
    // packed tables carved from scr (free during phase D)
    float* wrT  = scr;                 // 512: wrT[m*4+r] = wr_s[r*128+m]
    float* crsT = scr + 512;           // 512: crsT[n*4+r]
    float* rkT  = scr + 1024;          // 256: rkT[w*4+r] = xi[r*64+w]

    const int tid  = threadIdx.x;
    const int bx   = blockIdx.x;
    const int wid  = tid >> 5;         // 0..15
    const int lane = tid & 31;
    const int b    = bx;

    for (int i=tid;i<768*16;i+=THR){
        int k = i >> 4, c = i & 15;
        W_A[i] = g_Wt[(size_t)k*G4H + bx*16 + c];
    }
    for (int i=tid;i<512*4;i+=THR){
        int k = i >> 2, c = i & 3;
        int col = bx*4 + c;
        W_C[i] = (col < IFACE_) ? W_iface[(size_t)k*IFACE_ + col] : 0.f;
    }
    if (bx < B_){
        for (int i=tid;i<128*65;i+=THR)  M_s[i]=0.f;
        for (int i=tid;i<128*129;i+=THR) L_s[i]=0.f;
        for (int i=tid;i<512;i+=THR)     wr_s[i]=0.f;
        if (tid < N_){ u_s[tid]=0.f; p_s[tid]=0.f; ww_s[tid]=0.f; }
    }
    __syncthreads();

    float c_reg = 0.f;
    unsigned ep = 0;
    ull* scr2 = (ull*)scr;

    for (int t=0;t<T_;t++){
        const int rd = t & 1, wrb = rd ^ 1;

        // ============ Phase A: LSTM gemm (split-K over 16 warps, f32x2) ============
        {
            const int kbeg = wid*48;
            ull acc2[8];
            #pragma unroll
            for (int c=0;c<8;c++) acc2[c]=0ull;
            const float* hrd = g_hT[rd];
            #pragma unroll 4
            for (int k=kbeg;k<kbeg+48;k++){
                const float* ap = (k < 256) ? (g_rvT + k*B_) : (hrd + (k-256)*B_);
                ull as = splat2f(ap[lane]);
                const ulonglong2* wp = (const ulonglong2*)(W_A + k*16);
                ulonglong2 w01 = wp[0], w23 = wp[1], w45 = wp[2], w67 = wp[3];
                ffma2(acc2[0], as, w01.x); ffma2(acc2[1], as, w01.y);
                ffma2(acc2[2], as, w23.x); ffma2(acc2[3], as, w23.y);
                ffma2(acc2[4], as, w45.x); ffma2(acc2[5], as, w45.y);
                ffma2(acc2[6], as, w67.x); ffma2(acc2[7], as, w67.y);
            }
            #pragma unroll
            for (int c=0;c<8;c++) scr2[wid*256 + c*32 + lane] = acc2[c];
        }
        __syncthreads();
        if (tid < 128){
            int uu = tid >> 5;
            float4 s = *(const float4*)(g_G0 + ((size_t)lane*T_ + t)*G4H + bx*16 + uu*4);
            ull s01 = pack2(s.x, s.y), s23 = pack2(s.z, s.w);
            #pragma unroll
            for (int w16=0;w16<16;w16++){
                fadd2(s01, scr2[w16*256 + (2*uu  )*32 + lane]);
                fadd2(s23, scr2[w16*256 + (2*uu+1)*32 + lane]);
            }
            float2 g01 = unpack2(s01), g23 = unpack2(s23);
            float c = sigf(g01.y)*c_reg + sigf(g01.x)*tanhf(g23.x);
            float h = sigf(g23.y)*tanhf(c);
            c_reg = c;
            int jj = bx*4 + uu;
            g_hT[wrb][jj*B_ + lane] = h;
            size_t btrow = (size_t)lane*T_ + t;
            __nv_bfloat16 hh = __float2bfloat16(h);
            g_Uhi[btrow*KU + jj] = hh;
            g_Ulo[btrow*KU + jj] = __float2bfloat16(h - __bfloat162float(hh));
        }
        gridbar(++ep);

        // ============ Phase C: iface gemm (split-K over 16 warps) ============
        if (bx < 118){
            const int kbeg = wid*32;
            float a0=0.f,a1=0.f,a2=0.f,a3=0.f;
            const float* hsrc = g_hT[wrb];
            #pragma unroll 4
            for (int k=kbeg;k<kbeg+32;k++){
                float a = hsrc[k*B_ + lane];
                float4 wv = *(const float4*)(W_C + k*4);
                a0 += a*wv.x; a1 += a*wv.y; a2 += a*wv.z; a3 += a*wv.w;
            }
            scr[wid*128 +       lane] = a0;
            scr[wid*128 +  32 + lane] = a1;
            scr[wid*128 +  64 + lane] = a2;
            scr[wid*128 +  96 + lane] = a3;
            __syncthreads();
            if (tid < 128){
                int c = tid >> 5, col = bx*4 + c;
                if (col < IFACE_){
                    float s = b_iface[col];
                    #pragma unroll
                    for (int w16=0;w16<16;w16++) s += scr[w16*128 + c*32 + lane];
                    g_xiT[col*B_ + lane] = s;
                }
            }
        }
        gridbar(++ep);

        // ============ Phase D: DNC memory step (blocks 0..31) ============
        if (bx < B_){
            for (int i=tid;i<IFACE_;i+=THR) xi[i] = g_xiT[i*B_ + b];
            // packed OLD-wr table (wr_s stable since last step)
            wrT[tid] = wr_s[((tid&3)<<7) | (tid>>2)];
            __syncthreads();

            if (tid < 64){
                act[8+tid]  = sigf(xi[325+tid]);
                act[72+tid] = xi[389+tid];
            } else if (tid < 68){
                act[tid-64] = 1.f + splusf(xi[256 + (tid-64)]);
            } else if (tid == 68){
                act[4] = 1.f + splusf(xi[324]);
            } else if (tid < 73){
                act[136 + (tid-69)] = sigf(xi[453 + (tid-69)]);
            } else if (tid == 73){
                act[140] = sigf(xi[457]);
            } else if (tid == 74){
                act[141] = sigf(xi[458]);
            } else if (tid < 79){
                int r = tid - 75;
                float q0=xi[459+r*3], q1=xi[459+r*3+1], q2=xi[459+r*3+2];
                float m = fmaxf(q0, fmaxf(q1,q2));
                float e0=expf(q0-m), e1=expf(q1-m), e2=expf(q2-m);
                float s = e0+e1+e2;
                act[144+r*3]=e0/s; act[145+r*3]=e1/s; act[146+r*3]=e2/s;
            } else if (tid < 83){
                int r = tid - 79; float s = 0.f;
                #pragma unroll 8
                for (int w=0;w<WD_;w++){ float v = xi[r*WD_+w]; s += v*v; }
                act[156+r] = sqrtf(s);
            } else if (tid == 83){
                float s = 0.f;
                #pragma unroll 8
                for (int w=0;w<WD_;w++){ float v = xi[260+w]; s += v*v; }
                act[160] = sqrtf(s);
            } else if (tid >= 256){
                // packed read-key table rkT[w*4+r] = xi[r*64+w]
                int idx = tid - 256;
                rkT[idx] = xi[((idx&3)<<6) | (idx>>2)];
            }
            __syncthreads();

            if (tid < N_){
                float psi = 1.f;
                #pragma unroll
                for (int r=0;r<R_;r++) psi *= (1.f - act[136+r]*wr_s[r*N_+tid]);
                float uo=u_s[tid], wo=ww_s[tid];
                unew[tid] = (uo + wo - uo*wo)*psi;
            }
            __syncthreads();

            if (tid < N_){
                float ui = unew[tid]; int rk = 0;
                #pragma unroll 8
                for (int j=0;j<N_;j++){
                    float uj = unew[j];
                    rk += (uj < ui) || (uj == ui && j < tid);
                }
                rank_s[tid] = rk;
                srt[rk] = ui;
            }
            __syncthreads();

            float cp_p = 1.f;
            if (tid < N_){
                int w4 = tid >> 5, ln = tid & 31;
                cp_p = srt[tid];
                #pragma unroll
                for (int off=1;off<32;off<<=1){
                    float o = __shfl_up_sync(0xffffffffu, cp_p, off);
                    if (ln >= off) cp_p *= o;
                }
                if (ln == 31) red[w4] = cp_p;
            }
            __syncthreads();
            if (tid < N_){
                int w4 = tid >> 5;
                float pre = 1.f;
                #pragma unroll
                for (int j=0;j<3;j++) if (j < w4) pre *= red[j];
                incl[tid] = cp_p * pre;
            }
            __syncthreads();
            if (tid < N_) cpex[tid] = (tid == 0) ? 1.f : incl[tid-1];
            __syncthreads();

            float score_w = 0.f, ew = 0.f;
            if (tid < N_){
                a_s[tid] = (1.f - unew[tid]) * cpex[rank_s[tid]];
                float s2=0.f, dot=0.f;
                #pragma unroll 8
                for (int w=0;w<WD_;w++){ float m = M_s[tid*65+w]; s2 += m*m; dot += m*xi[260+w]; }
                score_w = act[4] * (dot / (act[160]*sqrtf(s2) + EPSF));
                float v = score_w;
                #pragma unroll
                for (int o=16;o;o>>=1) v = fmaxf(v, __shfl_xor_sync(0xffffffffu, v, o));
                if ((tid&31)==0) red[tid>>5] = v;
            }
            __syncthreads();
            float mxw = fmaxf(fmaxf(red[0],red[1]), fmaxf(red[2],red[3]));
            if (tid < N_){
                ew = expf(score_w - mxw);
                float s = ew;
                #pragma unroll
                for (int o=16;o;o>>=1) s += __shfl_xor_sync(0xffffffffu, s, o);
                if ((tid&31)==0) red[4 + (tid>>5)] = s;
            }
            __syncthreads();
            float sden = red[4]+red[5]+red[6]+red[7];
            if (tid < N_){
                float wv = act[141]*(act[140]*a_s[tid] + (1.f-act[140])*(ew/sden));
                wwn[tid] = wv;
                float s = wv;
                #pragma unroll
                for (int o=16;o;o>>=1) s += __shfl_xor_sync(0xffffffffu, s, o);
                if ((tid&31)==0) red[8 + (tid>>5)] = s;
            }
            __syncthreads();
            float sumww = red[8]+red[9]+red[10]+red[11];

            for (int i=tid;i<N_*WD_;i+=THR){
                int n=i>>6, w=i&63;
                float wwv = wwn[n];
                M_s[n*65+w] = M_s[n*65+w]*(1.f - wwv*act[8+w]) + wwv*act[72+w];
            }
            for (int i=tid;i<N_*N_;i+=THR){
                int n=i>>7, m=i&127;
                float v = (n==m) ? 0.f
                         : (1.f - wwn[n] - wwn[m])*L_s[n*129+m] + wwn[n]*p_s[m];
                L_s[n*129+m] = v;
            }
            __syncthreads();
            if (tid < N_) p_s[tid] = (1.f - sumww)*p_s[tid] + wwn[tid];

            // fwd/bwd (new L, OLD wr via wrT): thread-per-n, 4 r's each
            if (tid < N_){
                int n = tid;
                float f0=0.f,f1=0.f,f2=0.f,f3=0.f, b0=0.f,b1=0.f,b2=0.f,b3=0.f;
                #pragma unroll 4
                for (int m=0;m<N_;m++){
                    float lr = L_s[n*129+m];
                    float lc = L_s[m*129+n];
                    float4 w4 = *(const float4*)(wrT + m*4);
                    f0 += lr*w4.x; f1 += lr*w4.y; f2 += lr*w4.z; f3 += lr*w4.w;
                    b0 += lc*w4.x; b1 += lc*w4.y; b2 += lc*w4.z; b3 += lc*w4.w;
                }
                fwdw[      n]=f0; fwdw[  N_+n]=f1; fwdw[2*N_+n]=f2; fwdw[3*N_+n]=f3;
                bwdw[      n]=b0; bwdw[  N_+n]=b1; bwdw[2*N_+n]=b2; bwdw[3*N_+n]=b3;
            }
            // read content scores (new M) with packed rkT; folds M-norm
            if (tid < N_){
                float s2=0.f, d0=0.f,d1=0.f,d2=0.f,d3=0.f;
                #pragma unroll 8
                for (int w=0;w<WD_;w++){
                    float m = M_s[tid*65+w];
                    s2 += m*m;
                    float4 rk4 = *(const float4*)(rkT + w*4);
                    d0 += m*rk4.x; d1 += m*rk4.y; d2 += m*rk4.z; d3 += m*rk4.w;
                }
                float mn = sqrtf(s2);
                crs[      tid] = act[0]*(d0/(act[156]*mn + EPSF));
                crs[  N_+tid] = act[1]*(d1/(act[157]*mn + EPSF));
                crs[2*N_+tid] = act[2]*(d2/(act[158]*mn + EPSF));
                crs[3*N_+tid] = act[3]*(d3/(act[159]*mn + EPSF));
            }
            __syncthreads();
            if (tid < 128){
                int r = tid>>5, ln = tid&31;
                float v = fmaxf(fmaxf(crs[r*N_+ln],crs[r*N_+ln+32]),
                                fmaxf(crs[r*N_+ln+64],crs[r*N_+ln+96]));
                #pragma unroll
                for (int o=16;o;o>>=1) v = fmaxf(v, __shfl_xor_sync(0xffffffffu, v, o));
                if (ln==0) act[164+r]=v;
            }
            __syncthreads();
            if (tid < 128){
                int r = tid>>5, ln = tid&31;
                float m = act[164+r];
                float e0=expf(crs[r*N_+ln   ]-m);
                float e1=expf(crs[r*N_+ln+32]-m);
                float e2=expf(crs[r*N_+ln+64]-m);
                float e3=expf(crs[r*N_+ln+96]-m);
                crs[r*N_+ln]=e0; crs[r*N_+ln+32]=e1; crs[r*N_+ln+64]=e2; crs[r*N_+ln+96]=e3;
                float s = e0+e1+e2+e3;
                #pragma unroll
                for (int o=16;o;o>>=1) s += __shfl_xor_sync(0xffffffffu, s, o);
                if (ln==0) act[168+r]=s;
            }
            __syncthreads();
            // new read weights (+ packed crsT)
            for (int i=tid;i<R_*N_;i+=THR){
                int r = i>>7, n = i&127;
                float w = act[144+r*3]*bwdw[i] + act[145+r*3]*(crs[i]/act[168+r]) + act[146+r*3]*fwdw[i];
                crs[i] = w;
                crsT[n*4 + r] = w;
            }
            __syncthreads();
            // rv = wr @ M : thread-per-w, 4 r's, packed crsT broadcast
            if (tid < WD_){
                int w = tid;
                float s0=0.f,s1=0.f,s2v=0.f,s3=0.f;
                #pragma unroll 4
                for (int n=0;n<N_;n++){
                    float mv = M_s[n*65+w];
                    float4 c4 = *(const float4*)(crsT + n*4);
                    s0 += c4.x*mv; s1 += c4.y*mv; s2v += c4.z*mv; s3 += c4.w*mv;
                }
                size_t btrow = (size_t)b*T_ + t;
                float sv[4] = {s0,s1,s2v,s3};
                #pragma unroll
                for (int r=0;r<4;r++){
                    int idx = r*WD_ + w;
                    g_rvT[idx*B_ + b] = sv[r];
                    __nv_bfloat16 sh = __float2bfloat16(sv[r]);
                    g_Uhi[btrow*KU + H_ + idx] = sh;
                    g_Ulo[btrow*KU + H_ + idx] = __float2bfloat16(sv[r] - __bfloat162float(sh));
                }
            }
            __syncthreads();
            for (int i=tid;i<R_*N_;i+=THR) wr_s[i] = crs[i];
            if (tid < N_){ u_s[tid]=unew[tid]; ww_s[tid]=wwn[tid]; }
        }
        gridbar(++ep);
    }
}

// ---------------- launcher ----------------
extern "C" void kernel_launch(void* const* d_in, const int* in_sizes, int n_in,
                              void* d_out, int out_size){
    const int*   tokens  = (const int*)  d_in[0];
    const float* emb     = (const float*)d_in[1];
    const float* w_ih    = (const float*)d_in[2];
    const float* w_hh    = (const float*)d_in[3];
    const float* b_lstm  = (const float*)d_in[4];
    const float* W_iface = (const float*)d_in[5];
    const float* b_iface = (const float*)d_in[6];
    const float* W_out   = (const float*)d_in[7];
    const float* b_out   = (const float*)d_in[8];
    float* out = (float*)d_out;

    const int loop_smem = LOOP_SMEM_FLOATS * (int)sizeof(float);
    cudaFuncSetAttribute(loop_kernel, cudaFuncAttributeMaxDynamicSharedMemorySize, loop_smem);
    const int gout_smem = 8 * TILE_BF * (int)sizeof(__nv_bfloat16);
    cudaFuncSetAttribute(gemm_out, cudaFuncAttributeMaxDynamicSharedMemorySize, gout_smem);

    void *pX, *pG0, *pWihT, *pBl;
    cudaGetSymbolAddress(&pX, g_X);
    cudaGetSymbolAddress(&pG0, g_G0);
    cudaGetSymbolAddress(&pWihT, g_WihT);
    cudaGetSymbolAddress(&pBl, g_bl);

    embed_kernel<<<(BT_*E_ + 255)/256, 256>>>(tokens, emb);
    prep_w<<<(KU*G4H + 255)/256, 256>>>(w_ih, w_hh, b_lstm);
    prep_outT<<<dim3(VPAD/32, KU/32), dim3(32,8)>>>(W_out);
    zero_state<<<64, 256>>>();

    // G0 = X (8192x256) @ WihT (256x2048) + permuted bias
    sgemm128<<<dim3(G4H/128, BT_/128), 256>>>((const float*)pX, (const float*)pWihT,
                                              (const float*)pBl, (float*)pG0, BT_, G4H, E_);

    loop_kernel<<<NBLK, THR, loop_smem>>>(W_iface, b_iface);

    // out = U (8192x768) @ W_out (768x10000) + b_out   [bf16-split tensor cores]
    gemm_out<<<dim3((V_+127)/128, BT_/128), 256, gout_smem>>>(b_out, out);
}

// round 9
// speedup vs baseline: 2.4451x; 1.3487x over previous
#include <cuda_runtime.h>
#include <cuda_bf16.h>
#include <math.h>

#define B_ 32
#define T_ 256
#define V_ 10000
#define VPAD 10112
#define E_ 256
#define H_ 512
#define N_ 128
#define WD_ 64
#define R_ 4
#define IFACE_ 471
#define G4H 2048          // 4*H
#define KU 768            // H + R*WD
#define BT_ (B_*T_)       // 8192
#define EPSF 1e-6f
#define NBLK 128
#define THR 512

typedef unsigned long long ull;

// ---------------- f32x2 helpers ----------------
__device__ __forceinline__ ull pack2(float x, float y){
    ull r; asm("mov.b64 %0, {%1,%2};" : "=l"(r) : "r"(__float_as_uint(x)), "r"(__float_as_uint(y))); return r;
}
__device__ __forceinline__ ull splat2f(float x){ return pack2(x, x); }
__device__ __forceinline__ float2 unpack2(ull v){
    unsigned lo, hi;
    asm("mov.b64 {%0,%1}, %2;" : "=r"(lo), "=r"(hi) : "l"(v));
    return make_float2(__uint_as_float(lo), __uint_as_float(hi));
}
__device__ __forceinline__ void ffma2(ull& d, ull a, ull b){
    asm("fma.rn.f32x2 %0, %1, %2, %0;" : "+l"(d) : "l"(a), "l"(b));
}
__device__ __forceinline__ void fadd2(ull& d, ull a){
    asm("add.rn.f32x2 %0, %0, %1;" : "+l"(d) : "l"(a));
}
__device__ __forceinline__ void cpasync16(unsigned dst, const void* src){
    asm volatile("cp.async.cg.shared.global [%0], [%1], 16;" :: "r"(dst), "l"(src));
}

// ---------------- GPU-scope relaxed flag ops ----------------
__device__ __forceinline__ unsigned ld_rlx(const unsigned* p){
    unsigned v;
    asm volatile("ld.relaxed.gpu.global.u32 %0, [%1];" : "=r"(v) : "l"(p) : "memory");
    return v;
}
__device__ __forceinline__ void st_rlx(unsigned* p, unsigned v){
    asm volatile("st.relaxed.gpu.global.u32 [%0], %1;" :: "l"(p), "r"(v) : "memory");
}

// ---------------- device scratch ----------------
__device__ __align__(128) float g_X[BT_*E_];
__device__ __align__(128) float g_G0[(size_t)BT_*G4H];
__device__ __align__(128) float g_WihT[E_*G4H];               // permuted cols
__device__ __align__(128) float g_Wt[KU*G4H];                 // permuted cols: [rv ; h]
__device__ __align__(128) float g_bl[G4H];                    // permuted bias
__device__ __align__(128) __nv_bfloat16 g_WhiT[(size_t)VPAD*KU];
__device__ __align__(128) __nv_bfloat16 g_WloT[(size_t)VPAD*KU];
__device__ __align__(128) __nv_bfloat16 g_Uhi[(size_t)BT_*KU];
__device__ __align__(128) __nv_bfloat16 g_Ulo[(size_t)BT_*KU];
__device__ __align__(128) float g_hT[2][H_*B_];               // double-buffered [feat][batch]
__device__ __align__(128) float g_rvT[R_*WD_*B_];
__device__ __align__(128) float g_xiT[IFACE_*B_];
__device__ __align__(128) float g_Gh[B_*G4H];                 // [batch][col] h-part of next gates
__device__ __align__(128) unsigned g_flags[NBLK*32];
__device__ unsigned g_gen;

__device__ __forceinline__ float sigf(float x){ return 1.f/(1.f + expf(-x)); }
__device__ __forceinline__ float splusf(float x){ return fmaxf(x,0.f) + log1pf(expf(-fabsf(x))); }

// ---------------- flag-based grid barrier (gpu-scope; cross-block data via __ldcg) ----------------
__device__ __forceinline__ void gridbar(unsigned ep){
    __syncthreads();
    const int tid = threadIdx.x;
    const int bx  = blockIdx.x;
    if (tid == 0){
        __threadfence();                       // order this block's writes to L2
        st_rlx(&g_flags[bx*32], ep);
    }
    if (bx == 0){
        if (tid < NBLK){
            while (ld_rlx(&g_flags[tid*32]) < ep) { }
        }
        __syncthreads();
        if (tid == 0) st_rlx((unsigned*)&g_gen, ep);
    } else {
        if (tid == 0){
            while (ld_rlx((const unsigned*)&g_gen) < ep) { }
        }
    }
    __syncthreads();
}

// ---------------- prep kernels ----------------
__global__ void embed_kernel(const int* __restrict__ tok, const float* __restrict__ emb){
    int i = blockIdx.x*256 + threadIdx.x;
    if (i >= BT_*E_) return;
    int bt = i / E_, e = i % E_;
    g_X[i] = tanhf(emb[(size_t)tok[bt]*E_ + e]);
}

// weight permute + all state zeroing (zero_state folded in)
__global__ void prep_w(const float* __restrict__ w_ih, const float* __restrict__ w_hh,
                       const float* __restrict__ b_lstm){
    int i = blockIdx.x*256 + threadIdx.x;
    if (i < KU*G4H){
        int k = i >> 11, col = i & 2047;
        int jj = col >> 2, g = col & 3;
        int j = g*H_ + jj;
        g_Wt[i] = (k < R_*WD_) ? w_ih[(size_t)j*(E_+R_*WD_) + E_ + k]
                               : w_hh[(size_t)j*H_ + (k - R_*WD_)];
    }
    if (i < E_*G4H){
        int e = i >> 11, col = i & 2047;
        int jj = col >> 2, g = col & 3;
        int j = g*H_ + jj;
        g_WihT[i] = w_ih[(size_t)j*(E_+R_*WD_) + e];
    }
    if (i < G4H){
        int jj = i >> 2, g = i & 3;
        g_bl[i] = b_lstm[g*H_ + jj];
    }
    if (i < 2*H_*B_) ((float*)g_hT)[i] = 0.f;
    if (i < R_*WD_*B_) g_rvT[i] = 0.f;
    if (i < B_*G4H) g_Gh[i] = 0.f;
    if (i < NBLK*32) g_flags[i] = 0u;
    if (i == 0) g_gen = 0u;
}

// tiled transpose + bf16 hi/lo split
__global__ void prep_outT(const float* __restrict__ W_out){
    __shared__ float tile[32][33];
    int n0 = blockIdx.x*32, k0 = blockIdx.y*32;
    int tx = threadIdx.x, ty = threadIdx.y;   // 32 x 8
    #pragma unroll
    for (int dy=0;dy<32;dy+=8){
        int k = k0+ty+dy, n = n0+tx;
        tile[ty+dy][tx] = (n < V_) ? W_out[(size_t)k*V_+n] : 0.f;
    }
    __syncthreads();
    #pragma unroll
    for (int dy=0;dy<32;dy+=8){
        int n = n0+ty+dy, k = k0+tx;
        float v = tile[tx][ty+dy];
        __nv_bfloat16 h = __float2bfloat16(v);
        g_WhiT[(size_t)n*KU+k] = h;
        g_WloT[(size_t)n*KU+k] = __float2bfloat16(v - __bfloat162float(h));
    }
}

// ---------------- pipelined fp32 SGEMM (R4): C = A(MxK)@B(KxN) (+bias) ----------------
__global__ __launch_bounds__(256) void sgemm128(const float* __restrict__ A,
                         const float* __restrict__ Bm,
                         const float* __restrict__ bias, float* __restrict__ C,
                         int M, int Nn, int K){
    __shared__ float As[2][8][128];
    __shared__ float Bs[2][8][128];
    int tid = threadIdx.x;
    int row0 = blockIdx.y*128, col0 = blockIdx.x*128;
    int trow = (tid >> 4) * 8;
    int tcol = (tid & 15) * 8;
    float acc[8][8];
    #pragma unroll
    for (int i=0;i<8;i++)
        #pragma unroll
        for (int j=0;j<8;j++) acc[i][j]=0.f;

    int arow = tid >> 1, ak = (tid & 1)*4;
    int bk = tid >> 5,  bn = (tid & 31)*4;
    const float* Aptr = A + (size_t)(row0 + arow)*K + ak;
    int gn = col0 + bn;

    float4 av = *(const float4*)(Aptr);
    float4 bv = make_float4(0.f,0.f,0.f,0.f);
    if (gn < Nn) bv = *(const float4*)(Bm + (size_t)bk*Nn + gn);
    As[0][ak+0][arow]=av.x; As[0][ak+1][arow]=av.y; As[0][ak+2][arow]=av.z; As[0][ak+3][arow]=av.w;
    *(float4*)(&Bs[0][bk][bn]) = bv;
    __syncthreads();

    int buf = 0;
    for (int k0=0;k0<K;k0+=8){
        bool more = (k0 + 8) < K;
        if (more){
            av = *(const float4*)(Aptr + k0 + 8);
            bv = make_float4(0.f,0.f,0.f,0.f);
            if (gn < Nn) bv = *(const float4*)(Bm + (size_t)(k0+8+bk)*Nn + gn);
        }
        #pragma unroll
        for (int kk=0;kk<8;kk++){
            float ar[8], br[8];
            *(float4*)(ar)   = *(const float4*)(&As[buf][kk][trow]);
            *(float4*)(ar+4) = *(const float4*)(&As[buf][kk][trow+4]);
            *(float4*)(br)   = *(const float4*)(&Bs[buf][kk][tcol]);
            *(float4*)(br+4) = *(const float4*)(&Bs[buf][kk][tcol+4]);
            #pragma unroll
            for (int i=0;i<8;i++)
                #pragma unroll
                for (int j=0;j<8;j++) acc[i][j] += ar[i]*br[j];
        }
        if (more){
            int nb = buf ^ 1;
            As[nb][ak+0][arow]=av.x; As[nb][ak+1][arow]=av.y; As[nb][ak+2][arow]=av.z; As[nb][ak+3][arow]=av.w;
            *(float4*)(&Bs[nb][bk][bn]) = bv;
            __syncthreads();
            buf = nb;
        }
    }
    #pragma unroll
    for (int i=0;i<8;i++){
        size_t gm = (size_t)(row0 + trow + i);
        #pragma unroll
        for (int j=0;j<8;j+=4){
            int gnn = col0 + tcol + j;
            if (gnn < Nn){
                float4 v = make_float4(acc[i][j],acc[i][j+1],acc[i][j+2],acc[i][j+3]);
                if (bias){ v.x+=bias[gnn]; v.y+=bias[gnn+1]; v.z+=bias[gnn+2]; v.w+=bias[gnn+3]; }
                *(float4*)(C + gm*Nn + gnn) = v;
            }
        }
    }
}

// ---------------- bf16-split tensor-core GEMM: out = U@W_out + b ----------------
#define PITCH 40
#define TILE_BF (128*PITCH)

__device__ __forceinline__ void mma_bf16(float* c, unsigned a0,unsigned a1,unsigned a2,unsigned a3,
                                         unsigned b0, unsigned b1){
    asm volatile("mma.sync.aligned.m16n8k16.row.col.f32.bf16.bf16.f32 "
        "{%0,%1,%2,%3}, {%4,%5,%6,%7}, {%8,%9}, {%0,%1,%2,%3};"
        : "+f"(c[0]),"+f"(c[1]),"+f"(c[2]),"+f"(c[3])
        : "r"(a0),"r"(a1),"r"(a2),"r"(a3),"r"(b0),"r"(b1));
}

__global__ __launch_bounds__(256) void gemm_out(const float* __restrict__ bias,
                                                float* __restrict__ C){
    extern __shared__ __align__(16) char smraw[];
    __nv_bfloat16* AsHi = (__nv_bfloat16*)smraw;
    __nv_bfloat16* AsLo = AsHi + 2*TILE_BF;
    __nv_bfloat16* BsHi = AsLo + 2*TILE_BF;
    __nv_bfloat16* BsLo = BsHi + 2*TILE_BF;

    const int tid = threadIdx.x, lane = tid & 31, wid = tid >> 5;
    const int warp_m = wid >> 2, warp_n = wid & 3;
    const int gid = lane >> 2, tig = lane & 3;
    const int m0 = blockIdx.y*128, n0 = blockIdx.x*128;

    float acc[4][4][4];
    #pragma unroll
    for (int i=0;i<4;i++)
        #pragma unroll
        for (int j=0;j<4;j++)
            #pragma unroll
            for (int q=0;q<4;q++) acc[i][j][q]=0.f;

    unsigned sAhi = (unsigned)__cvta_generic_to_shared(AsHi);
    unsigned sAlo = (unsigned)__cvta_generic_to_shared(AsLo);
    unsigned sBhi = (unsigned)__cvta_generic_to_shared(BsHi);
    unsigned sBlo = (unsigned)__cvta_generic_to_shared(BsLo);

    auto loadA = [&](int s, int kt){
        #pragma unroll
        for (int it=0; it<2; it++){
            int idx = it*256 + tid;
            int row = idx>>2, seg = idx&3;
            size_t goff = (size_t)(m0+row)*KU + kt*32 + seg*8;
            unsigned doff = (unsigned)((s*TILE_BF + row*PITCH + seg*8)*2);
            cpasync16(sAhi + doff, g_Uhi + goff);
            cpasync16(sAlo + doff, g_Ulo + goff);
        }
    };
    auto loadB = [&](int s, int kt){
        #pragma unroll
        for (int it=0; it<2; it++){
            int idx = it*256 + tid;
            int row = idx>>2, seg = idx&3;
            size_t goff = (size_t)(n0+row)*KU + kt*32 + seg*8;
            unsigned doff = (unsigned)((s*TILE_BF + row*PITCH + seg*8)*2);
            cpasync16(sBhi + doff, g_WhiT + goff);
            cpasync16(sBlo + doff, g_WloT + goff);
        }
    };
    auto compute = [&](int s){
        #pragma unroll
        for (int kk=0;kk<2;kk++){
            const int kb = kk*16 + tig*2;
            unsigned bh[4][2], bl[4][2];
            #pragma unroll
            for (int j=0;j<4;j++){
                int nl = warp_n*32 + j*8 + gid;
                const __nv_bfloat16* bp  = BsHi + s*TILE_BF + nl*PITCH + kb;
                const __nv_bfloat16* bp2 = BsLo + s*TILE_BF + nl*PITCH + kb;
                bh[j][0] = *(const unsigned*)bp;   bh[j][1] = *(const unsigned*)(bp+8);
                bl[j][0] = *(const unsigned*)bp2;  bl[j][1] = *(const unsigned*)(bp2+8);
            }
            #pragma unroll
            for (int i=0;i<4;i++){
                int mr = warp_m*64 + i*16;
                const __nv_bfloat16* ap  = AsHi + s*TILE_BF + (mr+gid)*PITCH + kb;
                const __nv_bfloat16* ap2 = AsLo + s*TILE_BF + (mr+gid)*PITCH + kb;
                unsigned ah0 = *(const unsigned*)ap;
                unsigned ah1 = *(const unsigned*)(ap + 8*PITCH);
                unsigned ah2 = *(const unsigned*)(ap + 8);
                unsigned ah3 = *(const unsigned*)(ap + 8*PITCH + 8);
                unsigned al0 = *(const unsigned*)ap2;
                unsigned al1 = *(const unsigned*)(ap2 + 8*PITCH);
                unsigned al2 = *(const unsigned*)(ap2 + 8);
                unsigned al3 = *(const unsigned*)(ap2 + 8*PITCH + 8);
                #pragma unroll
                for (int j=0;j<4;j++){
                    mma_bf16(acc[i][j], ah0,ah1,ah2,ah3, bh[j][0],bh[j][1]);
                    mma_bf16(acc[i][j], ah0,ah1,ah2,ah3, bl[j][0],bl[j][1]);
                    mma_bf16(acc[i][j], al0,al1,al2,al3, bh[j][0],bh[j][1]);
                }
            }
        }
    };

    loadA(0, 0); loadB(0, 0);
    asm volatile("cp.async.commit_group;");
    asm volatile("cp.async.wait_group 0;");
    __syncthreads();

    const int KT = KU/32;   // 24
    for (int kt=0; kt<KT; kt++){
        int buf = kt & 1;
        if (kt+1 < KT){
            loadA(buf^1, kt+1);
            loadB(buf^1, kt+1);
            asm volatile("cp.async.commit_group;");
        }
        compute(buf);
        if (kt+1 < KT){
            asm volatile("cp.async.wait_group 0;");
        }
        __syncthreads();
    }

    #pragma unroll
    for (int i=0;i<4;i++){
        int gm = m0 + warp_m*64 + i*16 + gid;
        #pragma unroll
        for (int j=0;j<4;j++){
            int gn = n0 + warp_n*32 + j*8 + tig*2;
            if (gn < V_){
                float b0 = bias[gn], b1 = bias[gn+1];
                *(float2*)(C + (size_t)gm*V_ + gn) = make_float2(acc[i][j][0]+b0, acc[i][j][1]+b1);
                *(float2*)(C + (size_t)(gm+8)*V_ + gn) = make_float2(acc[i][j][2]+b0, acc[i][j][3]+b1);
            }
        }
    }
}

// ---------------- persistent sequential loop (pipelined Gh precompute) ----------------
// smem floats: W_A 4096 | W_C 2048 | scr 8192 | DNC region 28808
#define LOOP_SMEM_FLOATS (4096 + 2048 + 8192 + 28808)

__global__ __launch_bounds__(THR) void loop_kernel(const float* __restrict__ W_iface,
                                                   const float* __restrict__ b_iface){
    extern __shared__ float sm[];
    float* W_A  = sm;                  // 256*16 (rv-part LSTM weights, own 16 cols)
    float* W_C  = W_A + 4096;          // 512*4 (iface cols)
    float* scr  = W_C + 2048;          // 8192
    float* M_s  = scr + 8192;          // 128*65  (helpers: W_B overlay 512*32)
    float* L_s  = M_s + 8320;          // 128*129
    float* wr_s = L_s + 16512;         // 512
    float* u_s  = wr_s + 512;          // 128
    float* p_s  = u_s + 128;           // 128
    float* ww_s = p_s + 128;           // 128
    float* xi   = ww_s + 128;          // 472
    float* fwdw = xi + 472;            // 512
    float* bwdw = fwdw + 512;          // 512
    float* crs  = bwdw + 512;          // 512
    float* unew = crs + 512;           // 128
    float* srt  = unew + 128;          // 128
    float* incl = srt + 128;           // 128
    float* a_s  = incl + 128;          // 128
    float* wwn  = a_s + 128;           // 128
    float* red  = wwn + 128;           // 128
    float* act  = red + 128;           // 176
    int* rank_s = (int*)(act + 176);   // 128
    // packed tables carved from scr (free during phase D)
    float* wrT  = scr;                 // 512
    float* crsT = scr + 512;           // 512
    float* rkT  = scr + 1024;          // 256
    float* W_B  = M_s;                 // helpers: 512*32 h-part weights (16384 floats)

    const int tid  = threadIdx.x;
    const int bx   = blockIdx.x;
    const int wid  = tid >> 5;         // 0..15
    const int lane = tid & 31;
    const int b    = bx;

    // stage rv-part LSTM weights (all blocks, own 16 cols)
    for (int i=tid;i<256*16;i+=THR){
        int k = i >> 4, c = i & 15;
        W_A[i] = g_Wt[(size_t)k*G4H + bx*16 + c];
    }
    // stage iface weights
    for (int i=tid;i<512*4;i+=THR){
        int k = i >> 2, c = i & 3;
        int col = bx*4 + c;
        W_C[i] = (col < IFACE_) ? W_iface[(size_t)k*IFACE_ + col] : 0.f;
    }
    if (bx < B_){
        // DNC state init
        for (int i=tid;i<128*65;i+=THR)  M_s[i]=0.f;
        for (int i=tid;i<128*129;i+=THR) L_s[i]=0.f;
        for (int i=tid;i<512;i+=THR)     wr_s[i]=0.f;
        if (tid < N_){ u_s[tid]=0.f; p_s[tid]=0.f; ww_s[tid]=0.f; }
    } else if (bx < 96){
        // helpers: stage h-part weights for 32 cols
        for (int i=tid;i<512*32;i+=THR){
            int k = i >> 5, c = i & 31;
            W_B[i] = g_Wt[(size_t)(256+k)*G4H + (bx-32)*32 + c];
        }
    }
    __syncthreads();

    float c_reg = 0.f;
    unsigned ep = 0;
    ull* scr2 = (ull*)scr;

    for (int t=0;t<T_;t++){
        const int rd = t & 1, wrb = rd ^ 1;

        // ============ Phase A: gates = G0 + Gh + Wrv@rv ; LSTM elementwise ============
        {
            const int kbeg = wid*16;           // 16 warps x 16 K = 256
            ull acc2[8];
            #pragma unroll
            for (int c=0;c<8;c++) acc2[c]=0ull;
            #pragma unroll
            for (int k=kbeg;k<kbeg+16;k++){
                ull as = splat2f(__ldcg(g_rvT + k*B_ + lane));
                const ulonglong2* wp = (const ulonglong2*)(W_A + k*16);
                ulonglong2 w01 = wp[0], w23 = wp[1], w45 = wp[2], w67 = wp[3];
                ffma2(acc2[0], as, w01.x); ffma2(acc2[1], as, w01.y);
                ffma2(acc2[2], as, w23.x); ffma2(acc2[3], as, w23.y);
                ffma2(acc2[4], as, w45.x); ffma2(acc2[5], as, w45.y);
                ffma2(acc2[6], as, w67.x); ffma2(acc2[7], as, w67.y);
            }
            #pragma unroll
            for (int c=0;c<8;c++) scr2[wid*256 + c*32 + lane] = acc2[c];
        }
        __syncthreads();
        if (tid < 128){
            int uu = tid >> 5;
            float4 s = *(const float4*)(g_G0 + ((size_t)lane*T_ + t)*G4H + bx*16 + uu*4);
            float4 gh = __ldcg((const float4*)(g_Gh + (size_t)lane*G4H + bx*16 + uu*4));
            s.x += gh.x; s.y += gh.y; s.z += gh.z; s.w += gh.w;
            ull s01 = pack2(s.x, s.y), s23 = pack2(s.z, s.w);
            #pragma unroll
            for (int w16=0;w16<16;w16++){
                fadd2(s01, scr2[w16*256 + (2*uu  )*32 + lane]);
                fadd2(s23, scr2[w16*256 + (2*uu+1)*32 + lane]);
            }
            float2 g01 = unpack2(s01), g23 = unpack2(s23);
            float c = sigf(g01.y)*c_reg + sigf(g01.x)*tanhf(g23.x);
            float h = sigf(g23.y)*tanhf(c);
            c_reg = c;
            int jj = bx*4 + uu;
            g_hT[wrb][jj*B_ + lane] = h;
            size_t btrow = (size_t)lane*T_ + t;
            __nv_bfloat16 hh = __float2bfloat16(h);
            g_Uhi[btrow*KU + jj] = hh;
            g_Ulo[btrow*KU + jj] = __float2bfloat16(h - __bfloat162float(hh));
        }
        gridbar(++ep);

        // ============ Phase C: iface gemm (split-K over 16 warps) ============
        if (bx < 118){
            const int kbeg = wid*32;
            float a0=0.f,a1=0.f,a2=0.f,a3=0.f;
            const float* hsrc = g_hT[wrb];
            #pragma unroll 4
            for (int k=kbeg;k<kbeg+32;k++){
                float a = __ldcg(hsrc + k*B_ + lane);
                float4 wv = *(const float4*)(W_C + k*4);
                a0 += a*wv.x; a1 += a*wv.y; a2 += a*wv.z; a3 += a*wv.w;
            }
            scr[wid*128 +       lane] = a0;
            scr[wid*128 +  32 + lane] = a1;
            scr[wid*128 +  64 + lane] = a2;
            scr[wid*128 +  96 + lane] = a3;
            __syncthreads();
            if (tid < 128){
                int c = tid >> 5, col = bx*4 + c;
                if (col < IFACE_){
                    float s = b_iface[col];
                    #pragma unroll
                    for (int w16=0;w16<16;w16++) s += scr[w16*128 + c*32 + lane];
                    g_xiT[col*B_ + lane] = s;
                }
            }
        }
        gridbar(++ep);

        // ============ Phase D (blocks 0..31) || Gh precompute (blocks 32..95) ============
        if (bx < B_){
            int rk = 0;
            for (int i=tid;i<IFACE_;i+=THR) xi[i] = __ldcg(g_xiT + i*B_ + b);
            wrT[tid] = wr_s[((tid&3)<<7) | (tid>>2)];
            __syncthreads();

            if (tid < 64){
                act[8+tid]  = sigf(xi[325+tid]);
                act[72+tid] = xi[389+tid];
            } else if (tid < 68){
                act[tid-64] = 1.f + splusf(xi[256 + (tid-64)]);
            } else if (tid == 68){
                act[4] = 1.f + splusf(xi[324]);
            } else if (tid < 73){
                act[136 + (tid-69)] = sigf(xi[453 + (tid-69)]);
            } else if (tid == 73){
                act[140] = sigf(xi[457]);
            } else if (tid == 74){
                act[141] = sigf(xi[458]);
            } else if (tid < 79){
                int r = tid - 75;
                float q0=xi[459+r*3], q1=xi[459+r*3+1], q2=xi[459+r*3+2];
                float m = fmaxf(q0, fmaxf(q1,q2));
                float e0=expf(q0-m), e1=expf(q1-m), e2=expf(q2-m);
                float s = e0+e1+e2;
                act[144+r*3]=e0/s; act[145+r*3]=e1/s; act[146+r*3]=e2/s;
            } else if (tid < 83){
                int r = tid - 79; float s = 0.f;
                #pragma unroll 8
                for (int w=0;w<WD_;w++){ float v = xi[r*WD_+w]; s += v*v; }
                act[156+r] = sqrtf(s);
            } else if (tid == 83){
                float s = 0.f;
                #pragma unroll 8
                for (int w=0;w<WD_;w++){ float v = xi[260+w]; s += v*v; }
                act[160] = sqrtf(s);
            } else if (tid >= 256 && tid < 512){
                int idx = tid - 256;
                rkT[idx] = xi[((idx&3)<<6) | (idx>>2)];
            }
            __syncthreads();

            if (tid < N_){
                float psi = 1.f;
                #pragma unroll
                for (int r=0;r<R_;r++) psi *= (1.f - act[136+r]*wr_s[r*N_+tid]);
                float uo=u_s[tid], wo=ww_s[tid];
                unew[tid] = (uo + wo - uo*wo)*psi;
            }
            __syncthreads();

            if (tid < N_){
                float ui = unew[tid];
                #pragma unroll 8
                for (int j=0;j<N_;j++){
                    float uj = unew[j];
                    rk += (uj < ui) || (uj == ui && j < tid);
                }
                rank_s[tid] = rk;
                srt[rk] = ui;
            }
            __syncthreads();

            float cp_p = 1.f;
            if (tid < N_){
                int w4 = tid >> 5, ln = tid & 31;
                cp_p = srt[tid];
                #pragma unroll
                for (int off=1;off<32;off<<=1){
                    float o = __shfl_up_sync(0xffffffffu, cp_p, off);
                    if (ln >= off) cp_p *= o;
                }
                if (ln == 31) red[w4] = cp_p;
            }
            __syncthreads();
            if (tid < N_){
                int w4 = tid >> 5;
                float pre = 1.f;
                #pragma unroll
                for (int j=0;j<3;j++) if (j < w4) pre *= red[j];
                incl[tid] = cp_p * pre;
            }
            __syncthreads();

            float score_w = 0.f, ew = 0.f;
            if (tid < N_){
                float ce = (rk == 0) ? 1.f : incl[rk-1];      // exclusive cumprod at rank
                a_s[tid] = (1.f - unew[tid]) * ce;
                float s2=0.f, dot=0.f;
                #pragma unroll 8
                for (int w=0;w<WD_;w++){ float m = M_s[tid*65+w]; s2 += m*m; dot += m*xi[260+w]; }
                score_w = act[4] * (dot / (act[160]*sqrtf(s2) + EPSF));
                float v = score_w;
                #pragma unroll
                for (int o=16;o;o>>=1) v = fmaxf(v, __shfl_xor_sync(0xffffffffu, v, o));
                if ((tid&31)==0) red[tid>>5] = v;
            }
            __syncthreads();
            float mxw = fmaxf(fmaxf(red[0],red[1]), fmaxf(red[2],red[3]));
            if (tid < N_){
                ew = expf(score_w - mxw);
                float s = ew;
                #pragma unroll
                for (int o=16;o;o>>=1) s += __shfl_xor_sync(0xffffffffu, s, o);
                if ((tid&31)==0) red[4 + (tid>>5)] = s;
            }
            __syncthreads();
            float sden = red[4]+red[5]+red[6]+red[7];
            if (tid < N_){
                float wv = act[141]*(act[140]*a_s[tid] + (1.f-act[140])*(ew/sden));
                wwn[tid] = wv;
                float s = wv;
                #pragma unroll
                for (int o=16;o;o>>=1) s += __shfl_xor_sync(0xffffffffu, s, o);
                if ((tid&31)==0) red[8 + (tid>>5)] = s;
            }
            __syncthreads();
            float sumww = red[8]+red[9]+red[10]+red[11];

            for (int i=tid;i<N_*WD_;i+=THR){
                int n=i>>6, w=i&63;
                float wwv = wwn[n];
                M_s[n*65+w] = M_s[n*65+w]*(1.f - wwv*act[8+w]) + wwv*act[72+w];
            }
            for (int i=tid;i<N_*N_;i+=THR){
                int n=i>>7, m=i&127;
                float v = (n==m) ? 0.f
                         : (1.f - wwn[n] - wwn[m])*L_s[n*129+m] + wwn[n]*p_s[m];
                L_s[n*129+m] = v;
            }
            __syncthreads();
            if (tid < N_) p_s[tid] = (1.f - sumww)*p_s[tid] + wwn[tid];

            if (tid < N_){
                int n = tid;
                float f0=0.f,f1=0.f,f2=0.f,f3=0.f, b0=0.f,b1=0.f,b2=0.f,b3=0.f;
                #pragma unroll 4
                for (int m=0;m<N_;m++){
                    float lr = L_s[n*129+m];
                    float lc = L_s[m*129+n];
                    float4 w4 = *(const float4*)(wrT + m*4);
                    f0 += lr*w4.x; f1 += lr*w4.y; f2 += lr*w4.z; f3 += lr*w4.w;
                    b0 += lc*w4.x; b1 += lc*w4.y; b2 += lc*w4.z; b3 += lc*w4.w;
                }
                fwdw[      n]=f0; fwdw[  N_+n]=f1; fwdw[2*N_+n]=f2; fwdw[3*N_+n]=f3;
                bwdw[      n]=b0; bwdw[  N_+n]=b1; bwdw[2*N_+n]=b2; bwdw[3*N_+n]=b3;
            }
            if (tid < N_){
                float s2=0.f, d0=0.f,d1=0.f,d2=0.f,d3=0.f;
                #pragma unroll 8
                for (int w=0;w<WD_;w++){
                    float m = M_s[tid*65+w];
                    s2 += m*m;
                    float4 rk4 = *(const float4*)(rkT + w*4);
                    d0 += m*rk4.x; d1 += m*rk4.y; d2 += m*rk4.z; d3 += m*rk4.w;
                }
                float mn = sqrtf(s2);
                crs[      tid] = act[0]*(d0/(act[156]*mn + EPSF));
                crs[  N_+tid] = act[1]*(d1/(act[157]*mn + EPSF));
                crs[2*N_+tid] = act[2]*(d2/(act[158]*mn + EPSF));
                crs[3*N_+tid] = act[3]*(d3/(act[159]*mn + EPSF));
            }
            __syncthreads();
            if (tid < 128){
                int r = tid>>5, ln = tid&31;
                float v = fmaxf(fmaxf(crs[r*N_+ln],crs[r*N_+ln+32]),
                                fmaxf(crs[r*N_+ln+64],crs[r*N_+ln+96]));
                #pragma unroll
                for (int o=16;o;o>>=1) v = fmaxf(v, __shfl_xor_sync(0xffffffffu, v, o));
                if (ln==0) act[164+r]=v;
            }
            __syncthreads();
            if (tid < 128){
                int r = tid>>5, ln = tid&31;
                float m = act[164+r];
                float e0=expf(crs[r*N_+ln   ]-m);
                float e1=expf(crs[r*N_+ln+32]-m);
                float e2=expf(crs[r*N_+ln+64]-m);
                float e3=expf(crs[r*N_+ln+96]-m);
                crs[r*N_+ln]=e0; crs[r*N_+ln+32]=e1; crs[r*N_+ln+64]=e2; crs[r*N_+ln+96]=e3;
                float s = e0+e1+e2+e3;
                #pragma unroll
                for (int o=16;o;o>>=1) s += __shfl_xor_sync(0xffffffffu, s, o);
                if (ln==0) act[168+r]=s;
            }
            __syncthreads();
            for (int i=tid;i<R_*N_;i+=THR){
                int r = i>>7, n = i&127;
                float w = act[144+r*3]*bwdw[i] + act[145+r*3]*(crs[i]/act[168+r]) + act[146+r*3]*fwdw[i];
                crs[i] = w;
                crsT[n*4 + r] = w;
            }
            __syncthreads();
            if (tid < WD_){
                int w = tid;
                float s0=0.f,s1=0.f,s2v=0.f,s3=0.f;
                #pragma unroll 4
                for (int n=0;n<N_;n++){
                    float mv = M_s[n*65+w];
                    float4 c4 = *(const float4*)(crsT + n*4);
                    s0 += c4.x*mv; s1 += c4.y*mv; s2v += c4.z*mv; s3 += c4.w*mv;
                }
                size_t btrow = (size_t)b*T_ + t;
                float sv[4] = {s0,s1,s2v,s3};
                #pragma unroll
                for (int r=0;r<4;r++){
                    int idx = r*WD_ + w;
                    g_rvT[idx*B_ + b] = sv[r];
                    __nv_bfloat16 sh = __float2bfloat16(sv[r]);
                    g_Uhi[btrow*KU + H_ + idx] = sh;
                    g_Ulo[btrow*KU + H_ + idx] = __float2bfloat16(sv[r] - __bfloat162float(sh));
                }
            }
            __syncthreads();
            for (int i=tid;i<R_*N_;i+=THR) wr_s[i] = crs[i];
            if (tid < N_){ u_s[tid]=unew[tid]; ww_s[tid]=wwn[tid]; }
        } else if (bx < 96 && t+1 < T_){
            // ---- Gh precompute for step t+1: Gh = Wh @ h_t for 32 owned cols ----
            const int g  = wid >> 3;       // 0/1 col-group of 16
            const int wk = wid & 7;        // 8-way K split (64 K each)
            ull acc[8];
            #pragma unroll
            for (int c=0;c<8;c++) acc[c]=0ull;
            const float* hsrc = g_hT[wrb];
            #pragma unroll 4
            for (int k=wk*64; k<wk*64+64; k++){
                ull as = splat2f(__ldcg(hsrc + k*B_ + lane));
                const ulonglong2* wp = (const ulonglong2*)(W_B + k*32 + g*16);
                ulonglong2 w01 = wp[0], w23 = wp[1], w45 = wp[2], w67 = wp[3];
                ffma2(acc[0], as, w01.x); ffma2(acc[1], as, w01.y);
                ffma2(acc[2], as, w23.x); ffma2(acc[3], as, w23.y);
                ffma2(acc[4], as, w45.x); ffma2(acc[5], as, w45.y);
                ffma2(acc[6], as, w67.x); ffma2(acc[7], as, w67.y);
            }
            #pragma unroll
            for (int c=0;c<8;c++) scr2[g*2048 + wk*256 + c*32 + lane] = acc[c];
            __syncthreads();
            {
                int cp = tid >> 5;          // 0..15
                int g2 = cp >> 3, c2 = cp & 7;
                ull s = scr2[g2*2048 + c2*32 + lane];
                #pragma unroll
                for (int w8=1;w8<8;w8++) fadd2(s, scr2[g2*2048 + w8*256 + c2*32 + lane]);
                float2 v = unpack2(s);
                int col = (bx-32)*32 + g2*16 + 2*c2;
                *(float2*)(g_Gh + (size_t)lane*G4H + col) = v;
            }
        }
        gridbar(++ep);
    }
}

// ---------------- launcher ----------------
extern "C" void kernel_launch(void* const* d_in, const int* in_sizes, int n_in,
                              void* d_out, int out_size){
    const int*   tokens  = (const int*)  d_in[0];
    const float* emb     = (const float*)d_in[1];
    const float* w_ih    = (const float*)d_in[2];
    const float* w_hh    = (const float*)d_in[3];
    const float* b_lstm  = (const float*)d_in[4];
    const float* W_iface = (const float*)d_in[5];
    const float* b_iface = (const float*)d_in[6];
    const float* W_out   = (const float*)d_in[7];
    const float* b_out   = (const float*)d_in[8];
    float* out = (float*)d_out;

    const int loop_smem = LOOP_SMEM_FLOATS * (int)sizeof(float);
    cudaFuncSetAttribute(loop_kernel, cudaFuncAttributeMaxDynamicSharedMemorySize, loop_smem);
    const int gout_smem = 8 * TILE_BF * (int)sizeof(__nv_bfloat16);
    cudaFuncSetAttribute(gemm_out, cudaFuncAttributeMaxDynamicSharedMemorySize, gout_smem);

    void *pX, *pG0, *pWihT, *pBl;
    cudaGetSymbolAddress(&pX, g_X);
    cudaGetSymbolAddress(&pG0, g_G0);
    cudaGetSymbolAddress(&pWihT, g_WihT);
    cudaGetSymbolAddress(&pBl, g_bl);

    // order chosen so loop_kernel is the 4th launch (ncu -s 5 -c 1 captures it)
    embed_kernel<<<(BT_*E_ + 255)/256, 256>>>(tokens, emb);
    prep_w<<<(KU*G4H + 255)/256, 256>>>(w_ih, w_hh, b_lstm);
    sgemm128<<<dim3(G4H/128, BT_/128), 256>>>((const float*)pX, (const float*)pWihT,
                                              (const float*)pBl, (float*)pG0, BT_, G4H, E_);
    loop_kernel<<<NBLK, THR, loop_smem>>>(W_iface, b_iface);
    prep_outT<<<dim3(VPAD/32, KU/32), dim3(32,8)>>>(W_out);
    gemm_out<<<dim3((V_+127)/128, BT_/128), 256, gout_smem>>>(b_out, out);
}

// round 10
// speedup vs baseline: 2.7223x; 1.1134x over previous
#include <cuda_runtime.h>
#include <cuda_bf16.h>
#include <math.h>

#define B_ 32
#define T_ 256
#define V_ 10000
#define VPAD 10112
#define E_ 256
#define H_ 512
#define N_ 128
#define WD_ 64
#define R_ 4
#define IFACE_ 471
#define G4H 2048          // 4*H
#define KU 768            // H + R*WD
#define BT_ (B_*T_)       // 8192
#define EPSF 1e-6f
#define NBLK 128
#define THR 512

typedef unsigned long long ull;

// ---------------- f32x2 helpers ----------------
__device__ __forceinline__ ull pack2(float x, float y){
    ull r; asm("mov.b64 %0, {%1,%2};" : "=l"(r) : "r"(__float_as_uint(x)), "r"(__float_as_uint(y))); return r;
}
__device__ __forceinline__ ull splat2f(float x){ return pack2(x, x); }
__device__ __forceinline__ float2 unpack2(ull v){
    unsigned lo, hi;
    asm("mov.b64 {%0,%1}, %2;" : "=r"(lo), "=r"(hi) : "l"(v));
    return make_float2(__uint_as_float(lo), __uint_as_float(hi));
}
__device__ __forceinline__ void ffma2(ull& d, ull a, ull b){
    asm("fma.rn.f32x2 %0, %1, %2, %0;" : "+l"(d) : "l"(a), "l"(b));
}
__device__ __forceinline__ void fadd2(ull& d, ull a){
    asm("add.rn.f32x2 %0, %0, %1;" : "+l"(d) : "l"(a));
}
__device__ __forceinline__ void cpasync16(unsigned dst, const void* src){
    asm volatile("cp.async.cg.shared.global [%0], [%1], 16;" :: "r"(dst), "l"(src));
}

// ---------------- GPU-scope relaxed flag ops ----------------
__device__ __forceinline__ unsigned ld_rlx(const unsigned* p){
    unsigned v;
    asm volatile("ld.relaxed.gpu.global.u32 %0, [%1];" : "=r"(v) : "l"(p) : "memory");
    return v;
}
__device__ __forceinline__ void st_rlx(unsigned* p, unsigned v){
    asm volatile("st.relaxed.gpu.global.u32 [%0], %1;" :: "l"(p), "r"(v) : "memory");
}

// ---------------- device scratch ----------------
__device__ __align__(128) float g_X[BT_*E_];
__device__ __align__(128) float g_G0[(size_t)BT_*G4H];
__device__ __align__(128) float g_WihT[E_*G4H];               // permuted cols
__device__ __align__(128) float g_Wt[KU*G4H];                 // permuted cols: [rv ; h]
__device__ __align__(128) float g_bl[G4H];                    // permuted bias
__device__ __align__(128) __nv_bfloat16 g_WhiT[(size_t)VPAD*KU];
__device__ __align__(128) __nv_bfloat16 g_WloT[(size_t)VPAD*KU];
__device__ __align__(128) __nv_bfloat16 g_Uhi[(size_t)BT_*KU];
__device__ __align__(128) __nv_bfloat16 g_Ulo[(size_t)BT_*KU];
__device__ __align__(128) float g_hT[2][H_*B_];               // double-buffered [feat][batch]
__device__ __align__(128) float g_rvT[R_*WD_*B_];
__device__ __align__(128) float g_xiT[IFACE_*B_];
__device__ __align__(128) float g_Gh[B_*G4H];                 // [batch][col] h-part of next gates
__device__ __align__(128) unsigned g_flags[NBLK*32];
__device__ unsigned g_gen;

__device__ __forceinline__ float sigf(float x){ return 1.f/(1.f + expf(-x)); }
__device__ __forceinline__ float splusf(float x){ return fmaxf(x,0.f) + log1pf(expf(-fabsf(x))); }

// ---------------- all-to-all single-hop grid barrier ----------------
__device__ __forceinline__ void gridbar(unsigned ep){
    __syncthreads();
    if (threadIdx.x == 0){
        __threadfence();                       // order this block's writes to L2
        st_rlx(&g_flags[blockIdx.x*32], ep);
    }
    if (threadIdx.x < NBLK){
        while (ld_rlx(&g_flags[threadIdx.x*32]) < ep) { }
    }
    __syncthreads();
}

// ---------------- prep kernels ----------------
__global__ void embed_kernel(const int* __restrict__ tok, const float* __restrict__ emb){
    int i = blockIdx.x*256 + threadIdx.x;
    if (i >= BT_*E_) return;
    int bt = i / E_, e = i % E_;
    g_X[i] = tanhf(emb[(size_t)tok[bt]*E_ + e]);
}

// weight permute + all state zeroing
__global__ void prep_w(const float* __restrict__ w_ih, const float* __restrict__ w_hh,
                       const float* __restrict__ b_lstm){
    int i = blockIdx.x*256 + threadIdx.x;
    if (i < KU*G4H){
        int k = i >> 11, col = i & 2047;
        int jj = col >> 2, g = col & 3;
        int j = g*H_ + jj;
        g_Wt[i] = (k < R_*WD_) ? w_ih[(size_t)j*(E_+R_*WD_) + E_ + k]
                               : w_hh[(size_t)j*H_ + (k - R_*WD_)];
    }
    if (i < E_*G4H){
        int e = i >> 11, col = i & 2047;
        int jj = col >> 2, g = col & 3;
        int j = g*H_ + jj;
        g_WihT[i] = w_ih[(size_t)j*(E_+R_*WD_) + e];
    }
    if (i < G4H){
        int jj = i >> 2, g = i & 3;
        g_bl[i] = b_lstm[g*H_ + jj];
    }
    if (i < 2*H_*B_) ((float*)g_hT)[i] = 0.f;
    if (i < R_*WD_*B_) g_rvT[i] = 0.f;
    if (i < B_*G4H) g_Gh[i] = 0.f;
    if (i < NBLK*32) g_flags[i] = 0u;
    if (i == 0) g_gen = 0u;
}

// tiled transpose + bf16 hi/lo split
__global__ void prep_outT(const float* __restrict__ W_out){
    __shared__ float tile[32][33];
    int n0 = blockIdx.x*32, k0 = blockIdx.y*32;
    int tx = threadIdx.x, ty = threadIdx.y;   // 32 x 8
    #pragma unroll
    for (int dy=0;dy<32;dy+=8){
        int k = k0+ty+dy, n = n0+tx;
        tile[ty+dy][tx] = (n < V_) ? W_out[(size_t)k*V_+n] : 0.f;
    }
    __syncthreads();
    #pragma unroll
    for (int dy=0;dy<32;dy+=8){
        int n = n0+ty+dy, k = k0+tx;
        float v = tile[tx][ty+dy];
        __nv_bfloat16 h = __float2bfloat16(v);
        g_WhiT[(size_t)n*KU+k] = h;
        g_WloT[(size_t)n*KU+k] = __float2bfloat16(v - __bfloat162float(h));
    }
}

// ---------------- pipelined fp32 SGEMM (R4): C = A(MxK)@B(KxN) (+bias) ----------------
__global__ __launch_bounds__(256) void sgemm128(const float* __restrict__ A,
                         const float* __restrict__ Bm,
                         const float* __restrict__ bias, float* __restrict__ C,
                         int M, int Nn, int K){
    __shared__ float As[2][8][128];
    __shared__ float Bs[2][8][128];
    int tid = threadIdx.x;
    int row0 = blockIdx.y*128, col0 = blockIdx.x*128;
    int trow = (tid >> 4) * 8;
    int tcol = (tid & 15) * 8;
    float acc[8][8];
    #pragma unroll
    for (int i=0;i<8;i++)
        #pragma unroll
        for (int j=0;j<8;j++) acc[i][j]=0.f;

    int arow = tid >> 1, ak = (tid & 1)*4;
    int bk = tid >> 5,  bn = (tid & 31)*4;
    const float* Aptr = A + (size_t)(row0 + arow)*K + ak;
    int gn = col0 + bn;

    float4 av = *(const float4*)(Aptr);
    float4 bv = make_float4(0.f,0.f,0.f,0.f);
    if (gn < Nn) bv = *(const float4*)(Bm + (size_t)bk*Nn + gn);
    As[0][ak+0][arow]=av.x; As[0][ak+1][arow]=av.y; As[0][ak+2][arow]=av.z; As[0][ak+3][arow]=av.w;
    *(float4*)(&Bs[0][bk][bn]) = bv;
    __syncthreads();

    int buf = 0;
    for (int k0=0;k0<K;k0+=8){
        bool more = (k0 + 8) < K;
        if (more){
            av = *(const float4*)(Aptr + k0 + 8);
            bv = make_float4(0.f,0.f,0.f,0.f);
            if (gn < Nn) bv = *(const float4*)(Bm + (size_t)(k0+8+bk)*Nn + gn);
        }
        #pragma unroll
        for (int kk=0;kk<8;kk++){
            float ar[8], br[8];
            *(float4*)(ar)   = *(const float4*)(&As[buf][kk][trow]);
            *(float4*)(ar+4) = *(const float4*)(&As[buf][kk][trow+4]);
            *(float4*)(br)   = *(const float4*)(&Bs[buf][kk][tcol]);
            *(float4*)(br+4) = *(const float4*)(&Bs[buf][kk][tcol+4]);
            #pragma unroll
            for (int i=0;i<8;i++)
                #pragma unroll
                for (int j=0;j<8;j++) acc[i][j] += ar[i]*br[j];
        }
        if (more){
            int nb = buf ^ 1;
            As[nb][ak+0][arow]=av.x; As[nb][ak+1][arow]=av.y; As[nb][ak+2][arow]=av.z; As[nb][ak+3][arow]=av.w;
            *(float4*)(&Bs[nb][bk][bn]) = bv;
            __syncthreads();
            buf = nb;
        }
    }
    #pragma unroll
    for (int i=0;i<8;i++){
        size_t gm = (size_t)(row0 + trow + i);
        #pragma unroll
        for (int j=0;j<8;j+=4){
            int gnn = col0 + tcol + j;
            if (gnn < Nn){
                float4 v = make_float4(acc[i][j],acc[i][j+1],acc[i][j+2],acc[i][j+3]);
                if (bias){ v.x+=bias[gnn]; v.y+=bias[gnn+1]; v.z+=bias[gnn+2]; v.w+=bias[gnn+3]; }
                *(float4*)(C + gm*Nn + gnn) = v;
            }
        }
    }
}

// ---------------- bf16-split tensor-core GEMM: out = U@W_out + b ----------------
#define PITCH 40
#define TILE_BF (128*PITCH)

__device__ __forceinline__ void mma_bf16(float* c, unsigned a0,unsigned a1,unsigned a2,unsigned a3,
                                         unsigned b0, unsigned b1){
    asm volatile("mma.sync.aligned.m16n8k16.row.col.f32.bf16.bf16.f32 "
        "{%0,%1,%2,%3}, {%4,%5,%6,%7}, {%8,%9}, {%0,%1,%2,%3};"
        : "+f"(c[0]),"+f"(c[1]),"+f"(c[2]),"+f"(c[3])
        : "r"(a0),"r"(a1),"r"(a2),"r"(a3),"r"(b0),"r"(b1));
}

__global__ __launch_bounds__(256) void gemm_out(const float* __restrict__ bias,
                                                float* __restrict__ C){
    extern __shared__ __align__(16) char smraw[];
    __nv_bfloat16* AsHi = (__nv_bfloat16*)smraw;
    __nv_bfloat16* AsLo = AsHi + 2*TILE_BF;
    __nv_bfloat16* BsHi = AsLo + 2*TILE_BF;
    __nv_bfloat16* BsLo = BsHi + 2*TILE_BF;

    const int tid = threadIdx.x, lane = tid & 31, wid = tid >> 5;
    const int warp_m = wid >> 2, warp_n = wid & 3;
    const int gid = lane >> 2, tig = lane & 3;
    const int m0 = blockIdx.y*128, n0 = blockIdx.x*128;

    float acc[4][4][4];
    #pragma unroll
    for (int i=0;i<4;i++)
        #pragma unroll
        for (int j=0;j<4;j++)
            #pragma unroll
            for (int q=0;q<4;q++) acc[i][j][q]=0.f;

    unsigned sAhi = (unsigned)__cvta_generic_to_shared(AsHi);
    unsigned sAlo = (unsigned)__cvta_generic_to_shared(AsLo);
    unsigned sBhi = (unsigned)__cvta_generic_to_shared(BsHi);
    unsigned sBlo = (unsigned)__cvta_generic_to_shared(BsLo);

    auto loadA = [&](int s, int kt){
        #pragma unroll
        for (int it=0; it<2; it++){
            int idx = it*256 + tid;
            int row = idx>>2, seg = idx&3;
            size_t goff = (size_t)(m0+row)*KU + kt*32 + seg*8;
            unsigned doff = (unsigned)((s*TILE_BF + row*PITCH + seg*8)*2);
            cpasync16(sAhi + doff, g_Uhi + goff);
            cpasync16(sAlo + doff, g_Ulo + goff);
        }
    };
    auto loadB = [&](int s, int kt){
        #pragma unroll
        for (int it=0; it<2; it++){
            int idx = it*256 + tid;
            int row = idx>>2, seg = idx&3;
            size_t goff = (size_t)(n0+row)*KU + kt*32 + seg*8;
            unsigned doff = (unsigned)((s*TILE_BF + row*PITCH + seg*8)*2);
            cpasync16(sBhi + doff, g_WhiT + goff);
            cpasync16(sBlo + doff, g_WloT + goff);
        }
    };
    auto compute = [&](int s){
        #pragma unroll
        for (int kk=0;kk<2;kk++){
            const int kb = kk*16 + tig*2;
            unsigned bh[4][2], bl[4][2];
            #pragma unroll
            for (int j=0;j<4;j++){
                int nl = warp_n*32 + j*8 + gid;
                const __nv_bfloat16* bp  = BsHi + s*TILE_BF + nl*PITCH + kb;
                const __nv_bfloat16* bp2 = BsLo + s*TILE_BF + nl*PITCH + kb;
                bh[j][0] = *(const unsigned*)bp;   bh[j][1] = *(const unsigned*)(bp+8);
                bl[j][0] = *(const unsigned*)bp2;  bl[j][1] = *(const unsigned*)(bp2+8);
            }
            #pragma unroll
            for (int i=0;i<4;i++){
                int mr = warp_m*64 + i*16;
                const __nv_bfloat16* ap  = AsHi + s*TILE_BF + (mr+gid)*PITCH + kb;
                const __nv_bfloat16* ap2 = AsLo + s*TILE_BF + (mr+gid)*PITCH + kb;
                unsigned ah0 = *(const unsigned*)ap;
                unsigned ah1 = *(const unsigned*)(ap + 8*PITCH);
                unsigned ah2 = *(const unsigned*)(ap + 8);
                unsigned ah3 = *(const unsigned*)(ap + 8*PITCH + 8);
                unsigned al0 = *(const unsigned*)ap2;
                unsigned al1 = *(const unsigned*)(ap2 + 8*PITCH);
                unsigned al2 = *(const unsigned*)(ap2 + 8);
                unsigned al3 = *(const unsigned*)(ap2 + 8*PITCH + 8);
                #pragma unroll
                for (int j=0;j<4;j++){
                    mma_bf16(acc[i][j], ah0,ah1,ah2,ah3, bh[j][0],bh[j][1]);
                    mma_bf16(acc[i][j], ah0,ah1,ah2,ah3, bl[j][0],bl[j][1]);
                    mma_bf16(acc[i][j], al0,al1,al2,al3, bh[j][0],bh[j][1]);
                }
            }
        }
    };

    loadA(0, 0); loadB(0, 0);
    asm volatile("cp.async.commit_group;");
    asm volatile("cp.async.wait_group 0;");
    __syncthreads();

    const int KT = KU/32;   // 24
    for (int kt=0; kt<KT; kt++){
        int buf = kt & 1;
        if (kt+1 < KT){
            loadA(buf^1, kt+1);
            loadB(buf^1, kt+1);
            asm volatile("cp.async.commit_group;");
        }
        compute(buf);
        if (kt+1 < KT){
            asm volatile("cp.async.wait_group 0;");
        }
        __syncthreads();
    }

    #pragma unroll
    for (int i=0;i<4;i++){
        int gm = m0 + warp_m*64 + i*16 + gid;
        #pragma unroll
        for (int j=0;j<4;j++){
            int gn = n0 + warp_n*32 + j*8 + tig*2;
            if (gn < V_){
                float b0 = bias[gn], b1 = bias[gn+1];
                *(float2*)(C + (size_t)gm*V_ + gn) = make_float2(acc[i][j][0]+b0, acc[i][j][1]+b1);
                *(float2*)(C + (size_t)(gm+8)*V_ + gn) = make_float2(acc[i][j][2]+b0, acc[i][j][3]+b1);
            }
        }
    }
}

// ---------------- persistent sequential loop ----------------
#define LOOP_SMEM_FLOATS (4096 + 2048 + 8192 + 28808)

__global__ __launch_bounds__(THR) void loop_kernel(const float* __restrict__ W_iface,
                                                   const float* __restrict__ b_iface){
    extern __shared__ float sm[];
    float* W_A  = sm;                  // 256*16 (rv-part LSTM weights)
    float* W_C  = W_A + 4096;          // 512*4 (iface cols)
    float* scr  = W_C + 2048;          // 8192
    float* M_s  = scr + 8192;          // 128*65  (helpers: W_B overlay)
    float* L_s  = M_s + 8320;          // 128*129
    float* wr_s = L_s + 16512;         // 512
    float* u_s  = wr_s + 512;          // 128
    float* p_s  = u_s + 128;           // 128
    float* ww_s = p_s + 128;           // 128
    float* xi   = ww_s + 128;          // 472
    float* fwdw = xi + 472;            // 512
    float* bwdw = fwdw + 512;          // 512
    float* crs  = bwdw + 512;          // 512
    float* unew = crs + 512;           // 128
    float* srt  = unew + 128;          // 128
    float* incl = srt + 128;           // 128
    float* a_s  = incl + 128;          // 128
    float* wwn  = a_s + 128;           // 128
    float* red  = wwn + 128;           // 128
    float* act  = red + 128;           // 176
    int* rank_s = (int*)(act + 176);   // 128
    // scr carve-outs for phase D
    float* wrT  = scr;                 // [0,512)
    float* crsT = scr + 512;           // [512,1024)
    float* rkT  = scr + 1024;          // [1024,1280)
    float* P    = scr + 2048;          // [2048,6144) split-K partials
    int*  sortP = (int*)(scr + 6144);  // [6144,6656)
    float* W_B  = M_s;                 // helpers: 512*32 h-part weights

    const int tid  = threadIdx.x;
    const int bx   = blockIdx.x;
    const int wid  = tid >> 5;
    const int lane = tid & 31;
    const int b    = bx;

    for (int i=tid;i<256*16;i+=THR){
        int k = i >> 4, c = i & 15;
        W_A[i] = g_Wt[(size_t)k*G4H + bx*16 + c];
    }
    for (int i=tid;i<512*4;i+=THR){
        int k = i >> 2, c = i & 3;
        int col = bx*4 + c;
        W_C[i] = (col < IFACE_) ? W_iface[(size_t)k*IFACE_ + col] : 0.f;
    }
    if (bx < B_){
        for (int i=tid;i<128*65;i+=THR)  M_s[i]=0.f;
        for (int i=tid;i<128*129;i+=THR) L_s[i]=0.f;
        for (int i=tid;i<512;i+=THR)     wr_s[i]=0.f;
        if (tid < N_){ u_s[tid]=0.f; p_s[tid]=0.f; ww_s[tid]=0.f; }
    } else if (bx < 96){
        for (int i=tid;i<512*32;i+=THR){
            int k = i >> 5, c = i & 31;
            W_B[i] = g_Wt[(size_t)(256+k)*G4H + (bx-32)*32 + c];
        }
    }
    __syncthreads();

    float c_reg = 0.f;
    unsigned ep = 0;
    ull* scr2 = (ull*)scr;

    for (int t=0;t<T_;t++){
        const int rd = t & 1, wrb = rd ^ 1;

        // ============ Phase A: gates = G0 + Gh + Wrv@rv ; LSTM elementwise ============
        {
            const int kbeg = wid*16;
            ull acc2[8];
            #pragma unroll
            for (int c=0;c<8;c++) acc2[c]=0ull;
            #pragma unroll
            for (int k=kbeg;k<kbeg+16;k++){
                ull as = splat2f(__ldcg(g_rvT + k*B_ + lane));
                const ulonglong2* wp = (const ulonglong2*)(W_A + k*16);
                ulonglong2 w01 = wp[0], w23 = wp[1], w45 = wp[2], w67 = wp[3];
                ffma2(acc2[0], as, w01.x); ffma2(acc2[1], as, w01.y);
                ffma2(acc2[2], as, w23.x); ffma2(acc2[3], as, w23.y);
                ffma2(acc2[4], as, w45.x); ffma2(acc2[5], as, w45.y);
                ffma2(acc2[6], as, w67.x); ffma2(acc2[7], as, w67.y);
            }
            #pragma unroll
            for (int c=0;c<8;c++) scr2[wid*256 + c*32 + lane] = acc2[c];
        }
        __syncthreads();
        if (tid < 128){
            int uu = tid >> 5;
            float4 s = *(const float4*)(g_G0 + ((size_t)lane*T_ + t)*G4H + bx*16 + uu*4);
            float4 gh = __ldcg((const float4*)(g_Gh + (size_t)lane*G4H + bx*16 + uu*4));
            s.x += gh.x; s.y += gh.y; s.z += gh.z; s.w += gh.w;
            ull s01 = pack2(s.x, s.y), s23 = pack2(s.z, s.w);
            #pragma unroll
            for (int w16=0;w16<16;w16++){
                fadd2(s01, scr2[w16*256 + (2*uu  )*32 + lane]);
                fadd2(s23, scr2[w16*256 + (2*uu+1)*32 + lane]);
            }
            float2 g01 = unpack2(s01), g23 = unpack2(s23);
            float c = sigf(g01.y)*c_reg + sigf(g01.x)*tanhf(g23.x);
            float h = sigf(g23.y)*tanhf(c);
            c_reg = c;
            int jj = bx*4 + uu;
            g_hT[wrb][jj*B_ + lane] = h;
            size_t btrow = (size_t)lane*T_ + t;
            __nv_bfloat16 hh = __float2bfloat16(h);
            g_Uhi[btrow*KU + jj] = hh;
            g_Ulo[btrow*KU + jj] = __float2bfloat16(h - __bfloat162float(hh));
        }
        gridbar(++ep);

        // ============ Phase C: iface gemm (split-K over 16 warps) ============
        if (bx < 118){
            const int kbeg = wid*32;
            float a0=0.f,a1=0.f,a2=0.f,a3=0.f;
            const float* hsrc = g_hT[wrb];
            #pragma unroll 4
            for (int k=kbeg;k<kbeg+32;k++){
                float a = __ldcg(hsrc + k*B_ + lane);
                float4 wv = *(const float4*)(W_C + k*4);
                a0 += a*wv.x; a1 += a*wv.y; a2 += a*wv.z; a3 += a*wv.w;
            }
            scr[wid*128 +       lane] = a0;
            scr[wid*128 +  32 + lane] = a1;
            scr[wid*128 +  64 + lane] = a2;
            scr[wid*128 +  96 + lane] = a3;
            __syncthreads();
            if (tid < 128){
                int c = tid >> 5, col = bx*4 + c;
                if (col < IFACE_){
                    float s = b_iface[col];
                    #pragma unroll
                    for (int w16=0;w16<16;w16++) s += scr[w16*128 + c*32 + lane];
                    g_xiT[col*B_ + lane] = s;
                }
            }
        }
        gridbar(++ep);

        // ============ Phase D (blocks 0..31) || Gh precompute (blocks 32..95) ============
        if (bx < B_){
            int rk = 0;
            const int dn = tid & 127, dp = tid >> 7;   // split-K identity: n, part
            for (int i=tid;i<IFACE_;i+=THR) xi[i] = __ldcg(g_xiT + i*B_ + b);
            wrT[tid] = wr_s[((tid&3)<<7) | (tid>>2)];
            __syncthreads();

            if (tid < 64){
                act[8+tid]  = sigf(xi[325+tid]);
                act[72+tid] = xi[389+tid];
            } else if (tid < 68){
                act[tid-64] = 1.f + splusf(xi[256 + (tid-64)]);
            } else if (tid == 68){
                act[4] = 1.f + splusf(xi[324]);
            } else if (tid < 73){
                act[136 + (tid-69)] = sigf(xi[453 + (tid-69)]);
            } else if (tid == 73){
                act[140] = sigf(xi[457]);
            } else if (tid == 74){
                act[141] = sigf(xi[458]);
            } else if (tid < 79){
                int r = tid - 75;
                float q0=xi[459+r*3], q1=xi[459+r*3+1], q2=xi[459+r*3+2];
                float m = fmaxf(q0, fmaxf(q1,q2));
                float e0=expf(q0-m), e1=expf(q1-m), e2=expf(q2-m);
                float s = e0+e1+e2;
                act[144+r*3]=e0/s; act[145+r*3]=e1/s; act[146+r*3]=e2/s;
            } else if (tid < 83){
                int r = tid - 79; float s = 0.f;
                #pragma unroll 8
                for (int w=0;w<WD_;w++){ float v = xi[r*WD_+w]; s += v*v; }
                act[156+r] = sqrtf(s);
            } else if (tid == 83){
                float s = 0.f;
                #pragma unroll 8
                for (int w=0;w<WD_;w++){ float v = xi[260+w]; s += v*v; }
                act[160] = sqrtf(s);
            } else if (tid >= 256 && tid < 512){
                int idx = tid - 256;
                rkT[idx] = xi[((idx&3)<<6) | (idx>>2)];
            }
            __syncthreads();

            if (tid < N_){
                float psi = 1.f;
                #pragma unroll
                for (int r=0;r<R_;r++) psi *= (1.f - act[136+r]*wr_s[r*N_+tid]);
                float uo=u_s[tid], wo=ww_s[tid];
                unew[tid] = (uo + wo - uo*wo)*psi;
            }
            __syncthreads();

            // ---- sort ranks: split 128 comparisons over 4 parts ----
            {
                float ui = unew[dn];
                int prk = 0;
                const int j0 = dp*32;
                #pragma unroll 8
                for (int jj=0;jj<32;jj++){
                    int j = j0 + jj;
                    float uj = unew[j];
                    prk += (uj < ui) || (uj == ui && j < dn);
                }
                sortP[dp*128 + dn] = prk;
            }
            __syncthreads();
            if (tid < N_){
                rk = sortP[tid] + sortP[128+tid] + sortP[256+tid] + sortP[384+tid];
                rank_s[tid] = rk;
                srt[rk] = unew[tid];
            }
            __syncthreads();

            // ---- parallel cumprod (inclusive) ----
            float cp_p = 1.f;
            if (tid < N_){
                int w4 = tid >> 5, ln = tid & 31;
                cp_p = srt[tid];
                #pragma unroll
                for (int off=1;off<32;off<<=1){
                    float o = __shfl_up_sync(0xffffffffu, cp_p, off);
                    if (ln >= off) cp_p *= o;
                }
                if (ln == 31) red[w4] = cp_p;
            }
            __syncthreads();
            if (tid < N_){
                int w4 = tid >> 5;
                float pre = 1.f;
                #pragma unroll
                for (int j=0;j<3;j++) if (j < w4) pre *= red[j];
                incl[tid] = cp_p * pre;
            }
            // ---- write content score partials (old M), concurrent w/ cumprod tail ----
            {
                float s2=0.f, dot=0.f;
                const int w0 = dp*16;
                #pragma unroll
                for (int w=w0;w<w0+16;w++){
                    float m = M_s[dn*65+w];
                    s2 += m*m; dot += m*xi[260+w];
                }
                P[dp*128 + dn] = dot;
                P[512 + dp*128 + dn] = s2;
            }
            __syncthreads();

            float score_w = 0.f, ew = 0.f;
            if (tid < N_){
                float ce = (rk == 0) ? 1.f : incl[rk-1];
                a_s[tid] = (1.f - unew[tid]) * ce;
                float dot = P[tid] + P[128+tid] + P[256+tid] + P[384+tid];
                float s2  = P[512+tid] + P[640+tid] + P[768+tid] + P[896+tid];
                score_w = act[4] * (dot / (act[160]*sqrtf(s2) + EPSF));
                float v = score_w;
                #pragma unroll
                for (int o=16;o;o>>=1) v = fmaxf(v, __shfl_xor_sync(0xffffffffu, v, o));
                if ((tid&31)==0) red[tid>>5] = v;
            }
            __syncthreads();
            float mxw = fmaxf(fmaxf(red[0],red[1]), fmaxf(red[2],red[3]));
            if (tid < N_){
                ew = expf(score_w - mxw);
                float s = ew;
                #pragma unroll
                for (int o=16;o;o>>=1) s += __shfl_xor_sync(0xffffffffu, s, o);
                if ((tid&31)==0) red[4 + (tid>>5)] = s;
            }
            __syncthreads();
            float sden = red[4]+red[5]+red[6]+red[7];
            if (tid < N_){
                float wv = act[141]*(act[140]*a_s[tid] + (1.f-act[140])*(ew/sden));
                wwn[tid] = wv;
                float s = wv;
                #pragma unroll
                for (int o=16;o;o>>=1) s += __shfl_xor_sync(0xffffffffu, s, o);
                if ((tid&31)==0) red[8 + (tid>>5)] = s;
            }
            __syncthreads();
            float sumww = red[8]+red[9]+red[10]+red[11];

            for (int i=tid;i<N_*WD_;i+=THR){
                int n=i>>6, w=i&63;
                float wwv = wwn[n];
                M_s[n*65+w] = M_s[n*65+w]*(1.f - wwv*act[8+w]) + wwv*act[72+w];
            }
            for (int i=tid;i<N_*N_;i+=THR){
                int n=i>>7, m=i&127;
                float v = (n==m) ? 0.f
                         : (1.f - wwn[n] - wwn[m])*L_s[n*129+m] + wwn[n]*p_s[m];
                L_s[n*129+m] = v;
            }
            __syncthreads();
            if (tid < N_) p_s[tid] = (1.f - sumww)*p_s[tid] + wwn[tid];

            // ---- fwd/bwd partials: 4 parts x 32 m each ----
            {
                float f0=0.f,f1=0.f,f2=0.f,f3=0.f, b0=0.f,b1=0.f,b2=0.f,b3=0.f;
                const int m0 = dp*32;
                #pragma unroll 4
                for (int m=m0;m<m0+32;m++){
                    float lr = L_s[dn*129+m];
                    float lc = L_s[m*129+dn];
                    float4 w4 = *(const float4*)(wrT + m*4);
                    f0 += lr*w4.x; f1 += lr*w4.y; f2 += lr*w4.z; f3 += lr*w4.w;
                    b0 += lc*w4.x; b1 += lc*w4.y; b2 += lc*w4.z; b3 += lc*w4.w;
                }
                float* fb = P + dp*1024;
                fb[      dn]=f0; fb[128+dn]=f1; fb[256+dn]=f2; fb[384+dn]=f3;
                fb[512+dn]=b0; fb[640+dn]=b1; fb[768+dn]=b2; fb[896+dn]=b3;
            }
            __syncthreads();
            {
                // combine: tid -> (n=dn, q=dp): fwdw[q*128+n], bwdw[q*128+n]
                float fs = P[0*1024 + dp*128 + dn] + P[1*1024 + dp*128 + dn]
                         + P[2*1024 + dp*128 + dn] + P[3*1024 + dp*128 + dn];
                float bs = P[0*1024 + 512 + dp*128 + dn] + P[1*1024 + 512 + dp*128 + dn]
                         + P[2*1024 + 512 + dp*128 + dn] + P[3*1024 + 512 + dp*128 + dn];
                fwdw[dp*128 + dn] = fs;
                bwdw[dp*128 + dn] = bs;
            }
            __syncthreads();

            // ---- read content partials (new M): 4 parts x 16 w ----
            {
                float s2=0.f, d0=0.f,d1=0.f,d2=0.f,d3=0.f;
                const int w0 = dp*16;
                #pragma unroll
                for (int w=w0;w<w0+16;w++){
                    float m = M_s[dn*65+w];
                    s2 += m*m;
                    float4 rk4 = *(const float4*)(rkT + w*4);
                    d0 += m*rk4.x; d1 += m*rk4.y; d2 += m*rk4.z; d3 += m*rk4.w;
                }
                float* rc = P + dp*640;
                rc[      dn]=d0; rc[128+dn]=d1; rc[256+dn]=d2; rc[384+dn]=d3;
                rc[512+dn]=s2;
            }
            __syncthreads();
            {
                // combine: thread (n=dn, r=dp)
                float d = P[0*640 + dp*128 + dn] + P[1*640 + dp*128 + dn]
                        + P[2*640 + dp*128 + dn] + P[3*640 + dp*128 + dn];
                float s2 = P[0*640 + 512 + dn] + P[1*640 + 512 + dn]
                         + P[2*640 + 512 + dn] + P[3*640 + 512 + dn];
                float mn = sqrtf(s2);
                crs[dp*128 + dn] = act[dp]*(d/(act[156+dp]*mn + EPSF));
            }
            __syncthreads();
            if (tid < 128){
                int r = tid>>5, ln = tid&31;
                float v = fmaxf(fmaxf(crs[r*N_+ln],crs[r*N_+ln+32]),
                                fmaxf(crs[r*N_+ln+64],crs[r*N_+ln+96]));
                #pragma unroll
                for (int o=16;o;o>>=1) v = fmaxf(v, __shfl_xor_sync(0xffffffffu, v, o));
                if (ln==0) act[164+r]=v;
            }
            __syncthreads();
            if (tid < 128){
                int r = tid>>5, ln = tid&31;
                float m = act[164+r];
                float e0=expf(crs[r*N_+ln   ]-m);
                float e1=expf(crs[r*N_+ln+32]-m);
                float e2=expf(crs[r*N_+ln+64]-m);
                float e3=expf(crs[r*N_+ln+96]-m);
                crs[r*N_+ln]=e0; crs[r*N_+ln+32]=e1; crs[r*N_+ln+64]=e2; crs[r*N_+ln+96]=e3;
                float s = e0+e1+e2+e3;
                #pragma unroll
                for (int o=16;o;o>>=1) s += __shfl_xor_sync(0xffffffffu, s, o);
                if (ln==0) act[168+r]=s;
            }
            __syncthreads();
            {
                // new read weights over 512 threads: (r=dp, n=dn)
                int i = dp*128 + dn;
                float w = act[144+dp*3]*bwdw[i] + act[145+dp*3]*(crs[i]/act[168+dp]) + act[146+dp*3]*fwdw[i];
                crs[i] = w;
                crsT[dn*4 + dp] = w;
            }
            __syncthreads();
            // ---- rv partials: 8 parts x 16 n each ----
            {
                int w = tid & 63, part = tid >> 6;   // 0..7
                float s0=0.f,s1=0.f,s2v=0.f,s3=0.f;
                const int n0 = part*16;
                #pragma unroll
                for (int n=n0;n<n0+16;n++){
                    float mv = M_s[n*65+w];
                    float4 c4 = *(const float4*)(crsT + n*4);
                    s0 += c4.x*mv; s1 += c4.y*mv; s2v += c4.z*mv; s3 += c4.w*mv;
                }
                float* rv = P + part*256;
                rv[      w]=s0; rv[ 64+w]=s1; rv[128+w]=s2v; rv[192+w]=s3;
            }
            __syncthreads();
            if (tid < 256){
                int r = tid >> 6, w = tid & 63;
                float s = 0.f;
                #pragma unroll
                for (int part=0;part<8;part++) s += P[part*256 + r*64 + w];
                int idx = r*WD_ + w;
                g_rvT[idx*B_ + b] = s;
                size_t btrow = (size_t)b*T_ + t;
                __nv_bfloat16 sh = __float2bfloat16(s);
                g_Uhi[btrow*KU + H_ + idx] = sh;
                g_Ulo[btrow*KU + H_ + idx] = __float2bfloat16(s - __bfloat162float(sh));
            }
            __syncthreads();
            {
                wr_s[tid] = crs[tid];
            }
            if (tid < N_){ u_s[tid]=unew[tid]; ww_s[tid]=wwn[tid]; }
        } else if (bx < 96 && t+1 < T_){
            // ---- Gh precompute for step t+1 ----
            const int g  = wid >> 3;
            const int wk = wid & 7;
            ull acc[8];
            #pragma unroll
            for (int c=0;c<8;c++) acc[c]=0ull;
            const float* hsrc = g_hT[wrb];
            #pragma unroll 4
            for (int k=wk*64; k<wk*64+64; k++){
                ull as = splat2f(__ldcg(hsrc + k*B_ + lane));
                const ulonglong2* wp = (const ulonglong2*)(W_B + k*32 + g*16);
                ulonglong2 w01 = wp[0], w23 = wp[1], w45 = wp[2], w67 = wp[3];
                ffma2(acc[0], as, w01.x); ffma2(acc[1], as, w01.y);
                ffma2(acc[2], as, w23.x); ffma2(acc[3], as, w23.y);
                ffma2(acc[4], as, w45.x); ffma2(acc[5], as, w45.y);
                ffma2(acc[6], as, w67.x); ffma2(acc[7], as, w67.y);
            }
            #pragma unroll
            for (int c=0;c<8;c++) scr2[g*2048 + wk*256 + c*32 + lane] = acc[c];
            __syncthreads();
            {
                int cp = tid >> 5;
                int g2 = cp >> 3, c2 = cp & 7;
                ull s = scr2[g2*2048 + c2*32 + lane];
                #pragma unroll
                for (int w8=1;w8<8;w8++) fadd2(s, scr2[g2*2048 + w8*256 + c2*32 + lane]);
                float2 v = unpack2(s);
                int col = (bx-32)*32 + g2*16 + 2*c2;
                *(float2*)(g_Gh + (size_t)lane*G4H + col) = v;
            }
        }
        gridbar(++ep);
    }
}

// ---------------- launcher ----------------
extern "C" void kernel_launch(void* const* d_in, const int* in_sizes, int n_in,
                              void* d_out, int out_size){
    const int*   tokens  = (const int*)  d_in[0];
    const float* emb     = (const float*)d_in[1];
    const float* w_ih    = (const float*)d_in[2];
    const float* w_hh    = (const float*)d_in[3];
    const float* b_lstm  = (const float*)d_in[4];
    const float* W_iface = (const float*)d_in[5];
    const float* b_iface = (const float*)d_in[6];
    const float* W_out   = (const float*)d_in[7];
    const float* b_out   = (const float*)d_in[8];
    float* out = (float*)d_out;

    const int loop_smem = LOOP_SMEM_FLOATS * (int)sizeof(float);
    cudaFuncSetAttribute(loop_kernel, cudaFuncAttributeMaxDynamicSharedMemorySize, loop_smem);
    const int gout_smem = 8 * TILE_BF * (int)sizeof(__nv_bfloat16);
    cudaFuncSetAttribute(gemm_out, cudaFuncAttributeMaxDynamicSharedMemorySize, gout_smem);

    void *pX, *pG0, *pWihT, *pBl;
    cudaGetSymbolAddress(&pX, g_X);
    cudaGetSymbolAddress(&pG0, g_G0);
    cudaGetSymbolAddress(&pWihT, g_WihT);
    cudaGetSymbolAddress(&pBl, g_bl);

    embed_kernel<<<(BT_*E_ + 255)/256, 256>>>(tokens, emb);
    prep_w<<<(KU*G4H + 255)/256, 256>>>(w_ih, w_hh, b_lstm);
    sgemm128<<<dim3(G4H/128, BT_/128), 256>>>((const float*)pX, (const float*)pWihT,
                                              (const float*)pBl, (float*)pG0, BT_, G4H, E_);
    loop_kernel<<<NBLK, THR, loop_smem>>>(W_iface, b_iface);
    prep_outT<<<dim3(VPAD/32, KU/32), dim3(32,8)>>>(W_out);
    gemm_out<<<dim3((V_+127)/128, BT_/128), 256, gout_smem>>>(b_out, out);
}

// round 11
// speedup vs baseline: 2.7438x; 1.0079x over previous
#include <cuda_runtime.h>
#include <cuda_bf16.h>
#include <math.h>

#define B_ 32
#define T_ 256
#define V_ 10000
#define VPAD 10112
#define E_ 256
#define H_ 512
#define N_ 128
#define WD_ 64
#define R_ 4
#define IFACE_ 471
#define G4H 2048          // 4*H
#define KU 768            // H + R*WD
#define BT_ (B_*T_)       // 8192
#define EPSF 1e-6f
#define NBLK 128
#define THR 512

typedef unsigned long long ull;

// ---------------- f32x2 helpers ----------------
__device__ __forceinline__ ull pack2(float x, float y){
    ull r; asm("mov.b64 %0, {%1,%2};" : "=l"(r) : "r"(__float_as_uint(x)), "r"(__float_as_uint(y))); return r;
}
__device__ __forceinline__ ull splat2f(float x){ return pack2(x, x); }
__device__ __forceinline__ float2 unpack2(ull v){
    unsigned lo, hi;
    asm("mov.b64 {%0,%1}, %2;" : "=r"(lo), "=r"(hi) : "l"(v));
    return make_float2(__uint_as_float(lo), __uint_as_float(hi));
}
__device__ __forceinline__ void ffma2(ull& d, ull a, ull b){
    asm("fma.rn.f32x2 %0, %1, %2, %0;" : "+l"(d) : "l"(a), "l"(b));
}
__device__ __forceinline__ void fadd2(ull& d, ull a){
    asm("add.rn.f32x2 %0, %0, %1;" : "+l"(d) : "l"(a));
}
__device__ __forceinline__ void cpasync16(unsigned dst, const void* src){
    asm volatile("cp.async.cg.shared.global [%0], [%1], 16;" :: "r"(dst), "l"(src));
}

// ---------------- GPU-scope relaxed flag ops ----------------
__device__ __forceinline__ unsigned ld_rlx(const unsigned* p){
    unsigned v;
    asm volatile("ld.relaxed.gpu.global.u32 %0, [%1];" : "=r"(v) : "l"(p) : "memory");
    return v;
}
__device__ __forceinline__ void st_rlx(unsigned* p, unsigned v){
    asm volatile("st.relaxed.gpu.global.u32 [%0], %1;" :: "l"(p), "r"(v) : "memory");
}

// ---------------- device scratch ----------------
__device__ __align__(128) float g_X[BT_*E_];
__device__ __align__(128) float g_G0[(size_t)BT_*G4H];
__device__ __align__(128) float g_WihT[E_*G4H];               // permuted cols
__device__ __align__(128) float g_Wt[KU*G4H];                 // permuted cols: [rv ; h]
__device__ __align__(128) float g_bl[G4H];                    // permuted bias
__device__ __align__(128) __nv_bfloat16 g_WhiT[(size_t)VPAD*KU];
__device__ __align__(128) __nv_bfloat16 g_WloT[(size_t)VPAD*KU];
__device__ __align__(128) __nv_bfloat16 g_Uhi[(size_t)BT_*KU];
__device__ __align__(128) __nv_bfloat16 g_Ulo[(size_t)BT_*KU];
__device__ __align__(128) float g_hT[2][H_*B_];               // double-buffered [feat][batch]
__device__ __align__(128) float g_rvT[R_*WD_*B_];
__device__ __align__(128) float g_xiT[IFACE_*B_];
__device__ __align__(128) float g_Gh[B_*G4H];                 // [batch][col] h-part of next gates
__device__ __align__(128) unsigned g_flags[NBLK*32];
__device__ __align__(128) unsigned g_cflags[64*32];           // iface-done flags
__device__ unsigned g_gen;

__device__ __forceinline__ float sigf(float x){ return 1.f/(1.f + expf(-x)); }
__device__ __forceinline__ float splusf(float x){ return fmaxf(x,0.f) + log1pf(expf(-fabsf(x))); }

// ---------------- all-to-all single-hop grid barrier ----------------
__device__ __forceinline__ void gridbar(unsigned ep){
    __syncthreads();
    if (threadIdx.x == 0){
        __threadfence();                       // order this block's writes to L2
        st_rlx(&g_flags[blockIdx.x*32], ep);
    }
    if (threadIdx.x < NBLK){
        while (ld_rlx(&g_flags[threadIdx.x*32]) < ep) { }
    }
    __syncthreads();
}

// ---------------- prep kernels ----------------
__global__ void embed_kernel(const int* __restrict__ tok, const float* __restrict__ emb){
    int i = blockIdx.x*256 + threadIdx.x;
    if (i >= BT_*E_) return;
    int bt = i / E_, e = i % E_;
    g_X[i] = tanhf(emb[(size_t)tok[bt]*E_ + e]);
}

// weight permute + all state zeroing
__global__ void prep_w(const float* __restrict__ w_ih, const float* __restrict__ w_hh,
                       const float* __restrict__ b_lstm){
    int i = blockIdx.x*256 + threadIdx.x;
    if (i < KU*G4H){
        int k = i >> 11, col = i & 2047;
        int jj = col >> 2, g = col & 3;
        int j = g*H_ + jj;
        g_Wt[i] = (k < R_*WD_) ? w_ih[(size_t)j*(E_+R_*WD_) + E_ + k]
                               : w_hh[(size_t)j*H_ + (k - R_*WD_)];
    }
    if (i < E_*G4H){
        int e = i >> 11, col = i & 2047;
        int jj = col >> 2, g = col & 3;
        int j = g*H_ + jj;
        g_WihT[i] = w_ih[(size_t)j*(E_+R_*WD_) + e];
    }
    if (i < G4H){
        int jj = i >> 2, g = i & 3;
        g_bl[i] = b_lstm[g*H_ + jj];
    }
    if (i < 2*H_*B_) ((float*)g_hT)[i] = 0.f;
    if (i < R_*WD_*B_) g_rvT[i] = 0.f;
    if (i < B_*G4H) g_Gh[i] = 0.f;
    if (i < NBLK*32) g_flags[i] = 0u;
    if (i < 64*32) g_cflags[i] = 0u;
    if (i == 0) g_gen = 0u;
}

// tiled transpose + bf16 hi/lo split
__global__ void prep_outT(const float* __restrict__ W_out){
    __shared__ float tile[32][33];
    int n0 = blockIdx.x*32, k0 = blockIdx.y*32;
    int tx = threadIdx.x, ty = threadIdx.y;   // 32 x 8
    #pragma unroll
    for (int dy=0;dy<32;dy+=8){
        int k = k0+ty+dy, n = n0+tx;
        tile[ty+dy][tx] = (n < V_) ? W_out[(size_t)k*V_+n] : 0.f;
    }
    __syncthreads();
    #pragma unroll
    for (int dy=0;dy<32;dy+=8){
        int n = n0+ty+dy, k = k0+tx;
        float v = tile[tx][ty+dy];
        __nv_bfloat16 h = __float2bfloat16(v);
        g_WhiT[(size_t)n*KU+k] = h;
        g_WloT[(size_t)n*KU+k] = __float2bfloat16(v - __bfloat162float(h));
    }
}

// ---------------- pipelined fp32 SGEMM (R4): C = A(MxK)@B(KxN) (+bias) ----------------
__global__ __launch_bounds__(256) void sgemm128(const float* __restrict__ A,
                         const float* __restrict__ Bm,
                         const float* __restrict__ bias, float* __restrict__ C,
                         int M, int Nn, int K){
    __shared__ float As[2][8][128];
    __shared__ float Bs[2][8][128];
    int tid = threadIdx.x;
    int row0 = blockIdx.y*128, col0 = blockIdx.x*128;
    int trow = (tid >> 4) * 8;
    int tcol = (tid & 15) * 8;
    float acc[8][8];
    #pragma unroll
    for (int i=0;i<8;i++)
        #pragma unroll
        for (int j=0;j<8;j++) acc[i][j]=0.f;

    int arow = tid >> 1, ak = (tid & 1)*4;
    int bk = tid >> 5,  bn = (tid & 31)*4;
    const float* Aptr = A + (size_t)(row0 + arow)*K + ak;
    int gn = col0 + bn;

    float4 av = *(const float4*)(Aptr);
    float4 bv = make_float4(0.f,0.f,0.f,0.f);
    if (gn < Nn) bv = *(const float4*)(Bm + (size_t)bk*Nn + gn);
    As[0][ak+0][arow]=av.x; As[0][ak+1][arow]=av.y; As[0][ak+2][arow]=av.z; As[0][ak+3][arow]=av.w;
    *(float4*)(&Bs[0][bk][bn]) = bv;
    __syncthreads();

    int buf = 0;
    for (int k0=0;k0<K;k0+=8){
        bool more = (k0 + 8) < K;
        if (more){
            av = *(const float4*)(Aptr + k0 + 8);
            bv = make_float4(0.f,0.f,0.f,0.f);
            if (gn < Nn) bv = *(const float4*)(Bm + (size_t)(k0+8+bk)*Nn + gn);
        }
        #pragma unroll
        for (int kk=0;kk<8;kk++){
            float ar[8], br[8];
            *(float4*)(ar)   = *(const float4*)(&As[buf][kk][trow]);
            *(float4*)(ar+4) = *(const float4*)(&As[buf][kk][trow+4]);
            *(float4*)(br)   = *(const float4*)(&Bs[buf][kk][tcol]);
            *(float4*)(br+4) = *(const float4*)(&Bs[buf][kk][tcol+4]);
            #pragma unroll
            for (int i=0;i<8;i++)
                #pragma unroll
                for (int j=0;j<8;j++) acc[i][j] += ar[i]*br[j];
        }
        if (more){
            int nb = buf ^ 1;
            As[nb][ak+0][arow]=av.x; As[nb][ak+1][arow]=av.y; As[nb][ak+2][arow]=av.z; As[nb][ak+3][arow]=av.w;
            *(float4*)(&Bs[nb][bk][bn]) = bv;
            __syncthreads();
            buf = nb;
        }
    }
    #pragma unroll
    for (int i=0;i<8;i++){
        size_t gm = (size_t)(row0 + trow + i);
        #pragma unroll
        for (int j=0;j<8;j+=4){
            int gnn = col0 + tcol + j;
            if (gnn < Nn){
                float4 v = make_float4(acc[i][j],acc[i][j+1],acc[i][j+2],acc[i][j+3]);
                if (bias){ v.x+=bias[gnn]; v.y+=bias[gnn+1]; v.z+=bias[gnn+2]; v.w+=bias[gnn+3]; }
                *(float4*)(C + gm*Nn + gnn) = v;
            }
        }
    }
}

// ---------------- bf16-split tensor-core GEMM: out = U@W_out + b ----------------
#define PITCH 40
#define TILE_BF (128*PITCH)

__device__ __forceinline__ void mma_bf16(float* c, unsigned a0,unsigned a1,unsigned a2,unsigned a3,
                                         unsigned b0, unsigned b1){
    asm volatile("mma.sync.aligned.m16n8k16.row.col.f32.bf16.bf16.f32 "
        "{%0,%1,%2,%3}, {%4,%5,%6,%7}, {%8,%9}, {%0,%1,%2,%3};"
        : "+f"(c[0]),"+f"(c[1]),"+f"(c[2]),"+f"(c[3])
        : "r"(a0),"r"(a1),"r"(a2),"r"(a3),"r"(b0),"r"(b1));
}

__global__ __launch_bounds__(256) void gemm_out(const float* __restrict__ bias,
                                                float* __restrict__ C){
    extern __shared__ __align__(16) char smraw[];
    __nv_bfloat16* AsHi = (__nv_bfloat16*)smraw;
    __nv_bfloat16* AsLo = AsHi + 2*TILE_BF;
    __nv_bfloat16* BsHi = AsLo + 2*TILE_BF;
    __nv_bfloat16* BsLo = BsHi + 2*TILE_BF;

    const int tid = threadIdx.x, lane = tid & 31, wid = tid >> 5;
    const int warp_m = wid >> 2, warp_n = wid & 3;
    const int gid = lane >> 2, tig = lane & 3;
    const int m0 = blockIdx.y*128, n0 = blockIdx.x*128;

    float acc[4][4][4];
    #pragma unroll
    for (int i=0;i<4;i++)
        #pragma unroll
        for (int j=0;j<4;j++)
            #pragma unroll
            for (int q=0;q<4;q++) acc[i][j][q]=0.f;

    unsigned sAhi = (unsigned)__cvta_generic_to_shared(AsHi);
    unsigned sAlo = (unsigned)__cvta_generic_to_shared(AsLo);
    unsigned sBhi = (unsigned)__cvta_generic_to_shared(BsHi);
    unsigned sBlo = (unsigned)__cvta_generic_to_shared(BsLo);

    auto loadA = [&](int s, int kt){
        #pragma unroll
        for (int it=0; it<2; it++){
            int idx = it*256 + tid;
            int row = idx>>2, seg = idx&3;
            size_t goff = (size_t)(m0+row)*KU + kt*32 + seg*8;
            unsigned doff = (unsigned)((s*TILE_BF + row*PITCH + seg*8)*2);
            cpasync16(sAhi + doff, g_Uhi + goff);
            cpasync16(sAlo + doff, g_Ulo + goff);
        }
    };
    auto loadB = [&](int s, int kt){
        #pragma unroll
        for (int it=0; it<2; it++){
            int idx = it*256 + tid;
            int row = idx>>2, seg = idx&3;
            size_t goff = (size_t)(n0+row)*KU + kt*32 + seg*8;
            unsigned doff = (unsigned)((s*TILE_BF + row*PITCH + seg*8)*2);
            cpasync16(sBhi + doff, g_WhiT + goff);
            cpasync16(sBlo + doff, g_WloT + goff);
        }
    };
    auto compute = [&](int s){
        #pragma unroll
        for (int kk=0;kk<2;kk++){
            const int kb = kk*16 + tig*2;
            unsigned bh[4][2], bl[4][2];
            #pragma unroll
            for (int j=0;j<4;j++){
                int nl = warp_n*32 + j*8 + gid;
                const __nv_bfloat16* bp  = BsHi + s*TILE_BF + nl*PITCH + kb;
                const __nv_bfloat16* bp2 = BsLo + s*TILE_BF + nl*PITCH + kb;
                bh[j][0] = *(const unsigned*)bp;   bh[j][1] = *(const unsigned*)(bp+8);
                bl[j][0] = *(const unsigned*)bp2;  bl[j][1] = *(const unsigned*)(bp2+8);
            }
            #pragma unroll
            for (int i=0;i<4;i++){
                int mr = warp_m*64 + i*16;
                const __nv_bfloat16* ap  = AsHi + s*TILE_BF + (mr+gid)*PITCH + kb;
                const __nv_bfloat16* ap2 = AsLo + s*TILE_BF + (mr+gid)*PITCH + kb;
                unsigned ah0 = *(const unsigned*)ap;
                unsigned ah1 = *(const unsigned*)(ap + 8*PITCH);
                unsigned ah2 = *(const unsigned*)(ap + 8);
                unsigned ah3 = *(const unsigned*)(ap + 8*PITCH + 8);
                unsigned al0 = *(const unsigned*)ap2;
                unsigned al1 = *(const unsigned*)(ap2 + 8*PITCH);
                unsigned al2 = *(const unsigned*)(ap2 + 8);
                unsigned al3 = *(const unsigned*)(ap2 + 8*PITCH + 8);
                #pragma unroll
                for (int j=0;j<4;j++){
                    mma_bf16(acc[i][j], ah0,ah1,ah2,ah3, bh[j][0],bh[j][1]);
                    mma_bf16(acc[i][j], ah0,ah1,ah2,ah3, bl[j][0],bl[j][1]);
                    mma_bf16(acc[i][j], al0,al1,al2,al3, bh[j][0],bh[j][1]);
                }
            }
        }
    };

    loadA(0, 0); loadB(0, 0);
    asm volatile("cp.async.commit_group;");
    asm volatile("cp.async.wait_group 0;");
    __syncthreads();

    const int KT = KU/32;   // 24
    for (int kt=0; kt<KT; kt++){
        int buf = kt & 1;
        if (kt+1 < KT){
            loadA(buf^1, kt+1);
            loadB(buf^1, kt+1);
            asm volatile("cp.async.commit_group;");
        }
        compute(buf);
        if (kt+1 < KT){
            asm volatile("cp.async.wait_group 0;");
        }
        __syncthreads();
    }

    #pragma unroll
    for (int i=0;i<4;i++){
        int gm = m0 + warp_m*64 + i*16 + gid;
        #pragma unroll
        for (int j=0;j<4;j++){
            int gn = n0 + warp_n*32 + j*8 + tig*2;
            if (gn < V_){
                float b0 = bias[gn], b1 = bias[gn+1];
                *(float2*)(C + (size_t)gm*V_ + gn) = make_float2(acc[i][j][0]+b0, acc[i][j][1]+b1);
                *(float2*)(C + (size_t)(gm+8)*V_ + gn) = make_float2(acc[i][j][2]+b0, acc[i][j][3]+b1);
            }
        }
    }
}

// ---------------- persistent sequential loop ----------------
// smem floats: W_A 4096 | W_C 4096 | scr 8192 | DNC region 28808
#define LOOP_SMEM_FLOATS (4096 + 4096 + 8192 + 28808)

__global__ __launch_bounds__(THR) void loop_kernel(const float* __restrict__ W_iface,
                                                   const float* __restrict__ b_iface){
    extern __shared__ float sm[];
    float* W_A  = sm;                  // 256*16 (rv-part LSTM weights)
    float* W_C  = W_A + 4096;          // 512*8 (iface cols, C-blocks only)
    float* scr  = W_C + 4096;          // 8192
    float* M_s  = scr + 8192;          // 128*65  (helpers: W_B overlay)
    float* L_s  = M_s + 8320;          // 128*129
    float* wr_s = L_s + 16512;         // 512
    float* u_s  = wr_s + 512;          // 128
    float* p_s  = u_s + 128;           // 128
    float* ww_s = p_s + 128;           // 128
    float* xi   = ww_s + 128;          // 472
    float* fwdw = xi + 472;            // 512
    float* bwdw = fwdw + 512;          // 512
    float* crs  = bwdw + 512;          // 512
    float* unew = crs + 512;           // 128
    float* srt  = unew + 128;          // 128
    float* incl = srt + 128;           // 128
    float* a_s  = incl + 128;          // 128
    float* wwn  = a_s + 128;           // 128
    float* red  = wwn + 128;           // 128
    float* act  = red + 128;           // 176
    // scr carve-outs for phase D
    float* wrT  = scr;                 // [0,512)
    float* crsT = scr + 512;           // [512,1024)
    float* rkT  = scr + 1024;          // [1024,1280)
    float* P    = scr + 1280;          // [1280,8192): 6912 floats of partials
    int*  sortP = (int*)P;             // aliases P (used before P writes)
    float* W_B  = M_s;                 // helpers: 512*32 h-part weights

    const int tid  = threadIdx.x;
    const int bx   = blockIdx.x;
    const int wid  = tid >> 5;
    const int lane = tid & 31;
    const int b    = bx;
    const bool isC = (bx < 32) || (bx >= 96);
    const int cidx = (bx < 32) ? bx : bx - 64;

    for (int i=tid;i<256*16;i+=THR){
        int k = i >> 4, c = i & 15;
        W_A[i] = g_Wt[(size_t)k*G4H + bx*16 + c];
    }
    if (isC){
        for (int i=tid;i<512*8;i+=THR){
            int k = i >> 3, c = i & 7;
            int col = cidx*8 + c;
            W_C[i] = (col < IFACE_) ? W_iface[(size_t)k*IFACE_ + col] : 0.f;
        }
    }
    if (bx < B_){
        for (int i=tid;i<128*65;i+=THR)  M_s[i]=0.f;
        for (int i=tid;i<128*129;i+=THR) L_s[i]=0.f;
        for (int i=tid;i<512;i+=THR)     wr_s[i]=0.f;
        if (tid < N_){ u_s[tid]=0.f; p_s[tid]=0.f; ww_s[tid]=0.f; }
    } else if (bx < 96){
        for (int i=tid;i<512*32;i+=THR){
            int k = i >> 5, c = i & 31;
            W_B[i] = g_Wt[(size_t)(256+k)*G4H + (bx-32)*32 + c];
        }
    }
    __syncthreads();

    float c_reg = 0.f;
    unsigned ep = 0;
    ull* scr2 = (ull*)scr;

    for (int t=0;t<T_;t++){
        const int rd = t & 1, wrb = rd ^ 1;

        // ============ Phase A: gates = G0 + Gh + Wrv@rv ; LSTM elementwise ============
        {
            const int kbeg = wid*16;
            ull acc2[8];
            #pragma unroll
            for (int c=0;c<8;c++) acc2[c]=0ull;
            #pragma unroll
            for (int k=kbeg;k<kbeg+16;k++){
                ull as = splat2f(__ldcg(g_rvT + k*B_ + lane));
                const ulonglong2* wp = (const ulonglong2*)(W_A + k*16);
                ulonglong2 w01 = wp[0], w23 = wp[1], w45 = wp[2], w67 = wp[3];
                ffma2(acc2[0], as, w01.x); ffma2(acc2[1], as, w01.y);
                ffma2(acc2[2], as, w23.x); ffma2(acc2[3], as, w23.y);
                ffma2(acc2[4], as, w45.x); ffma2(acc2[5], as, w45.y);
                ffma2(acc2[6], as, w67.x); ffma2(acc2[7], as, w67.y);
            }
            #pragma unroll
            for (int c=0;c<8;c++) scr2[wid*256 + c*32 + lane] = acc2[c];
        }
        __syncthreads();
        if (tid < 128){
            int uu = tid >> 5;
            float4 s = *(const float4*)(g_G0 + ((size_t)lane*T_ + t)*G4H + bx*16 + uu*4);
            float4 gh = __ldcg((const float4*)(g_Gh + (size_t)lane*G4H + bx*16 + uu*4));
            s.x += gh.x; s.y += gh.y; s.z += gh.z; s.w += gh.w;
            ull s01 = pack2(s.x, s.y), s23 = pack2(s.z, s.w);
            #pragma unroll
            for (int w16=0;w16<16;w16++){
                fadd2(s01, scr2[w16*256 + (2*uu  )*32 + lane]);
                fadd2(s23, scr2[w16*256 + (2*uu+1)*32 + lane]);
            }
            float2 g01 = unpack2(s01), g23 = unpack2(s23);
            float c = sigf(g01.y)*c_reg + sigf(g01.x)*tanhf(g23.x);
            float h = sigf(g23.y)*tanhf(c);
            c_reg = c;
            int jj = bx*4 + uu;
            g_hT[wrb][jj*B_ + lane] = h;
            size_t btrow = (size_t)lane*T_ + t;
            __nv_bfloat16 hh = __float2bfloat16(h);
            g_Uhi[btrow*KU + jj] = hh;
            g_Ulo[btrow*KU + jj] = __float2bfloat16(h - __bfloat162float(hh));
        }
        gridbar(++ep);

        // ============ Phase B: C (64 blocks) -> flags ; Gh (blocks 32..95) ; D (0..31) ============
        if (isC){
            // iface: 8 cols, split-K over 16 warps
            const int kbeg = wid*32;
            float acc[8];
            #pragma unroll
            for (int c=0;c<8;c++) acc[c]=0.f;
            const float* hsrc = g_hT[wrb];
            #pragma unroll 4
            for (int k=kbeg;k<kbeg+32;k++){
                float a = __ldcg(hsrc + k*B_ + lane);
                const float4* wp = (const float4*)(W_C + k*8);
                float4 w0 = wp[0], w1 = wp[1];
                acc[0]+=a*w0.x; acc[1]+=a*w0.y; acc[2]+=a*w0.z; acc[3]+=a*w0.w;
                acc[4]+=a*w1.x; acc[5]+=a*w1.y; acc[6]+=a*w1.z; acc[7]+=a*w1.w;
            }
            #pragma unroll
            for (int c=0;c<8;c++) scr[wid*256 + c*32 + lane] = acc[c];
            __syncthreads();
            if (tid < 256){
                int c = tid >> 5, ln = tid & 31;
                int col = cidx*8 + c;
                if (col < IFACE_){
                    float s = b_iface[col];
                    #pragma unroll
                    for (int w16=0;w16<16;w16++) s += scr[w16*256 + c*32 + ln];
                    g_xiT[col*B_ + ln] = s;
                }
            }
            __syncthreads();
            if (tid == 0){
                __threadfence();
                st_rlx(&g_cflags[cidx*32], (unsigned)(t+1));
            }
        }

        if (bx >= 32 && bx < 96){
            // ---- Gh precompute for step t+1 ----
            if (t+1 < T_){
                const int g  = wid >> 3;
                const int wk = wid & 7;
                ull acc[8];
                #pragma unroll
                for (int c=0;c<8;c++) acc[c]=0ull;
                const float* hsrc = g_hT[wrb];
                #pragma unroll 4
                for (int k=wk*64; k<wk*64+64; k++){
                    ull as = splat2f(__ldcg(hsrc + k*B_ + lane));
                    const ulonglong2* wp = (const ulonglong2*)(W_B + k*32 + g*16);
                    ulonglong2 w01 = wp[0], w23 = wp[1], w45 = wp[2], w67 = wp[3];
                    ffma2(acc[0], as, w01.x); ffma2(acc[1], as, w01.y);
                    ffma2(acc[2], as, w23.x); ffma2(acc[3], as, w23.y);
                    ffma2(acc[4], as, w45.x); ffma2(acc[5], as, w45.y);
                    ffma2(acc[6], as, w67.x); ffma2(acc[7], as, w67.y);
                }
                #pragma unroll
                for (int c=0;c<8;c++) scr2[g*2048 + wk*256 + c*32 + lane] = acc[c];
                __syncthreads();
                {
                    int cp = tid >> 5;
                    int g2 = cp >> 3, c2 = cp & 7;
                    ull s = scr2[g2*2048 + c2*32 + lane];
                    #pragma unroll
                    for (int w8=1;w8<8;w8++) fadd2(s, scr2[g2*2048 + w8*256 + c2*32 + lane]);
                    float2 v = unpack2(s);
                    int col = (bx-32)*32 + g2*16 + 2*c2;
                    *(float2*)(g_Gh + (size_t)lane*G4H + col) = v;
                }
            }
        } else if (bx < B_){
            // ---- wait for all iface flags, then DNC ----
            if (tid < 64){
                while (ld_rlx(&g_cflags[tid*32]) < (unsigned)(t+1)) { }
            }
            __syncthreads();

            int rk = 0;
            const int dn = tid & 127, dp = tid >> 7;
            for (int i=tid;i<IFACE_;i+=THR) xi[i] = __ldcg(g_xiT + i*B_ + b);
            wrT[tid] = wr_s[((tid&3)<<7) | (tid>>2)];
            __syncthreads();

            if (tid < 64){
                act[8+tid]  = sigf(xi[325+tid]);
                act[72+tid] = xi[389+tid];
            } else if (tid < 68){
                act[tid-64] = 1.f + splusf(xi[256 + (tid-64)]);
            } else if (tid == 68){
                act[4] = 1.f + splusf(xi[324]);
            } else if (tid < 73){
                act[136 + (tid-69)] = sigf(xi[453 + (tid-69)]);
            } else if (tid == 73){
                act[140] = sigf(xi[457]);
            } else if (tid == 74){
                act[141] = sigf(xi[458]);
            } else if (tid < 79){
                int r = tid - 75;
                float q0=xi[459+r*3], q1=xi[459+r*3+1], q2=xi[459+r*3+2];
                float m = fmaxf(q0, fmaxf(q1,q2));
                float e0=expf(q0-m), e1=expf(q1-m), e2=expf(q2-m);
                float s = e0+e1+e2;
                act[144+r*3]=e0/s; act[145+r*3]=e1/s; act[146+r*3]=e2/s;
            } else if (tid < 83){
                int r = tid - 79; float s = 0.f;
                #pragma unroll 8
                for (int w=0;w<WD_;w++){ float v = xi[r*WD_+w]; s += v*v; }
                act[156+r] = sqrtf(s);
            } else if (tid == 83){
                float s = 0.f;
                #pragma unroll 8
                for (int w=0;w<WD_;w++){ float v = xi[260+w]; s += v*v; }
                act[160] = sqrtf(s);
            } else if (tid >= 256 && tid < 512){
                int idx = tid - 256;
                rkT[idx] = xi[((idx&3)<<6) | (idx>>2)];
            }
            __syncthreads();

            if (tid < N_){
                float psi = 1.f;
                #pragma unroll
                for (int r=0;r<R_;r++) psi *= (1.f - act[136+r]*wr_s[r*N_+tid]);
                float uo=u_s[tid], wo=ww_s[tid];
                unew[tid] = (uo + wo - uo*wo)*psi;
            }
            __syncthreads();

            // ---- sort ranks: split 128 comparisons over 4 parts ----
            {
                float ui = unew[dn];
                int prk = 0;
                const int j0 = dp*32;
                #pragma unroll 8
                for (int jj=0;jj<32;jj++){
                    int j = j0 + jj;
                    float uj = unew[j];
                    prk += (uj < ui) || (uj == ui && j < dn);
                }
                sortP[dp*128 + dn] = prk;
            }
            __syncthreads();
            if (tid < N_){
                rk = sortP[tid] + sortP[128+tid] + sortP[256+tid] + sortP[384+tid];
                srt[rk] = unew[tid];
            }
            __syncthreads();

            // ---- parallel cumprod (inclusive) + write-content partials ----
            float cp_p = 1.f;
            if (tid < N_){
                int w4 = tid >> 5, ln = tid & 31;
                cp_p = srt[tid];
                #pragma unroll
                for (int off=1;off<32;off<<=1){
                    float o = __shfl_up_sync(0xffffffffu, cp_p, off);
                    if (ln >= off) cp_p *= o;
                }
                if (ln == 31) red[w4] = cp_p;
            }
            __syncthreads();
            if (tid < N_){
                int w4 = tid >> 5;
                float pre = 1.f;
                #pragma unroll
                for (int j=0;j<3;j++) if (j < w4) pre *= red[j];
                incl[tid] = cp_p * pre;
            }
            {
                float s2=0.f, dot=0.f;
                const int w0 = dp*16;
                #pragma unroll
                for (int w=w0;w<w0+16;w++){
                    float m = M_s[dn*65+w];
                    s2 += m*m; dot += m*xi[260+w];
                }
                P[dp*128 + dn] = dot;
                P[512 + dp*128 + dn] = s2;
            }
            __syncthreads();

            float score_w = 0.f, ew = 0.f;
            if (tid < N_){
                float ce = (rk == 0) ? 1.f : incl[rk-1];
                a_s[tid] = (1.f - unew[tid]) * ce;
                float dot = P[tid] + P[128+tid] + P[256+tid] + P[384+tid];
                float s2  = P[512+tid] + P[640+tid] + P[768+tid] + P[896+tid];
                score_w = act[4] * (dot / (act[160]*sqrtf(s2) + EPSF));
                float v = score_w;
                #pragma unroll
                for (int o=16;o;o>>=1) v = fmaxf(v, __shfl_xor_sync(0xffffffffu, v, o));
                if ((tid&31)==0) red[tid>>5] = v;
            }
            __syncthreads();
            float mxw = fmaxf(fmaxf(red[0],red[1]), fmaxf(red[2],red[3]));
            if (tid < N_){
                ew = expf(score_w - mxw);
                float s = ew;
                #pragma unroll
                for (int o=16;o;o>>=1) s += __shfl_xor_sync(0xffffffffu, s, o);
                if ((tid&31)==0) red[4 + (tid>>5)] = s;
            }
            __syncthreads();
            float sden = red[4]+red[5]+red[6]+red[7];
            if (tid < N_){
                float wv = act[141]*(act[140]*a_s[tid] + (1.f-act[140])*(ew/sden));
                wwn[tid] = wv;
                float s = wv;
                #pragma unroll
                for (int o=16;o;o>>=1) s += __shfl_xor_sync(0xffffffffu, s, o);
                if ((tid&31)==0) red[8 + (tid>>5)] = s;
            }
            __syncthreads();
            float sumww = red[8]+red[9]+red[10]+red[11];

            for (int i=tid;i<N_*WD_;i+=THR){
                int n=i>>6, w=i&63;
                float wwv = wwn[n];
                M_s[n*65+w] = M_s[n*65+w]*(1.f - wwv*act[8+w]) + wwv*act[72+w];
            }
            for (int i=tid;i<N_*N_;i+=THR){
                int n=i>>7, m=i&127;
                float v = (n==m) ? 0.f
                         : (1.f - wwn[n] - wwn[m])*L_s[n*129+m] + wwn[n]*p_s[m];
                L_s[n*129+m] = v;
            }
            __syncthreads();
            if (tid < N_) p_s[tid] = (1.f - sumww)*p_s[tid] + wwn[tid];

            // ---- MERGED: fwd/bwd partials (new L) + read-content partials (new M) ----
            {
                float f0=0.f,f1=0.f,f2=0.f,f3=0.f, b0=0.f,b1=0.f,b2=0.f,b3=0.f;
                const int m0 = dp*32;
                #pragma unroll 4
                for (int m=m0;m<m0+32;m++){
                    float lr = L_s[dn*129+m];
                    float lc = L_s[m*129+dn];
                    float4 w4 = *(const float4*)(wrT + m*4);
                    f0 += lr*w4.x; f1 += lr*w4.y; f2 += lr*w4.z; f3 += lr*w4.w;
                    b0 += lc*w4.x; b1 += lc*w4.y; b2 += lc*w4.z; b3 += lc*w4.w;
                }
                float* fb = P + dp*1024;
                fb[      dn]=f0; fb[128+dn]=f1; fb[256+dn]=f2; fb[384+dn]=f3;
                fb[512+dn]=b0; fb[640+dn]=b1; fb[768+dn]=b2; fb[896+dn]=b3;

                float s2=0.f, d0=0.f,d1=0.f,d2=0.f,d3=0.f;
                const int w0 = dp*16;
                #pragma unroll
                for (int w=w0;w<w0+16;w++){
                    float m = M_s[dn*65+w];
                    s2 += m*m;
                    float4 rk4 = *(const float4*)(rkT + w*4);
                    d0 += m*rk4.x; d1 += m*rk4.y; d2 += m*rk4.z; d3 += m*rk4.w;
                }
                float* rc = P + 4096 + dp*640;
                rc[      dn]=d0; rc[128+dn]=d1; rc[256+dn]=d2; rc[384+dn]=d3;
                rc[512+dn]=s2;
            }
            __syncthreads();
            {
                // combine both: thread (n=dn, r=dp)
                float fs = P[0*1024 + dp*128 + dn] + P[1*1024 + dp*128 + dn]
                         + P[2*1024 + dp*128 + dn] + P[3*1024 + dp*128 + dn];
                float bs = P[0*1024 + 512 + dp*128 + dn] + P[1*1024 + 512 + dp*128 + dn]
                         + P[2*1024 + 512 + dp*128 + dn] + P[3*1024 + 512 + dp*128 + dn];
                fwdw[dp*128 + dn] = fs;
                bwdw[dp*128 + dn] = bs;
                float d = P[4096 + 0*640 + dp*128 + dn] + P[4096 + 1*640 + dp*128 + dn]
                        + P[4096 + 2*640 + dp*128 + dn] + P[4096 + 3*640 + dp*128 + dn];
                float s2 = P[4096 + 0*640 + 512 + dn] + P[4096 + 1*640 + 512 + dn]
                         + P[4096 + 2*640 + 512 + dn] + P[4096 + 3*640 + 512 + dn];
                float mn = sqrtf(s2);
                crs[dp*128 + dn] = act[dp]*(d/(act[156+dp]*mn + EPSF));
            }
            __syncthreads();
            if (tid < 128){
                int r = tid>>5, ln = tid&31;
                float v = fmaxf(fmaxf(crs[r*N_+ln],crs[r*N_+ln+32]),
                                fmaxf(crs[r*N_+ln+64],crs[r*N_+ln+96]));
                #pragma unroll
                for (int o=16;o;o>>=1) v = fmaxf(v, __shfl_xor_sync(0xffffffffu, v, o));
                if (ln==0) act[164+r]=v;
            }
            __syncthreads();
            if (tid < 128){
                int r = tid>>5, ln = tid&31;
                float m = act[164+r];
                float e0=expf(crs[r*N_+ln   ]-m);
                float e1=expf(crs[r*N_+ln+32]-m);
                float e2=expf(crs[r*N_+ln+64]-m);
                float e3=expf(crs[r*N_+ln+96]-m);
                crs[r*N_+ln]=e0; crs[r*N_+ln+32]=e1; crs[r*N_+ln+64]=e2; crs[r*N_+ln+96]=e3;
                float s = e0+e1+e2+e3;
                #pragma unroll
                for (int o=16;o;o>>=1) s += __shfl_xor_sync(0xffffffffu, s, o);
                if (ln==0) act[168+r]=s;
            }
            __syncthreads();
            {
                int i = dp*128 + dn;
                float w = act[144+dp*3]*bwdw[i] + act[145+dp*3]*(crs[i]/act[168+dp]) + act[146+dp*3]*fwdw[i];
                crs[i] = w;
                crsT[dn*4 + dp] = w;
            }
            __syncthreads();
            // ---- rv partials: 8 parts x 16 n each ----
            {
                int w = tid & 63, part = tid >> 6;
                float s0=0.f,s1=0.f,s2v=0.f,s3=0.f;
                const int n0 = part*16;
                #pragma unroll
                for (int n=n0;n<n0+16;n++){
                    float mv = M_s[n*65+w];
                    float4 c4 = *(const float4*)(crsT + n*4);
                    s0 += c4.x*mv; s1 += c4.y*mv; s2v += c4.z*mv; s3 += c4.w*mv;
                }
                float* rv = P + part*256;
                rv[      w]=s0; rv[ 64+w]=s1; rv[128+w]=s2v; rv[192+w]=s3;
            }
            __syncthreads();
            if (tid < 256){
                int r = tid >> 6, w = tid & 63;
                float s = 0.f;
                #pragma unroll
                for (int part=0;part<8;part++) s += P[part*256 + r*64 + w];
                int idx = r*WD_ + w;
                g_rvT[idx*B_ + b] = s;
                size_t btrow = (size_t)b*T_ + t;
                __nv_bfloat16 sh = __float2bfloat16(s);
                g_Uhi[btrow*KU + H_ + idx] = sh;
                g_Ulo[btrow*KU + H_ + idx] = __float2bfloat16(s - __bfloat162float(sh));
            }
            __syncthreads();
            wr_s[tid] = crs[tid];
            if (tid < N_){ u_s[tid]=unew[tid]; ww_s[tid]=wwn[tid]; }
        }
        gridbar(++ep);
    }
}

// ---------------- launcher ----------------
extern "C" void kernel_launch(void* const* d_in, const int* in_sizes, int n_in,
                              void* d_out, int out_size){
    const int*   tokens  = (const int*)  d_in[0];
    const float* emb     = (const float*)d_in[1];
    const float* w_ih    = (const float*)d_in[2];
    const float* w_hh    = (const float*)d_in[3];
    const float* b_lstm  = (const float*)d_in[4];
    const float* W_iface = (const float*)d_in[5];
    const float* b_iface = (const float*)d_in[6];
    const float* W_out   = (const float*)d_in[7];
    const float* b_out   = (const float*)d_in[8];
    float* out = (float*)d_out;

    const int loop_smem = LOOP_SMEM_FLOATS * (int)sizeof(float);
    cudaFuncSetAttribute(loop_kernel, cudaFuncAttributeMaxDynamicSharedMemorySize, loop_smem);
    const int gout_smem = 8 * TILE_BF * (int)sizeof(__nv_bfloat16);
    cudaFuncSetAttribute(gemm_out, cudaFuncAttributeMaxDynamicSharedMemorySize, gout_smem);

    void *pX, *pG0, *pWihT, *pBl;
    cudaGetSymbolAddress(&pX, g_X);
    cudaGetSymbolAddress(&pG0, g_G0);
    cudaGetSymbolAddress(&pWihT, g_WihT);
    cudaGetSymbolAddress(&pBl, g_bl);

    embed_kernel<<<(BT_*E_ + 255)/256, 256>>>(tokens, emb);
    prep_w<<<(KU*G4H + 255)/256, 256>>>(w_ih, w_hh, b_lstm);
    sgemm128<<<dim3(G4H/128, BT_/128), 256>>>((const float*)pX, (const float*)pWihT,
                                              (const float*)pBl, (float*)pG0, BT_, G4H, E_);
    loop_kernel<<<NBLK, THR, loop_smem>>>(W_iface, b_iface);
    prep_outT<<<dim3(VPAD/32, KU/32), dim3(32,8)>>>(W_out);
    gemm_out<<<dim3((V_+127)/128, BT_/128), 256, gout_smem>>>(b_out, out);
}

// round 12
// speedup vs baseline: 2.8027x; 1.0215x over previous
#include <cuda_runtime.h>
#include <cuda_bf16.h>
#include <math.h>

#define B_ 32
#define T_ 256
#define V_ 10000
#define VPAD 10112
#define E_ 256
#define H_ 512
#define N_ 128
#define WD_ 64
#define R_ 4
#define IFACE_ 471
#define G4H 2048          // 4*H
#define KU 768            // H + R*WD
#define BT_ (B_*T_)       // 8192
#define EPSF 1e-6f
#define NBLK 128
#define THR 512
#define MP 66             // M row pitch
#define LP 130            // L row pitch

typedef unsigned long long ull;

// ---------------- f32x2 helpers ----------------
__device__ __forceinline__ ull pack2(float x, float y){
    ull r; asm("mov.b64 %0, {%1,%2};" : "=l"(r) : "r"(__float_as_uint(x)), "r"(__float_as_uint(y))); return r;
}
__device__ __forceinline__ ull splat2f(float x){ return pack2(x, x); }
__device__ __forceinline__ float2 unpack2(ull v){
    unsigned lo, hi;
    asm("mov.b64 {%0,%1}, %2;" : "=r"(lo), "=r"(hi) : "l"(v));
    return make_float2(__uint_as_float(lo), __uint_as_float(hi));
}
__device__ __forceinline__ void ffma2(ull& d, ull a, ull b){
    asm("fma.rn.f32x2 %0, %1, %2, %0;" : "+l"(d) : "l"(a), "l"(b));
}
__device__ __forceinline__ void fadd2(ull& d, ull a){
    asm("add.rn.f32x2 %0, %0, %1;" : "+l"(d) : "l"(a));
}
__device__ __forceinline__ void cpasync16(unsigned dst, const void* src){
    asm volatile("cp.async.cg.shared.global [%0], [%1], 16;" :: "r"(dst), "l"(src));
}

// ---------------- GPU-scope relaxed flag ops ----------------
__device__ __forceinline__ unsigned ld_rlx(const unsigned* p){
    unsigned v;
    asm volatile("ld.relaxed.gpu.global.u32 %0, [%1];" : "=r"(v) : "l"(p) : "memory");
    return v;
}
__device__ __forceinline__ void st_rlx(unsigned* p, unsigned v){
    asm volatile("st.relaxed.gpu.global.u32 [%0], %1;" :: "l"(p), "r"(v) : "memory");
}

// ---------------- device scratch ----------------
__device__ __align__(128) float g_X[BT_*E_];
__device__ __align__(128) float g_G0[(size_t)BT_*G4H];
__device__ __align__(128) float g_WihT[E_*G4H];
__device__ __align__(128) float g_Wt[KU*G4H];
__device__ __align__(128) float g_bl[G4H];
__device__ __align__(128) __nv_bfloat16 g_WhiT[(size_t)VPAD*KU];
__device__ __align__(128) __nv_bfloat16 g_WloT[(size_t)VPAD*KU];
__device__ __align__(128) __nv_bfloat16 g_Uhi[(size_t)BT_*KU];
__device__ __align__(128) __nv_bfloat16 g_Ulo[(size_t)BT_*KU];
__device__ __align__(128) float g_hT[2][H_*B_];
__device__ __align__(128) float g_rvT[R_*WD_*B_];
__device__ __align__(128) float g_xiT[IFACE_*B_];
__device__ __align__(128) float g_Gh[B_*G4H];
__device__ __align__(128) unsigned g_flags[NBLK*32];
__device__ __align__(128) unsigned g_cflags[64*32];
__device__ unsigned g_gen;

__device__ __forceinline__ float sigf(float x){ return 1.f/(1.f + expf(-x)); }
__device__ __forceinline__ float splusf(float x){ return fmaxf(x,0.f) + log1pf(expf(-fabsf(x))); }

// ---------------- all-to-all single-hop grid barrier ----------------
__device__ __forceinline__ void gridbar(unsigned ep){
    __syncthreads();
    if (threadIdx.x == 0){
        __threadfence();
        st_rlx(&g_flags[blockIdx.x*32], ep);
    }
    if (threadIdx.x < NBLK){
        while (ld_rlx(&g_flags[threadIdx.x*32]) < ep) { }
    }
    __syncthreads();
}

// ---------------- prep kernels ----------------
__global__ void embed_kernel(const int* __restrict__ tok, const float* __restrict__ emb){
    int i = blockIdx.x*256 + threadIdx.x;
    if (i >= BT_*E_) return;
    int bt = i / E_, e = i % E_;
    g_X[i] = tanhf(emb[(size_t)tok[bt]*E_ + e]);
}

__global__ void prep_w(const float* __restrict__ w_ih, const float* __restrict__ w_hh,
                       const float* __restrict__ b_lstm){
    int i = blockIdx.x*256 + threadIdx.x;
    if (i < KU*G4H){
        int k = i >> 11, col = i & 2047;
        int jj = col >> 2, g = col & 3;
        int j = g*H_ + jj;
        g_Wt[i] = (k < R_*WD_) ? w_ih[(size_t)j*(E_+R_*WD_) + E_ + k]
                               : w_hh[(size_t)j*H_ + (k - R_*WD_)];
    }
    if (i < E_*G4H){
        int e = i >> 11, col = i & 2047;
        int jj = col >> 2, g = col & 3;
        int j = g*H_ + jj;
        g_WihT[i] = w_ih[(size_t)j*(E_+R_*WD_) + e];
    }
    if (i < G4H){
        int jj = i >> 2, g = i & 3;
        g_bl[i] = b_lstm[g*H_ + jj];
    }
    if (i < 2*H_*B_) ((float*)g_hT)[i] = 0.f;
    if (i < R_*WD_*B_) g_rvT[i] = 0.f;
    if (i < B_*G4H) g_Gh[i] = 0.f;
    if (i < NBLK*32) g_flags[i] = 0u;
    if (i < 64*32) g_cflags[i] = 0u;
    if (i == 0) g_gen = 0u;
}

__global__ void prep_outT(const float* __restrict__ W_out){
    __shared__ float tile[32][33];
    int n0 = blockIdx.x*32, k0 = blockIdx.y*32;
    int tx = threadIdx.x, ty = threadIdx.y;
    #pragma unroll
    for (int dy=0;dy<32;dy+=8){
        int k = k0+ty+dy, n = n0+tx;
        tile[ty+dy][tx] = (n < V_) ? W_out[(size_t)k*V_+n] : 0.f;
    }
    __syncthreads();
    #pragma unroll
    for (int dy=0;dy<32;dy+=8){
        int n = n0+ty+dy, k = k0+tx;
        float v = tile[tx][ty+dy];
        __nv_bfloat16 h = __float2bfloat16(v);
        g_WhiT[(size_t)n*KU+k] = h;
        g_WloT[(size_t)n*KU+k] = __float2bfloat16(v - __bfloat162float(h));
    }
}

// ---------------- pipelined fp32 SGEMM: C = A(MxK)@B(KxN) (+bias) ----------------
__global__ __launch_bounds__(256) void sgemm128(const float* __restrict__ A,
                         const float* __restrict__ Bm,
                         const float* __restrict__ bias, float* __restrict__ C,
                         int M, int Nn, int K){
    __shared__ float As[2][8][128];
    __shared__ float Bs[2][8][128];
    int tid = threadIdx.x;
    int row0 = blockIdx.y*128, col0 = blockIdx.x*128;
    int trow = (tid >> 4) * 8;
    int tcol = (tid & 15) * 8;
    float acc[8][8];
    #pragma unroll
    for (int i=0;i<8;i++)
        #pragma unroll
        for (int j=0;j<8;j++) acc[i][j]=0.f;

    int arow = tid >> 1, ak = (tid & 1)*4;
    int bk = tid >> 5,  bn = (tid & 31)*4;
    const float* Aptr = A + (size_t)(row0 + arow)*K + ak;
    int gn = col0 + bn;

    float4 av = *(const float4*)(Aptr);
    float4 bv = make_float4(0.f,0.f,0.f,0.f);
    if (gn < Nn) bv = *(const float4*)(Bm + (size_t)bk*Nn + gn);
    As[0][ak+0][arow]=av.x; As[0][ak+1][arow]=av.y; As[0][ak+2][arow]=av.z; As[0][ak+3][arow]=av.w;
    *(float4*)(&Bs[0][bk][bn]) = bv;
    __syncthreads();

    int buf = 0;
    for (int k0=0;k0<K;k0+=8){
        bool more = (k0 + 8) < K;
        if (more){
            av = *(const float4*)(Aptr + k0 + 8);
            bv = make_float4(0.f,0.f,0.f,0.f);
            if (gn < Nn) bv = *(const float4*)(Bm + (size_t)(k0+8+bk)*Nn + gn);
        }
        #pragma unroll
        for (int kk=0;kk<8;kk++){
            float ar[8], br[8];
            *(float4*)(ar)   = *(const float4*)(&As[buf][kk][trow]);
            *(float4*)(ar+4) = *(const float4*)(&As[buf][kk][trow+4]);
            *(float4*)(br)   = *(const float4*)(&Bs[buf][kk][tcol]);
            *(float4*)(br+4) = *(const float4*)(&Bs[buf][kk][tcol+4]);
            #pragma unroll
            for (int i=0;i<8;i++)
                #pragma unroll
                for (int j=0;j<8;j++) acc[i][j] += ar[i]*br[j];
        }
        if (more){
            int nb = buf ^ 1;
            As[nb][ak+0][arow]=av.x; As[nb][ak+1][arow]=av.y; As[nb][ak+2][arow]=av.z; As[nb][ak+3][arow]=av.w;
            *(float4*)(&Bs[nb][bk][bn]) = bv;
            __syncthreads();
            buf = nb;
        }
    }
    #pragma unroll
    for (int i=0;i<8;i++){
        size_t gm = (size_t)(row0 + trow + i);
        #pragma unroll
        for (int j=0;j<8;j+=4){
            int gnn = col0 + tcol + j;
            if (gnn < Nn){
                float4 v = make_float4(acc[i][j],acc[i][j+1],acc[i][j+2],acc[i][j+3]);
                if (bias){ v.x+=bias[gnn]; v.y+=bias[gnn+1]; v.z+=bias[gnn+2]; v.w+=bias[gnn+3]; }
                *(float4*)(C + gm*Nn + gnn) = v;
            }
        }
    }
}

// ---------------- bf16-split tensor-core GEMM: out = U@W_out + b ----------------
#define PITCH 40
#define TILE_BF (128*PITCH)

__device__ __forceinline__ void mma_bf16(float* c, unsigned a0,unsigned a1,unsigned a2,unsigned a3,
                                         unsigned b0, unsigned b1){
    asm volatile("mma.sync.aligned.m16n8k16.row.col.f32.bf16.bf16.f32 "
        "{%0,%1,%2,%3}, {%4,%5,%6,%7}, {%8,%9}, {%0,%1,%2,%3};"
        : "+f"(c[0]),"+f"(c[1]),"+f"(c[2]),"+f"(c[3])
        : "r"(a0),"r"(a1),"r"(a2),"r"(a3),"r"(b0),"r"(b1));
}

__global__ __launch_bounds__(256) void gemm_out(const float* __restrict__ bias,
                                                float* __restrict__ C){
    extern __shared__ __align__(16) char smraw[];
    __nv_bfloat16* AsHi = (__nv_bfloat16*)smraw;
    __nv_bfloat16* AsLo = AsHi + 2*TILE_BF;
    __nv_bfloat16* BsHi = AsLo + 2*TILE_BF;
    __nv_bfloat16* BsLo = BsHi + 2*TILE_BF;

    const int tid = threadIdx.x, lane = tid & 31, wid = tid >> 5;
    const int warp_m = wid >> 2, warp_n = wid & 3;
    const int gid = lane >> 2, tig = lane & 3;
    const int m0 = blockIdx.y*128, n0 = blockIdx.x*128;

    float acc[4][4][4];
    #pragma unroll
    for (int i=0;i<4;i++)
        #pragma unroll
        for (int j=0;j<4;j++)
            #pragma unroll
            for (int q=0;q<4;q++) acc[i][j][q]=0.f;

    unsigned sAhi = (unsigned)__cvta_generic_to_shared(AsHi);
    unsigned sAlo = (unsigned)__cvta_generic_to_shared(AsLo);
    unsigned sBhi = (unsigned)__cvta_generic_to_shared(BsHi);
    unsigned sBlo = (unsigned)__cvta_generic_to_shared(BsLo);

    auto loadA = [&](int s, int kt){
        #pragma unroll
        for (int it=0; it<2; it++){
            int idx = it*256 + tid;
            int row = idx>>2, seg = idx&3;
            size_t goff = (size_t)(m0+row)*KU + kt*32 + seg*8;
            unsigned doff = (unsigned)((s*TILE_BF + row*PITCH + seg*8)*2);
            cpasync16(sAhi + doff, g_Uhi + goff);
            cpasync16(sAlo + doff, g_Ulo + goff);
        }
    };
    auto loadB = [&](int s, int kt){
        #pragma unroll
        for (int it=0; it<2; it++){
            int idx = it*256 + tid;
            int row = idx>>2, seg = idx&3;
            size_t goff = (size_t)(n0+row)*KU + kt*32 + seg*8;
            unsigned doff = (unsigned)((s*TILE_BF + row*PITCH + seg*8)*2);
            cpasync16(sBhi + doff, g_WhiT + goff);
            cpasync16(sBlo + doff, g_WloT + goff);
        }
    };
    auto compute = [&](int s){
        #pragma unroll
        for (int kk=0;kk<2;kk++){
            const int kb = kk*16 + tig*2;
            unsigned bh[4][2], bl[4][2];
            #pragma unroll
            for (int j=0;j<4;j++){
                int nl = warp_n*32 + j*8 + gid;
                const __nv_bfloat16* bp  = BsHi + s*TILE_BF + nl*PITCH + kb;
                const __nv_bfloat16* bp2 = BsLo + s*TILE_BF + nl*PITCH + kb;
                bh[j][0] = *(const unsigned*)bp;   bh[j][1] = *(const unsigned*)(bp+8);
                bl[j][0] = *(const unsigned*)bp2;  bl[j][1] = *(const unsigned*)(bp2+8);
            }
            #pragma unroll
            for (int i=0;i<4;i++){
                int mr = warp_m*64 + i*16;
                const __nv_bfloat16* ap  = AsHi + s*TILE_BF + (mr+gid)*PITCH + kb;
                const __nv_bfloat16* ap2 = AsLo + s*TILE_BF + (mr+gid)*PITCH + kb;
                unsigned ah0 = *(const unsigned*)ap;
                unsigned ah1 = *(const unsigned*)(ap + 8*PITCH);
                unsigned ah2 = *(const unsigned*)(ap + 8);
                unsigned ah3 = *(const unsigned*)(ap + 8*PITCH + 8);
                unsigned al0 = *(const unsigned*)ap2;
                unsigned al1 = *(const unsigned*)(ap2 + 8*PITCH);
                unsigned al2 = *(const unsigned*)(ap2 + 8);
                unsigned al3 = *(const unsigned*)(ap2 + 8*PITCH + 8);
                #pragma unroll
                for (int j=0;j<4;j++){
                    mma_bf16(acc[i][j], ah0,ah1,ah2,ah3, bh[j][0],bh[j][1]);
                    mma_bf16(acc[i][j], ah0,ah1,ah2,ah3, bl[j][0],bl[j][1]);
                    mma_bf16(acc[i][j], al0,al1,al2,al3, bh[j][0],bh[j][1]);
                }
            }
        }
    };

    loadA(0, 0); loadB(0, 0);
    asm volatile("cp.async.commit_group;");
    asm volatile("cp.async.wait_group 0;");
    __syncthreads();

    const int KT = KU/32;
    for (int kt=0; kt<KT; kt++){
        int buf = kt & 1;
        if (kt+1 < KT){
            loadA(buf^1, kt+1);
            loadB(buf^1, kt+1);
            asm volatile("cp.async.commit_group;");
        }
        compute(buf);
        if (kt+1 < KT){
            asm volatile("cp.async.wait_group 0;");
        }
        __syncthreads();
    }

    #pragma unroll
    for (int i=0;i<4;i++){
        int gm = m0 + warp_m*64 + i*16 + gid;
        #pragma unroll
        for (int j=0;j<4;j++){
            int gn = n0 + warp_n*32 + j*8 + tig*2;
            if (gn < V_){
                float b0 = bias[gn], b1 = bias[gn+1];
                *(float2*)(C + (size_t)gm*V_ + gn) = make_float2(acc[i][j][0]+b0, acc[i][j][1]+b1);
                *(float2*)(C + (size_t)(gm+8)*V_ + gn) = make_float2(acc[i][j][2]+b0, acc[i][j][3]+b1);
            }
        }
    }
}

// ---------------- persistent sequential loop ----------------
#define LOOP_SMEM_FLOATS (16384 + 28936)

__global__ __launch_bounds__(THR) void loop_kernel(const float* __restrict__ W_iface,
                                                   const float* __restrict__ b_iface){
    extern __shared__ float sm[];
    float* W_A  = sm;                  // 256*16
    float* W_C  = W_A + 4096;          // 512*8
    float* scr  = W_C + 4096;          // 8192
    float* M_s  = scr + 8192;          // 128*66
    float* L_s  = M_s + 128*MP;        // 128*130
    float* wr_s = L_s + 128*LP;        // 512
    float* u_s  = wr_s + 512;          // 128
    float* p_s  = u_s + 128;           // 128
    float* ww_s = p_s + 128;           // 128
    float* xi   = ww_s + 128;          // 472
    float* fwdw = xi + 472;            // 512
    float* bwdw = fwdw + 512;          // 512
    float* crs  = bwdw + 512;          // 512
    float* unew = crs + 512;           // 128
    float* srt  = unew + 128;          // 128
    float* incl = srt + 128;           // 128
    float* a_s  = incl + 128;          // 128
    float* wwn  = a_s + 128;           // 128
    float* red  = wwn + 128;           // 128
    float* act  = red + 128;           // 176
    // scr carve-outs (phase D)
    float* wrT  = scr;                 // [0,512)
    float* crsT = scr + 512;           // [512,1024)
    float* rkT  = scr + 1024;          // [1024,1280)
    float* P    = scr + 1280;          // [1280,8192)
    int*  sortP = (int*)P;
    float* W_B  = M_s;                 // helpers overlay: 512*32

    const int tid  = threadIdx.x;
    const int bx   = blockIdx.x;
    const int wid  = tid >> 5;
    const int lane = tid & 31;
    const int b    = bx;
    const bool isC = (bx < 32) || (bx >= 96);
    const int cidx = (bx < 32) ? bx : bx - 64;

    for (int i=tid;i<256*16;i+=THR){
        int k = i >> 4, c = i & 15;
        W_A[i] = g_Wt[(size_t)k*G4H + bx*16 + c];
    }
    if (isC){
        for (int i=tid;i<512*8;i+=THR){
            int k = i >> 3, c = i & 7;
            int col = cidx*8 + c;
            W_C[i] = (col < IFACE_) ? W_iface[(size_t)k*IFACE_ + col] : 0.f;
        }
    }
    if (bx < B_){
        for (int i=tid;i<128*MP;i+=THR)  M_s[i]=0.f;
        for (int i=tid;i<128*LP;i+=THR)  L_s[i]=0.f;
        for (int i=tid;i<512;i+=THR)     wr_s[i]=0.f;
        if (tid < N_){ u_s[tid]=0.f; p_s[tid]=0.f; ww_s[tid]=0.f; }
    } else if (bx < 96){
        for (int i=tid;i<512*32;i+=THR){
            int k = i >> 5, c = i & 31;
            W_B[i] = g_Wt[(size_t)(256+k)*G4H + (bx-32)*32 + c];
        }
    }
    __syncthreads();

    float c_reg = 0.f;
    unsigned ep = 0;
    ull* scr2 = (ull*)scr;

    for (int t=0;t<T_;t++){
        const int rd = t & 1, wrb = rd ^ 1;

        // ============ Phase A ============
        {
            const int kbeg = wid*16;
            ull acc2[8];
            #pragma unroll
            for (int c=0;c<8;c++) acc2[c]=0ull;
            #pragma unroll
            for (int k=kbeg;k<kbeg+16;k++){
                ull as = splat2f(__ldcg(g_rvT + k*B_ + lane));
                const ulonglong2* wp = (const ulonglong2*)(W_A + k*16);
                ulonglong2 w01 = wp[0], w23 = wp[1], w45 = wp[2], w67 = wp[3];
                ffma2(acc2[0], as, w01.x); ffma2(acc2[1], as, w01.y);
                ffma2(acc2[2], as, w23.x); ffma2(acc2[3], as, w23.y);
                ffma2(acc2[4], as, w45.x); ffma2(acc2[5], as, w45.y);
                ffma2(acc2[6], as, w67.x); ffma2(acc2[7], as, w67.y);
            }
            #pragma unroll
            for (int c=0;c<8;c++) scr2[wid*256 + c*32 + lane] = acc2[c];
        }
        __syncthreads();
        if (tid < 128){
            int uu = tid >> 5;
            float4 s = *(const float4*)(g_G0 + ((size_t)lane*T_ + t)*G4H + bx*16 + uu*4);
            float4 gh = __ldcg((const float4*)(g_Gh + (size_t)lane*G4H + bx*16 + uu*4));
            s.x += gh.x; s.y += gh.y; s.z += gh.z; s.w += gh.w;
            ull s01 = pack2(s.x, s.y), s23 = pack2(s.z, s.w);
            #pragma unroll
            for (int w16=0;w16<16;w16++){
                fadd2(s01, scr2[w16*256 + (2*uu  )*32 + lane]);
                fadd2(s23, scr2[w16*256 + (2*uu+1)*32 + lane]);
            }
            float2 g01 = unpack2(s01), g23 = unpack2(s23);
            float c = sigf(g01.y)*c_reg + sigf(g01.x)*tanhf(g23.x);
            float h = sigf(g23.y)*tanhf(c);
            c_reg = c;
            int jj = bx*4 + uu;
            g_hT[wrb][jj*B_ + lane] = h;
            size_t btrow = (size_t)lane*T_ + t;
            __nv_bfloat16 hh = __float2bfloat16(h);
            g_Uhi[btrow*KU + jj] = hh;
            g_Ulo[btrow*KU + jj] = __float2bfloat16(h - __bfloat162float(hh));
        }
        gridbar(++ep);

        // ============ Phase B ============
        if (isC){
            const int kbeg = wid*32;
            float acc[8];
            #pragma unroll
            for (int c=0;c<8;c++) acc[c]=0.f;
            const float* hsrc = g_hT[wrb];
            #pragma unroll 4
            for (int k=kbeg;k<kbeg+32;k++){
                float a = __ldcg(hsrc + k*B_ + lane);
                const float4* wp = (const float4*)(W_C + k*8);
                float4 w0 = wp[0], w1 = wp[1];
                acc[0]+=a*w0.x; acc[1]+=a*w0.y; acc[2]+=a*w0.z; acc[3]+=a*w0.w;
                acc[4]+=a*w1.x; acc[5]+=a*w1.y; acc[6]+=a*w1.z; acc[7]+=a*w1.w;
            }
            #pragma unroll
            for (int c=0;c<8;c++) scr[wid*256 + c*32 + lane] = acc[c];
            __syncthreads();
            if (tid < 256){
                int c = tid >> 5, ln = tid & 31;
                int col = cidx*8 + c;
                if (col < IFACE_){
                    float s = b_iface[col];
                    #pragma unroll
                    for (int w16=0;w16<16;w16++) s += scr[w16*256 + c*32 + ln];
                    g_xiT[col*B_ + ln] = s;
                }
            }
            __syncthreads();
            if (tid == 0){
                __threadfence();
                st_rlx(&g_cflags[cidx*32], (unsigned)(t+1));
            }
        }

        if (bx >= 32 && bx < 96){
            if (t+1 < T_){
                const int g  = wid >> 3;
                const int wk = wid & 7;
                ull acc[8];
                #pragma unroll
                for (int c=0;c<8;c++) acc[c]=0ull;
                const float* hsrc = g_hT[wrb];
                #pragma unroll 4
                for (int k=wk*64; k<wk*64+64; k++){
                    ull as = splat2f(__ldcg(hsrc + k*B_ + lane));
                    const ulonglong2* wp = (const ulonglong2*)(W_B + k*32 + g*16);
                    ulonglong2 w01 = wp[0], w23 = wp[1], w45 = wp[2], w67 = wp[3];
                    ffma2(acc[0], as, w01.x); ffma2(acc[1], as, w01.y);
                    ffma2(acc[2], as, w23.x); ffma2(acc[3], as, w23.y);
                    ffma2(acc[4], as, w45.x); ffma2(acc[5], as, w45.y);
                    ffma2(acc[6], as, w67.x); ffma2(acc[7], as, w67.y);
                }
                #pragma unroll
                for (int c=0;c<8;c++) scr2[g*2048 + wk*256 + c*32 + lane] = acc[c];
                __syncthreads();
                {
                    int cp = tid >> 5;
                    int g2 = cp >> 3, c2 = cp & 7;
                    ull s = scr2[g2*2048 + c2*32 + lane];
                    #pragma unroll
                    for (int w8=1;w8<8;w8++) fadd2(s, scr2[g2*2048 + w8*256 + c2*32 + lane]);
                    float2 v = unpack2(s);
                    int col = (bx-32)*32 + g2*16 + 2*c2;
                    *(float2*)(g_Gh + (size_t)lane*G4H + col) = v;
                }
            }
        } else if (bx < B_){
            if (tid < 64){
                while (ld_rlx(&g_cflags[tid*32]) < (unsigned)(t+1)) { }
            }
            __syncthreads();

            int rk = 0;
            const int dn = tid & 127, dp = tid >> 7;
            for (int i=tid;i<IFACE_;i+=THR) xi[i] = __ldcg(g_xiT + i*B_ + b);
            wrT[tid] = wr_s[((tid&3)<<7) | (tid>>2)];
            __syncthreads();

            // ---- activations + psi/usage (single segment) ----
            if (tid < 64){
                act[8+tid]  = sigf(xi[325+tid]);
                act[72+tid] = xi[389+tid];
            } else if (tid < 68){
                act[tid-64] = 1.f + splusf(xi[256 + (tid-64)]);
            } else if (tid == 68){
                act[4] = 1.f + splusf(xi[324]);
            } else if (tid == 73){
                act[140] = sigf(xi[457]);
            } else if (tid == 74){
                act[141] = sigf(xi[458]);
            } else if (tid >= 75 && tid < 79){
                int r = tid - 75;
                float q0=xi[459+r*3], q1=xi[459+r*3+1], q2=xi[459+r*3+2];
                float m = fmaxf(q0, fmaxf(q1,q2));
                float e0=expf(q0-m), e1=expf(q1-m), e2=expf(q2-m);
                float s = e0+e1+e2;
                act[144+r*3]=e0/s; act[145+r*3]=e1/s; act[146+r*3]=e2/s;
            } else if (tid >= 79 && tid < 83){
                int r = tid - 79; float s = 0.f;
                #pragma unroll 8
                for (int w=0;w<WD_;w++){ float v = xi[r*WD_+w]; s += v*v; }
                act[156+r] = sqrtf(s);
            } else if (tid == 83){
                float s = 0.f;
                #pragma unroll 8
                for (int w=0;w<WD_;w++){ float v = xi[260+w]; s += v*v; }
                act[160] = sqrtf(s);
            } else if (tid >= 256){
                int idx = tid - 256;
                rkT[idx] = xi[((idx&3)<<6) | (idx>>2)];
            }
            if (tid < N_){
                float fg0 = sigf(xi[453]), fg1 = sigf(xi[454]);
                float fg2 = sigf(xi[455]), fg3 = sigf(xi[456]);
                float psi = (1.f - fg0*wr_s[tid])*(1.f - fg1*wr_s[N_+tid])
                          * (1.f - fg2*wr_s[2*N_+tid])*(1.f - fg3*wr_s[3*N_+tid]);
                float uo=u_s[tid], wo=ww_s[tid];
                unew[tid] = (uo + wo - uo*wo)*psi;
            }
            __syncthreads();

            // ---- sort ranks (float2 scans, 4 parts) ----
            {
                float ui = unew[dn];
                int prk = 0;
                const float2* u2 = (const float2*)unew;
                const int j20 = dp*16;
                #pragma unroll 8
                for (int jj=0;jj<16;jj++){
                    float2 v = u2[j20+jj];
                    int j = (j20+jj)*2;
                    prk += (v.x < ui) || (v.x == ui && j < dn);
                    prk += (v.y < ui) || (v.y == ui && (j+1) < dn);
                }
                sortP[dp*128 + dn] = prk;
            }
            __syncthreads();
            if (tid < N_){
                rk = sortP[tid] + sortP[128+tid] + sortP[256+tid] + sortP[384+tid];
                srt[rk] = unew[tid];
            }
            __syncthreads();

            // ---- parallel cumprod + write-content partials ----
            float cp_p = 1.f;
            if (tid < N_){
                int w4 = tid >> 5, ln = tid & 31;
                cp_p = srt[tid];
                #pragma unroll
                for (int off=1;off<32;off<<=1){
                    float o = __shfl_up_sync(0xffffffffu, cp_p, off);
                    if (ln >= off) cp_p *= o;
                }
                if (ln == 31) red[w4] = cp_p;
            }
            __syncthreads();
            if (tid < N_){
                int w4 = tid >> 5;
                float pre = 1.f;
                #pragma unroll
                for (int j=0;j<3;j++) if (j < w4) pre *= red[j];
                incl[tid] = cp_p * pre;
            }
            {
                float s2=0.f, dot=0.f;
                const int w0 = dp*16;
                #pragma unroll
                for (int wp=0; wp<8; wp++){
                    int w = w0 + 2*wp;
                    float2 m2 = *(const float2*)&M_s[dn*MP+w];
                    float2 k2 = *(const float2*)&xi[260+w];
                    s2 += m2.x*m2.x + m2.y*m2.y;
                    dot += m2.x*k2.x + m2.y*k2.y;
                }
                P[dp*128 + dn] = dot;
                P[512 + dp*128 + dn] = s2;
            }
            __syncthreads();

            // ---- alloc weights + write softmax (no max-sub) ----
            float ew = 0.f;
            if (tid < N_){
                float ce = (rk == 0) ? 1.f : incl[rk-1];
                a_s[tid] = (1.f - unew[tid]) * ce;
                float dot = P[tid] + P[128+tid] + P[256+tid] + P[384+tid];
                float s2  = P[512+tid] + P[640+tid] + P[768+tid] + P[896+tid];
                float score = act[4] * (dot / (act[160]*sqrtf(s2) + EPSF));
                ew = expf(score);
                float s = ew;
                #pragma unroll
                for (int o=16;o;o>>=1) s += __shfl_xor_sync(0xffffffffu, s, o);
                if ((tid&31)==0) red[tid>>5] = s;
            }
            __syncthreads();
            float sden = red[0]+red[1]+red[2]+red[3];
            if (tid < N_){
                float wv = act[141]*(act[140]*a_s[tid] + (1.f-act[140])*(ew/sden));
                wwn[tid] = wv;
                float s = wv;
                #pragma unroll
                for (int o=16;o;o>>=1) s += __shfl_xor_sync(0xffffffffu, s, o);
                if ((tid&31)==0) red[4 + (tid>>5)] = s;
            }
            __syncthreads();
            float sumww = red[4]+red[5]+red[6]+red[7];

            // ---- memory write (float2) + link update (float2) ----
            for (int i2=tid; i2<N_*WD_/2; i2+=THR){
                int n = i2>>5, wp = i2&31;
                int w = 2*wp;
                float2 m2 = *(const float2*)&M_s[n*MP+w];
                float wwv = wwn[n];
                float2 er2 = *(const float2*)&act[8+w];
                float2 wv2 = *(const float2*)&act[72+w];
                m2.x = m2.x*(1.f - wwv*er2.x) + wwv*wv2.x;
                m2.y = m2.y*(1.f - wwv*er2.y) + wwv*wv2.y;
                *(float2*)&M_s[n*MP+w] = m2;
            }
            for (int i2=tid; i2<N_*N_/2; i2+=THR){
                int n = i2>>6, mp2 = i2&63;
                int m = 2*mp2;
                float2 l2 = *(const float2*)&L_s[n*LP+m];
                float2 p2 = *(const float2*)&p_s[m];
                float a = 1.f - wwn[n];
                float wn = wwn[n];
                l2.x = (n==m  ) ? 0.f : (a - wwn[m  ])*l2.x + wn*p2.x;
                l2.y = (n==m+1) ? 0.f : (a - wwn[m+1])*l2.y + wn*p2.y;
                *(float2*)&L_s[n*LP+m] = l2;
            }
            __syncthreads();
            if (tid < N_) p_s[tid] = (1.f - sumww)*p_s[tid] + wwn[tid];

            // ---- MERGED fwd/bwd + read-content partials ----
            {
                float f0=0.f,f1=0.f,f2=0.f,f3=0.f, b0=0.f,b1=0.f,b2=0.f,b3=0.f;
                const int m0 = dp*32;
                #pragma unroll 4
                for (int mp2=0; mp2<16; mp2++){
                    int m = m0 + 2*mp2;
                    float2 lr = *(const float2*)&L_s[dn*LP+m];
                    float lc0 = L_s[m*LP+dn], lc1 = L_s[(m+1)*LP+dn];
                    float4 wa = *(const float4*)&wrT[m*4];
                    float4 wb2 = *(const float4*)&wrT[(m+1)*4];
                    f0 += lr.x*wa.x + lr.y*wb2.x; f1 += lr.x*wa.y + lr.y*wb2.y;
                    f2 += lr.x*wa.z + lr.y*wb2.z; f3 += lr.x*wa.w + lr.y*wb2.w;
                    b0 += lc0*wa.x + lc1*wb2.x;   b1 += lc0*wa.y + lc1*wb2.y;
                    b2 += lc0*wa.z + lc1*wb2.z;   b3 += lc0*wa.w + lc1*wb2.w;
                }
                float* fb = P + dp*1024;
                fb[      dn]=f0; fb[128+dn]=f1; fb[256+dn]=f2; fb[384+dn]=f3;
                fb[512+dn]=b0; fb[640+dn]=b1; fb[768+dn]=b2; fb[896+dn]=b3;

                float s2=0.f, d0=0.f,d1=0.f,d2=0.f,d3=0.f;
                const int w0 = dp*16;
                #pragma unroll
                for (int wp=0; wp<8; wp++){
                    int w = w0 + 2*wp;
                    float2 m2 = *(const float2*)&M_s[dn*MP+w];
                    s2 += m2.x*m2.x + m2.y*m2.y;
                    float4 ra = *(const float4*)&rkT[w*4];
                    float4 rb2 = *(const float4*)&rkT[(w+1)*4];
                    d0 += m2.x*ra.x + m2.y*rb2.x; d1 += m2.x*ra.y + m2.y*rb2.y;
                    d2 += m2.x*ra.z + m2.y*rb2.z; d3 += m2.x*ra.w + m2.y*rb2.w;
                }
                float* rc = P + 4096 + dp*640;
                rc[      dn]=d0; rc[128+dn]=d1; rc[256+dn]=d2; rc[384+dn]=d3;
                rc[512+dn]=s2;
            }
            __syncthreads();
            {
                // combine both + exp (no max-sub)
                float fs = P[0*1024 + dp*128 + dn] + P[1*1024 + dp*128 + dn]
                         + P[2*1024 + dp*128 + dn] + P[3*1024 + dp*128 + dn];
                float bs = P[0*1024 + 512 + dp*128 + dn] + P[1*1024 + 512 + dp*128 + dn]
                         + P[2*1024 + 512 + dp*128 + dn] + P[3*1024 + 512 + dp*128 + dn];
                fwdw[dp*128 + dn] = fs;
                bwdw[dp*128 + dn] = bs;
                float d = P[4096 + 0*640 + dp*128 + dn] + P[4096 + 1*640 + dp*128 + dn]
                        + P[4096 + 2*640 + dp*128 + dn] + P[4096 + 3*640 + dp*128 + dn];
                float s2 = P[4096 + 0*640 + 512 + dn] + P[4096 + 1*640 + 512 + dn]
                         + P[4096 + 2*640 + 512 + dn] + P[4096 + 3*640 + 512 + dn];
                float mn = sqrtf(s2);
                float raw = act[dp]*(d/(act[156+dp]*mn + EPSF));
                crs[dp*128 + dn] = expf(raw);
            }
            __syncthreads();
            if (tid < 128){
                int r = tid>>5, ln = tid&31;
                float s = crs[r*N_+ln] + crs[r*N_+ln+32] + crs[r*N_+ln+64] + crs[r*N_+ln+96];
                #pragma unroll
                for (int o=16;o;o>>=1) s += __shfl_xor_sync(0xffffffffu, s, o);
                if (ln==0) act[168+r]=s;
            }
            __syncthreads();
            {
                int i = dp*128 + dn;
                float w = act[144+dp*3]*bwdw[i] + act[145+dp*3]*(crs[i]/act[168+dp]) + act[146+dp*3]*fwdw[i];
                crs[i] = w;
                crsT[dn*4 + dp] = w;
            }
            __syncthreads();
            // ---- rv partials ----
            {
                int w = tid & 63, part = tid >> 6;
                float s0=0.f,s1=0.f,s2v=0.f,s3=0.f;
                const int n0 = part*16;
                #pragma unroll
                for (int n=n0;n<n0+16;n++){
                    float mv = M_s[n*MP+w];
                    float4 c4 = *(const float4*)(crsT + n*4);
                    s0 += c4.x*mv; s1 += c4.y*mv; s2v += c4.z*mv; s3 += c4.w*mv;
                }
                float* rv = P + part*256;
                rv[      w]=s0; rv[ 64+w]=s1; rv[128+w]=s2v; rv[192+w]=s3;
            }
            __syncthreads();
            if (tid < 256){
                int r = tid >> 6, w = tid & 63;
                float s = 0.f;
                #pragma unroll
                for (int part=0;part<8;part++) s += P[part*256 + r*64 + w];
                int idx = r*WD_ + w;
                g_rvT[idx*B_ + b] = s;
                size_t btrow = (size_t)b*T_ + t;
                __nv_bfloat16 sh = __float2bfloat16(s);
                g_Uhi[btrow*KU + H_ + idx] = sh;
                g_Ulo[btrow*KU + H_ + idx] = __float2bfloat16(s - __bfloat162float(sh));
            }
            __syncthreads();
            wr_s[tid] = crs[tid];
            if (tid < N_){ u_s[tid]=unew[tid]; ww_s[tid]=wwn[tid]; }
        }
        gridbar(++ep);
    }
}

// ---------------- launcher ----------------
extern "C" void kernel_launch(void* const* d_in, const int* in_sizes, int n_in,
                              void* d_out, int out_size){
    const int*   tokens  = (const int*)  d_in[0];
    const float* emb     = (const float*)d_in[1];
    const float* w_ih    = (const float*)d_in[2];
    const float* w_hh    = (const float*)d_in[3];
    const float* b_lstm  = (const float*)d_in[4];
    const float* W_iface = (const float*)d_in[5];
    const float* b_iface = (const float*)d_in[6];
    const float* W_out   = (const float*)d_in[7];
    const float* b_out   = (const float*)d_in[8];
    float* out = (float*)d_out;

    const int loop_smem = LOOP_SMEM_FLOATS * (int)sizeof(float);
    cudaFuncSetAttribute(loop_kernel, cudaFuncAttributeMaxDynamicSharedMemorySize, loop_smem);
    const int gout_smem = 8 * TILE_BF * (int)sizeof(__nv_bfloat16);
    cudaFuncSetAttribute(gemm_out, cudaFuncAttributeMaxDynamicSharedMemorySize, gout_smem);

    void *pX, *pG0, *pWihT, *pBl;
    cudaGetSymbolAddress(&pX, g_X);
    cudaGetSymbolAddress(&pG0, g_G0);
    cudaGetSymbolAddress(&pWihT, g_WihT);
    cudaGetSymbolAddress(&pBl, g_bl);

    embed_kernel<<<(BT_*E_ + 255)/256, 256>>>(tokens, emb);
    prep_w<<<(KU*G4H + 255)/256, 256>>>(w_ih, w_hh, b_lstm);
    sgemm128<<<dim3(G4H/128, BT_/128), 256>>>((const float*)pX, (const float*)pWihT,
                                              (const float*)pBl, (float*)pG0, BT_, G4H, E_);
    loop_kernel<<<NBLK, THR, loop_smem>>>(W_iface, b_iface);
    prep_outT<<<dim3(VPAD/32, KU/32), dim3(32,8)>>>(W_out);
    gemm_out<<<dim3((V_+127)/128, BT_/128), 256, gout_smem>>>(b_out, out);
}

// round 13
// speedup vs baseline: 3.0059x; 1.0725x over previous
#include <cuda_runtime.h>
#include <cuda_bf16.h>
#include <math.h>

#define B_ 32
#define T_ 256
#define V_ 10000
#define VPAD 10112
#define E_ 256
#define H_ 512
#define N_ 128
#define WD_ 64
#define R_ 4
#define IFACE_ 471
#define G4H 2048          // 4*H
#define KU 768            // H + R*WD
#define BT_ (B_*T_)       // 8192
#define EPSF 1e-6f
#define NBLK 128
#define THR 512
#define MP 66             // M row pitch
#define LP 130            // L row pitch

typedef unsigned long long ull;

// ---------------- f32x2 helpers ----------------
__device__ __forceinline__ ull pack2(float x, float y){
    ull r; asm("mov.b64 %0, {%1,%2};" : "=l"(r) : "r"(__float_as_uint(x)), "r"(__float_as_uint(y))); return r;
}
__device__ __forceinline__ ull splat2f(float x){ return pack2(x, x); }
__device__ __forceinline__ float2 unpack2(ull v){
    unsigned lo, hi;
    asm("mov.b64 {%0,%1}, %2;" : "=r"(lo), "=r"(hi) : "l"(v));
    return make_float2(__uint_as_float(lo), __uint_as_float(hi));
}
__device__ __forceinline__ void ffma2(ull& d, ull a, ull b){
    asm("fma.rn.f32x2 %0, %1, %2, %0;" : "+l"(d) : "l"(a), "l"(b));
}
__device__ __forceinline__ void fadd2(ull& d, ull a){
    asm("add.rn.f32x2 %0, %0, %1;" : "+l"(d) : "l"(a));
}
__device__ __forceinline__ void cpasync16(unsigned dst, const void* src){
    asm volatile("cp.async.cg.shared.global [%0], [%1], 16;" :: "r"(dst), "l"(src));
}
#define NBAR(id, cnt) asm volatile("bar.sync %0, %1;" :: "r"(id), "r"(cnt) : "memory")

// ---------------- GPU-scope relaxed flag ops ----------------
__device__ __forceinline__ unsigned ld_rlx(const unsigned* p){
    unsigned v;
    asm volatile("ld.relaxed.gpu.global.u32 %0, [%1];" : "=r"(v) : "l"(p) : "memory");
    return v;
}
__device__ __forceinline__ void st_rlx(unsigned* p, unsigned v){
    asm volatile("st.relaxed.gpu.global.u32 [%0], %1;" :: "l"(p), "r"(v) : "memory");
}

// ---------------- device scratch ----------------
__device__ __align__(128) float g_X[BT_*E_];
__device__ __align__(128) float g_G0[(size_t)BT_*G4H];
__device__ __align__(128) float g_WihT[E_*G4H];
__device__ __align__(128) float g_Wt[KU*G4H];
__device__ __align__(128) float g_bl[G4H];
__device__ __align__(128) __nv_bfloat16 g_WhiT[(size_t)VPAD*KU];
__device__ __align__(128) __nv_bfloat16 g_WloT[(size_t)VPAD*KU];
__device__ __align__(128) __nv_bfloat16 g_Uhi[(size_t)BT_*KU];
__device__ __align__(128) __nv_bfloat16 g_Ulo[(size_t)BT_*KU];
__device__ __align__(128) float g_hT[2][H_*B_];
__device__ __align__(128) float g_rvT[R_*WD_*B_];
__device__ __align__(128) float g_xiT[IFACE_*B_];
__device__ __align__(128) float g_Gh[B_*G4H];
__device__ __align__(128) unsigned g_flags[NBLK*32];
__device__ __align__(128) unsigned g_cflags[64*32];
__device__ unsigned g_gen;

__device__ __forceinline__ float sigf(float x){ return 1.f/(1.f + expf(-x)); }
__device__ __forceinline__ float splusf(float x){ return fmaxf(x,0.f) + log1pf(expf(-fabsf(x))); }

// ---------------- all-to-all single-hop grid barrier ----------------
__device__ __forceinline__ void gridbar(unsigned ep){
    __syncthreads();
    if (threadIdx.x == 0){
        __threadfence();
        st_rlx(&g_flags[blockIdx.x*32], ep);
    }
    if (threadIdx.x < NBLK){
        while (ld_rlx(&g_flags[threadIdx.x*32]) < ep) { }
    }
    __syncthreads();
}

// ---------------- prep kernels ----------------
__global__ void embed_kernel(const int* __restrict__ tok, const float* __restrict__ emb){
    int i = blockIdx.x*256 + threadIdx.x;
    if (i >= BT_*E_) return;
    int bt = i / E_, e = i % E_;
    g_X[i] = tanhf(emb[(size_t)tok[bt]*E_ + e]);
}

__global__ void prep_w(const float* __restrict__ w_ih, const float* __restrict__ w_hh,
                       const float* __restrict__ b_lstm){
    int i = blockIdx.x*256 + threadIdx.x;
    if (i < KU*G4H){
        int k = i >> 11, col = i & 2047;
        int jj = col >> 2, g = col & 3;
        int j = g*H_ + jj;
        g_Wt[i] = (k < R_*WD_) ? w_ih[(size_t)j*(E_+R_*WD_) + E_ + k]
                               : w_hh[(size_t)j*H_ + (k - R_*WD_)];
    }
    if (i < E_*G4H){
        int e = i >> 11, col = i & 2047;
        int jj = col >> 2, g = col & 3;
        int j = g*H_ + jj;
        g_WihT[i] = w_ih[(size_t)j*(E_+R_*WD_) + e];
    }
    if (i < G4H){
        int jj = i >> 2, g = i & 3;
        g_bl[i] = b_lstm[g*H_ + jj];
    }
    if (i < 2*H_*B_) ((float*)g_hT)[i] = 0.f;
    if (i < R_*WD_*B_) g_rvT[i] = 0.f;
    if (i < B_*G4H) g_Gh[i] = 0.f;
    if (i < NBLK*32) g_flags[i] = 0u;
    if (i < 64*32) g_cflags[i] = 0u;
    if (i == 0) g_gen = 0u;
}

__global__ void prep_outT(const float* __restrict__ W_out){
    __shared__ float tile[32][33];
    int n0 = blockIdx.x*32, k0 = blockIdx.y*32;
    int tx = threadIdx.x, ty = threadIdx.y;
    #pragma unroll
    for (int dy=0;dy<32;dy+=8){
        int k = k0+ty+dy, n = n0+tx;
        tile[ty+dy][tx] = (n < V_) ? W_out[(size_t)k*V_+n] : 0.f;
    }
    __syncthreads();
    #pragma unroll
    for (int dy=0;dy<32;dy+=8){
        int n = n0+ty+dy, k = k0+tx;
        float v = tile[tx][ty+dy];
        __nv_bfloat16 h = __float2bfloat16(v);
        g_WhiT[(size_t)n*KU+k] = h;
        g_WloT[(size_t)n*KU+k] = __float2bfloat16(v - __bfloat162float(h));
    }
}

// ---------------- pipelined fp32 SGEMM: C = A(MxK)@B(KxN) (+bias) ----------------
__global__ __launch_bounds__(256) void sgemm128(const float* __restrict__ A,
                         const float* __restrict__ Bm,
                         const float* __restrict__ bias, float* __restrict__ C,
                         int M, int Nn, int K){
    __shared__ float As[2][8][128];
    __shared__ float Bs[2][8][128];
    int tid = threadIdx.x;
    int row0 = blockIdx.y*128, col0 = blockIdx.x*128;
    int trow = (tid >> 4) * 8;
    int tcol = (tid & 15) * 8;
    float acc[8][8];
    #pragma unroll
    for (int i=0;i<8;i++)
        #pragma unroll
        for (int j=0;j<8;j++) acc[i][j]=0.f;

    int arow = tid >> 1, ak = (tid & 1)*4;
    int bk = tid >> 5,  bn = (tid & 31)*4;
    const float* Aptr = A + (size_t)(row0 + arow)*K + ak;
    int gn = col0 + bn;

    float4 av = *(const float4*)(Aptr);
    float4 bv = make_float4(0.f,0.f,0.f,0.f);
    if (gn < Nn) bv = *(const float4*)(Bm + (size_t)bk*Nn + gn);
    As[0][ak+0][arow]=av.x; As[0][ak+1][arow]=av.y; As[0][ak+2][arow]=av.z; As[0][ak+3][arow]=av.w;
    *(float4*)(&Bs[0][bk][bn]) = bv;
    __syncthreads();

    int buf = 0;
    for (int k0=0;k0<K;k0+=8){
        bool more = (k0 + 8) < K;
        if (more){
            av = *(const float4*)(Aptr + k0 + 8);
            bv = make_float4(0.f,0.f,0.f,0.f);
            if (gn < Nn) bv = *(const float4*)(Bm + (size_t)(k0+8+bk)*Nn + gn);
        }
        #pragma unroll
        for (int kk=0;kk<8;kk++){
            float ar[8], br[8];
            *(float4*)(ar)   = *(const float4*)(&As[buf][kk][trow]);
            *(float4*)(ar+4) = *(const float4*)(&As[buf][kk][trow+4]);
            *(float4*)(br)   = *(const float4*)(&Bs[buf][kk][tcol]);
            *(float4*)(br+4) = *(const float4*)(&Bs[buf][kk][tcol+4]);
            #pragma unroll
            for (int i=0;i<8;i++)
                #pragma unroll
                for (int j=0;j<8;j++) acc[i][j] += ar[i]*br[j];
        }
        if (more){
            int nb = buf ^ 1;
            As[nb][ak+0][arow]=av.x; As[nb][ak+1][arow]=av.y; As[nb][ak+2][arow]=av.z; As[nb][ak+3][arow]=av.w;
            *(float4*)(&Bs[nb][bk][bn]) = bv;
            __syncthreads();
            buf = nb;
        }
    }
    #pragma unroll
    for (int i=0;i<8;i++){
        size_t gm = (size_t)(row0 + trow + i);
        #pragma unroll
        for (int j=0;j<8;j+=4){
            int gnn = col0 + tcol + j;
            if (gnn < Nn){
                float4 v = make_float4(acc[i][j],acc[i][j+1],acc[i][j+2],acc[i][j+3]);
                if (bias){ v.x+=bias[gnn]; v.y+=bias[gnn+1]; v.z+=bias[gnn+2]; v.w+=bias[gnn+3]; }
                *(float4*)(C + gm*Nn + gnn) = v;
            }
        }
    }
}

// ---------------- bf16-split tensor-core GEMM: out = U@W_out + b ----------------
#define PITCH 40
#define TILE_BF (128*PITCH)

__device__ __forceinline__ void mma_bf16(float* c, unsigned a0,unsigned a1,unsigned a2,unsigned a3,
                                         unsigned b0, unsigned b1){
    asm volatile("mma.sync.aligned.m16n8k16.row.col.f32.bf16.bf16.f32 "
        "{%0,%1,%2,%3}, {%4,%5,%6,%7}, {%8,%9}, {%0,%1,%2,%3};"
        : "+f"(c[0]),"+f"(c[1]),"+f"(c[2]),"+f"(c[3])
        : "r"(a0),"r"(a1),"r"(a2),"r"(a3),"r"(b0),"r"(b1));
}

__global__ __launch_bounds__(256) void gemm_out(const float* __restrict__ bias,
                                                float* __restrict__ C){
    extern __shared__ __align__(16) char smraw[];
    __nv_bfloat16* AsHi = (__nv_bfloat16*)smraw;
    __nv_bfloat16* AsLo = AsHi + 2*TILE_BF;
    __nv_bfloat16* BsHi = AsLo + 2*TILE_BF;
    __nv_bfloat16* BsLo = BsHi + 2*TILE_BF;

    const int tid = threadIdx.x, lane = tid & 31, wid = tid >> 5;
    const int warp_m = wid >> 2, warp_n = wid & 3;
    const int gid = lane >> 2, tig = lane & 3;
    const int m0 = blockIdx.y*128, n0 = blockIdx.x*128;

    float acc[4][4][4];
    #pragma unroll
    for (int i=0;i<4;i++)
        #pragma unroll
        for (int j=0;j<4;j++)
            #pragma unroll
            for (int q=0;q<4;q++) acc[i][j][q]=0.f;

    unsigned sAhi = (unsigned)__cvta_generic_to_shared(AsHi);
    unsigned sAlo = (unsigned)__cvta_generic_to_shared(AsLo);
    unsigned sBhi = (unsigned)__cvta_generic_to_shared(BsHi);
    unsigned sBlo = (unsigned)__cvta_generic_to_shared(BsLo);

    auto loadA = [&](int s, int kt){
        #pragma unroll
        for (int it=0; it<2; it++){
            int idx = it*256 + tid;
            int row = idx>>2, seg = idx&3;
            size_t goff = (size_t)(m0+row)*KU + kt*32 + seg*8;
            unsigned doff = (unsigned)((s*TILE_BF + row*PITCH + seg*8)*2);
            cpasync16(sAhi + doff, g_Uhi + goff);
            cpasync16(sAlo + doff, g_Ulo + goff);
        }
    };
    auto loadB = [&](int s, int kt){
        #pragma unroll
        for (int it=0; it<2; it++){
            int idx = it*256 + tid;
            int row = idx>>2, seg = idx&3;
            size_t goff = (size_t)(n0+row)*KU + kt*32 + seg*8;
            unsigned doff = (unsigned)((s*TILE_BF + row*PITCH + seg*8)*2);
            cpasync16(sBhi + doff, g_WhiT + goff);
            cpasync16(sBlo + doff, g_WloT + goff);
        }
    };
    auto compute = [&](int s){
        #pragma unroll
        for (int kk=0;kk<2;kk++){
            const int kb = kk*16 + tig*2;
            unsigned bh[4][2], bl[4][2];
            #pragma unroll
            for (int j=0;j<4;j++){
                int nl = warp_n*32 + j*8 + gid;
                const __nv_bfloat16* bp  = BsHi + s*TILE_BF + nl*PITCH + kb;
                const __nv_bfloat16* bp2 = BsLo + s*TILE_BF + nl*PITCH + kb;
                bh[j][0] = *(const unsigned*)bp;   bh[j][1] = *(const unsigned*)(bp+8);
                bl[j][0] = *(const unsigned*)bp2;  bl[j][1] = *(const unsigned*)(bp2+8);
            }
            #pragma unroll
            for (int i=0;i<4;i++){
                int mr = warp_m*64 + i*16;
                const __nv_bfloat16* ap  = AsHi + s*TILE_BF + (mr+gid)*PITCH + kb;
                const __nv_bfloat16* ap2 = AsLo + s*TILE_BF + (mr+gid)*PITCH + kb;
                unsigned ah0 = *(const unsigned*)ap;
                unsigned ah1 = *(const unsigned*)(ap + 8*PITCH);
                unsigned ah2 = *(const unsigned*)(ap + 8);
                unsigned ah3 = *(const unsigned*)(ap + 8*PITCH + 8);
                unsigned al0 = *(const unsigned*)ap2;
                unsigned al1 = *(const unsigned*)(ap2 + 8*PITCH);
                unsigned al2 = *(const unsigned*)(ap2 + 8);
                unsigned al3 = *(const unsigned*)(ap2 + 8*PITCH + 8);
                #pragma unroll
                for (int j=0;j<4;j++){
                    mma_bf16(acc[i][j], ah0,ah1,ah2,ah3, bh[j][0],bh[j][1]);
                    mma_bf16(acc[i][j], ah0,ah1,ah2,ah3, bl[j][0],bl[j][1]);
                    mma_bf16(acc[i][j], al0,al1,al2,al3, bh[j][0],bh[j][1]);
                }
            }
        }
    };

    loadA(0, 0); loadB(0, 0);
    asm volatile("cp.async.commit_group;");
    asm volatile("cp.async.wait_group 0;");
    __syncthreads();

    const int KT = KU/32;
    for (int kt=0; kt<KT; kt++){
        int buf = kt & 1;
        if (kt+1 < KT){
            loadA(buf^1, kt+1);
            loadB(buf^1, kt+1);
            asm volatile("cp.async.commit_group;");
        }
        compute(buf);
        if (kt+1 < KT){
            asm volatile("cp.async.wait_group 0;");
        }
        __syncthreads();
    }

    #pragma unroll
    for (int i=0;i<4;i++){
        int gm = m0 + warp_m*64 + i*16 + gid;
        #pragma unroll
        for (int j=0;j<4;j++){
            int gn = n0 + warp_n*32 + j*8 + tig*2;
            if (gn < V_){
                float b0 = bias[gn], b1 = bias[gn+1];
                *(float2*)(C + (size_t)gm*V_ + gn) = make_float2(acc[i][j][0]+b0, acc[i][j][1]+b1);
                *(float2*)(C + (size_t)(gm+8)*V_ + gn) = make_float2(acc[i][j][2]+b0, acc[i][j][3]+b1);
            }
        }
    }
}

// ---------------- persistent sequential loop ----------------
#define LOOP_SMEM_FLOATS (16384 + 28936)

__global__ __launch_bounds__(THR) void loop_kernel(const float* __restrict__ W_iface,
                                                   const float* __restrict__ b_iface){
    extern __shared__ float sm[];
    float* W_A  = sm;                  // 256*16
    float* W_C  = W_A + 4096;          // 512*8
    float* scr  = W_C + 4096;          // 8192
    float* M_s  = scr + 8192;          // 128*66
    float* L_s  = M_s + 128*MP;        // 128*130
    float* wr_s = L_s + 128*LP;        // 512
    float* u_s  = wr_s + 512;          // 128
    float* p_s  = u_s + 128;           // 128
    float* ww_s = p_s + 128;           // 128
    float* xi   = ww_s + 128;          // 472
    float* fwdw = xi + 472;            // 512
    float* bwdw = fwdw + 512;          // 512
    float* crs  = bwdw + 512;          // 512
    float* unew = crs + 512;           // 128
    float* srt  = unew + 128;          // 128
    float* incl = srt + 128;           // 128
    float* a_s  = incl + 128;          // 128
    float* wwn  = a_s + 128;           // 128
    float* red  = wwn + 128;           // 128
    float* act  = red + 128;           // 176
    // scr carve-outs (phase D)
    float* wrT  = scr;                 // [0,512)
    float* crsT = scr + 512;           // [512,1024)
    float* rkT  = scr + 1024;          // [1024,1280)
    float* P    = scr + 1280;          // [1280,8192)
    float* W_B  = M_s;                 // helpers overlay: 512*32

    const int tid  = threadIdx.x;
    const int bx   = blockIdx.x;
    const int wid  = tid >> 5;
    const int lane = tid & 31;
    const int b    = bx;
    const bool isC = (bx < 32) || (bx >= 96);
    const int cidx = (bx < 32) ? bx : bx - 64;

    for (int i=tid;i<256*16;i+=THR){
        int k = i >> 4, c = i & 15;
        W_A[i] = g_Wt[(size_t)k*G4H + bx*16 + c];
    }
    if (isC){
        for (int i=tid;i<512*8;i+=THR){
            int k = i >> 3, c = i & 7;
            int col = cidx*8 + c;
            W_C[i] = (col < IFACE_) ? W_iface[(size_t)k*IFACE_ + col] : 0.f;
        }
    }
    if (bx < B_){
        for (int i=tid;i<128*MP;i+=THR)  M_s[i]=0.f;
        for (int i=tid;i<128*LP;i+=THR)  L_s[i]=0.f;
        for (int i=tid;i<512;i+=THR)     wr_s[i]=0.f;
        if (tid < N_){ u_s[tid]=0.f; p_s[tid]=0.f; ww_s[tid]=0.f; }
    } else if (bx < 96){
        for (int i=tid;i<512*32;i+=THR){
            int k = i >> 5, c = i & 31;
            W_B[i] = g_Wt[(size_t)(256+k)*G4H + (bx-32)*32 + c];
        }
    }
    __syncthreads();

    float c_reg = 0.f;
    unsigned ep = 0;
    ull* scr2 = (ull*)scr;

    for (int t=0;t<T_;t++){
        const int rd = t & 1, wrb = rd ^ 1;

        // ============ Phase A: gates = G0 + Gh + Wrv@rv ============
        // prefetch G0/Gh early (long-latency), batch rv loads
        float4 sG = make_float4(0,0,0,0), gH = make_float4(0,0,0,0);
        if (tid < 128){
            int uu = tid >> 5;
            sG = *(const float4*)(g_G0 + ((size_t)lane*T_ + t)*G4H + bx*16 + uu*4);
            gH = __ldcg((const float4*)(g_Gh + (size_t)lane*G4H + bx*16 + uu*4));
        }
        {
            const int kbeg = wid*16;
            float rv[16];
            #pragma unroll
            for (int k=0;k<16;k++) rv[k] = __ldcg(g_rvT + (kbeg+k)*B_ + lane);
            ull acc2[8];
            #pragma unroll
            for (int c=0;c<8;c++) acc2[c]=0ull;
            #pragma unroll
            for (int k=0;k<16;k++){
                ull as = splat2f(rv[k]);
                const ulonglong2* wp = (const ulonglong2*)(W_A + (kbeg+k)*16);
                ulonglong2 w01 = wp[0], w23 = wp[1], w45 = wp[2], w67 = wp[3];
                ffma2(acc2[0], as, w01.x); ffma2(acc2[1], as, w01.y);
                ffma2(acc2[2], as, w23.x); ffma2(acc2[3], as, w23.y);
                ffma2(acc2[4], as, w45.x); ffma2(acc2[5], as, w45.y);
                ffma2(acc2[6], as, w67.x); ffma2(acc2[7], as, w67.y);
            }
            #pragma unroll
            for (int c=0;c<8;c++) scr2[wid*256 + c*32 + lane] = acc2[c];
        }
        __syncthreads();
        if (tid < 128){
            int uu = tid >> 5;
            sG.x += gH.x; sG.y += gH.y; sG.z += gH.z; sG.w += gH.w;
            ull s01 = pack2(sG.x, sG.y), s23 = pack2(sG.z, sG.w);
            #pragma unroll
            for (int w16=0;w16<16;w16++){
                fadd2(s01, scr2[w16*256 + (2*uu  )*32 + lane]);
                fadd2(s23, scr2[w16*256 + (2*uu+1)*32 + lane]);
            }
            float2 g01 = unpack2(s01), g23 = unpack2(s23);
            float c = sigf(g01.y)*c_reg + sigf(g01.x)*tanhf(g23.x);
            float h = sigf(g23.y)*tanhf(c);
            c_reg = c;
            int jj = bx*4 + uu;
            g_hT[wrb][jj*B_ + lane] = h;
            size_t btrow = (size_t)lane*T_ + t;
            __nv_bfloat16 hh = __float2bfloat16(h);
            g_Uhi[btrow*KU + jj] = hh;
            g_Ulo[btrow*KU + jj] = __float2bfloat16(h - __bfloat162float(hh));
        }
        gridbar(++ep);

        // ============ Phase B ============
        if (isC){
            const int kbeg = wid*32;
            const float* hsrc = g_hT[wrb];
            float acc[8];
            #pragma unroll
            for (int c=0;c<8;c++) acc[c]=0.f;
            #pragma unroll
            for (int ch=0; ch<2; ch++){
                float hreg[16];
                #pragma unroll
                for (int k=0;k<16;k++) hreg[k] = __ldcg(hsrc + (kbeg+ch*16+k)*B_ + lane);
                #pragma unroll
                for (int k=0;k<16;k++){
                    float a = hreg[k];
                    const float4* wp = (const float4*)(W_C + (kbeg+ch*16+k)*8);
                    float4 w0 = wp[0], w1 = wp[1];
                    acc[0]+=a*w0.x; acc[1]+=a*w0.y; acc[2]+=a*w0.z; acc[3]+=a*w0.w;
                    acc[4]+=a*w1.x; acc[5]+=a*w1.y; acc[6]+=a*w1.z; acc[7]+=a*w1.w;
                }
            }
            #pragma unroll
            for (int c=0;c<8;c++) scr[wid*256 + c*32 + lane] = acc[c];
            __syncthreads();
            if (tid < 256){
                int c = tid >> 5, ln = tid & 31;
                int col = cidx*8 + c;
                if (col < IFACE_){
                    float s = b_iface[col];
                    #pragma unroll
                    for (int w16=0;w16<16;w16++) s += scr[w16*256 + c*32 + ln];
                    g_xiT[col*B_ + ln] = s;
                }
            }
            __syncthreads();
            if (tid == 0){
                __threadfence();
                st_rlx(&g_cflags[cidx*32], (unsigned)(t+1));
            }
        }

        if (bx >= 32 && bx < 96){
            if (t+1 < T_){
                const int g  = wid >> 3;
                const int wk = wid & 7;
                ull acc[8];
                #pragma unroll
                for (int c=0;c<8;c++) acc[c]=0ull;
                const float* hsrc = g_hT[wrb];
                #pragma unroll
                for (int ch=0; ch<4; ch++){
                    float hreg[16];
                    #pragma unroll
                    for (int k=0;k<16;k++) hreg[k] = __ldcg(hsrc + (wk*64+ch*16+k)*B_ + lane);
                    #pragma unroll
                    for (int k=0;k<16;k++){
                        ull as = splat2f(hreg[k]);
                        const ulonglong2* wp = (const ulonglong2*)(W_B + (wk*64+ch*16+k)*32 + g*16);
                        ulonglong2 w01 = wp[0], w23 = wp[1], w45 = wp[2], w67 = wp[3];
                        ffma2(acc[0], as, w01.x); ffma2(acc[1], as, w01.y);
                        ffma2(acc[2], as, w23.x); ffma2(acc[3], as, w23.y);
                        ffma2(acc[4], as, w45.x); ffma2(acc[5], as, w45.y);
                        ffma2(acc[6], as, w67.x); ffma2(acc[7], as, w67.y);
                    }
                }
                #pragma unroll
                for (int c=0;c<8;c++) scr2[g*2048 + wk*256 + c*32 + lane] = acc[c];
                __syncthreads();
                {
                    int cp = tid >> 5;
                    int g2 = cp >> 3, c2 = cp & 7;
                    ull s = scr2[g2*2048 + c2*32 + lane];
                    #pragma unroll
                    for (int w8=1;w8<8;w8++) fadd2(s, scr2[g2*2048 + w8*256 + c2*32 + lane]);
                    float2 v = unpack2(s);
                    int col = (bx-32)*32 + g2*16 + 2*c2;
                    *(float2*)(g_Gh + (size_t)lane*G4H + col) = v;
                }
            }
        } else if (bx < B_){
            if (tid < 64){
                while (ld_rlx(&g_cflags[tid*32]) < (unsigned)(t+1)) { }
            }
            __syncthreads();

            const int dn = tid & 127, dp = tid >> 7;
            for (int i=tid;i<IFACE_;i+=THR) xi[i] = __ldcg(g_xiT + i*B_ + b);
            wrT[tid] = wr_s[((tid&3)<<7) | (tid>>2)];
            __syncthreads();

            // ---- activations + psi/usage (single segment) ----
            if (tid < 64){
                act[8+tid]  = sigf(xi[325+tid]);
                act[72+tid] = xi[389+tid];
            } else if (tid < 68){
                act[tid-64] = 1.f + splusf(xi[256 + (tid-64)]);
            } else if (tid == 68){
                act[4] = 1.f + splusf(xi[324]);
            } else if (tid == 73){
                act[140] = sigf(xi[457]);
            } else if (tid == 74){
                act[141] = sigf(xi[458]);
            } else if (tid >= 75 && tid < 79){
                int r = tid - 75;
                float q0=xi[459+r*3], q1=xi[459+r*3+1], q2=xi[459+r*3+2];
                float m = fmaxf(q0, fmaxf(q1,q2));
                float e0=expf(q0-m), e1=expf(q1-m), e2=expf(q2-m);
                float s = e0+e1+e2;
                act[144+r*3]=e0/s; act[145+r*3]=e1/s; act[146+r*3]=e2/s;
            } else if (tid >= 79 && tid < 83){
                int r = tid - 79; float s = 0.f;
                #pragma unroll 8
                for (int w=0;w<WD_;w++){ float v = xi[r*WD_+w]; s += v*v; }
                act[156+r] = sqrtf(s);
            } else if (tid == 83){
                float s = 0.f;
                #pragma unroll 8
                for (int w=0;w<WD_;w++){ float v = xi[260+w]; s += v*v; }
                act[160] = sqrtf(s);
            } else if (tid >= 256){
                int idx = tid - 256;
                rkT[idx] = xi[((idx&3)<<6) | (idx>>2)];
            }
            if (tid < N_){
                float fg0 = sigf(xi[453]), fg1 = sigf(xi[454]);
                float fg2 = sigf(xi[455]), fg3 = sigf(xi[456]);
                float psi = (1.f - fg0*wr_s[tid])*(1.f - fg1*wr_s[N_+tid])
                          * (1.f - fg2*wr_s[2*N_+tid])*(1.f - fg3*wr_s[3*N_+tid]);
                float uo=u_s[tid], wo=ww_s[tid];
                unew[tid] = (uo + wo - uo*wo)*psi;
            }
            __syncthreads();

            // ===== WARP-SPECIALIZED: chain X (warps 0-3) || chain Y (warps 8-15) =====
            int rk = 0;
            if (tid < 128){
                // ---- X: sort ranks (full scan) ----
                float ui = unew[tid];
                const float2* u2 = (const float2*)unew;
                #pragma unroll 8
                for (int jj=0;jj<64;jj++){
                    float2 v = u2[jj];
                    int j = jj*2;
                    rk += (v.x < ui) || (v.x == ui && j < tid);
                    rk += (v.y < ui) || (v.y == ui && (j+1) < tid);
                }
                srt[rk] = ui;
                NBAR(1, 128);
                // ---- X: cumprod scan ----
                int w4 = tid >> 5, ln = tid & 31;
                float cp_p = srt[tid];
                #pragma unroll
                for (int off=1;off<32;off<<=1){
                    float o = __shfl_up_sync(0xffffffffu, cp_p, off);
                    if (ln >= off) cp_p *= o;
                }
                if (ln == 31) red[w4] = cp_p;
                NBAR(1, 128);
                float pre = 1.f;
                #pragma unroll
                for (int j=0;j<3;j++) if (j < w4) pre *= red[j];
                incl[tid] = cp_p * pre;
                NBAR(1, 128);
                float ce = (rk == 0) ? 1.f : incl[rk-1];
                a_s[tid] = (1.f - unew[tid]) * ce;
            } else if (tid >= 256){
                // ---- Y: write-content scores (old M) ----
                int yidx = tid - 256;
                int yn = yidx & 127, yp = yidx >> 7;
                float s2=0.f, dot=0.f;
                const int w0 = yp*32;
                #pragma unroll
                for (int wp=0; wp<16; wp++){
                    int w = w0 + 2*wp;
                    float2 m2 = *(const float2*)&M_s[yn*MP+w];
                    float2 k2 = *(const float2*)&xi[260+w];
                    s2 += m2.x*m2.x + m2.y*m2.y;
                    dot += m2.x*k2.x + m2.y*k2.y;
                }
                P[yp*128 + yn] = dot;
                P[256 + yp*128 + yn] = s2;
                NBAR(2, 256);
                if (yp == 0){
                    float d = P[yn] + P[128+yn];
                    float ss = P[256+yn] + P[384+yn];
                    float score = act[4] * (d / (act[160]*sqrtf(ss) + EPSF));
                    float ew = expf(score);
                    crs[yn] = ew;               // ewbuf
                    float s = ew;
                    #pragma unroll
                    for (int o=16;o;o>>=1) s += __shfl_xor_sync(0xffffffffu, s, o);
                    if ((yn&31)==0) red[8 + (yn>>5)] = s;
                }
            }
            __syncthreads();   // join

            // ---- wwn (needs a_s, crs=ew, sden) ----
            float sden = red[8]+red[9]+red[10]+red[11];
            if (tid < N_){
                float wv = act[141]*(act[140]*a_s[tid] + (1.f-act[140])*(crs[tid]/sden));
                wwn[tid] = wv;
                float s = wv;
                #pragma unroll
                for (int o=16;o;o>>=1) s += __shfl_xor_sync(0xffffffffu, s, o);
                if ((tid&31)==0) red[4 + (tid>>5)] = s;
            }
            __syncthreads();
            float sumww = red[4]+red[5]+red[6]+red[7];

            // ---- memory write + link update (float2) ----
            for (int i2=tid; i2<N_*WD_/2; i2+=THR){
                int n = i2>>5, wp = i2&31;
                int w = 2*wp;
                float2 m2 = *(const float2*)&M_s[n*MP+w];
                float wwv = wwn[n];
                float2 er2 = *(const float2*)&act[8+w];
                float2 wv2 = *(const float2*)&act[72+w];
                m2.x = m2.x*(1.f - wwv*er2.x) + wwv*wv2.x;
                m2.y = m2.y*(1.f - wwv*er2.y) + wwv*wv2.y;
                *(float2*)&M_s[n*MP+w] = m2;
            }
            for (int i2=tid; i2<N_*N_/2; i2+=THR){
                int n = i2>>6, mp2 = i2&63;
                int m = 2*mp2;
                float2 l2 = *(const float2*)&L_s[n*LP+m];
                float2 p2 = *(const float2*)&p_s[m];
                float a = 1.f - wwn[n];
                float wn = wwn[n];
                l2.x = (n==m  ) ? 0.f : (a - wwn[m  ])*l2.x + wn*p2.x;
                l2.y = (n==m+1) ? 0.f : (a - wwn[m+1])*l2.y + wn*p2.y;
                *(float2*)&L_s[n*LP+m] = l2;
            }
            __syncthreads();
            if (tid < N_) p_s[tid] = (1.f - sumww)*p_s[tid] + wwn[tid];

            // ---- MERGED fwd/bwd + read-content partials ----
            {
                float f0=0.f,f1=0.f,f2=0.f,f3=0.f, b0=0.f,b1=0.f,b2=0.f,b3=0.f;
                const int m0 = dp*32;
                #pragma unroll 4
                for (int mp2=0; mp2<16; mp2++){
                    int m = m0 + 2*mp2;
                    float2 lr = *(const float2*)&L_s[dn*LP+m];
                    float lc0 = L_s[m*LP+dn], lc1 = L_s[(m+1)*LP+dn];
                    float4 wa = *(const float4*)&wrT[m*4];
                    float4 wb2 = *(const float4*)&wrT[(m+1)*4];
                    f0 += lr.x*wa.x + lr.y*wb2.x; f1 += lr.x*wa.y + lr.y*wb2.y;
                    f2 += lr.x*wa.z + lr.y*wb2.z; f3 += lr.x*wa.w + lr.y*wb2.w;
                    b0 += lc0*wa.x + lc1*wb2.x;   b1 += lc0*wa.y + lc1*wb2.y;
                    b2 += lc0*wa.z + lc1*wb2.z;   b3 += lc0*wa.w + lc1*wb2.w;
                }
                float* fb = P + dp*1024;
                fb[      dn]=f0; fb[128+dn]=f1; fb[256+dn]=f2; fb[384+dn]=f3;
                fb[512+dn]=b0; fb[640+dn]=b1; fb[768+dn]=b2; fb[896+dn]=b3;

                float s2=0.f, d0=0.f,d1=0.f,d2=0.f,d3=0.f;
                const int w0 = dp*16;
                #pragma unroll
                for (int wp=0; wp<8; wp++){
                    int w = w0 + 2*wp;
                    float2 m2 = *(const float2*)&M_s[dn*MP+w];
                    s2 += m2.x*m2.x + m2.y*m2.y;
                    float4 ra = *(const float4*)&rkT[w*4];
                    float4 rb2 = *(const float4*)&rkT[(w+1)*4];
                    d0 += m2.x*ra.x + m2.y*rb2.x; d1 += m2.x*ra.y + m2.y*rb2.y;
                    d2 += m2.x*ra.z + m2.y*rb2.z; d3 += m2.x*ra.w + m2.y*rb2.w;
                }
                float* rc = P + 4096 + dp*640;
                rc[      dn]=d0; rc[128+dn]=d1; rc[256+dn]=d2; rc[384+dn]=d3;
                rc[512+dn]=s2;
            }
            __syncthreads();
            {
                float fs = P[0*1024 + dp*128 + dn] + P[1*1024 + dp*128 + dn]
                         + P[2*1024 + dp*128 + dn] + P[3*1024 + dp*128 + dn];
                float bs = P[0*1024 + 512 + dp*128 + dn] + P[1*1024 + 512 + dp*128 + dn]
                         + P[2*1024 + 512 + dp*128 + dn] + P[3*1024 + 512 + dp*128 + dn];
                fwdw[dp*128 + dn] = fs;
                bwdw[dp*128 + dn] = bs;
                float d = P[4096 + 0*640 + dp*128 + dn] + P[4096 + 1*640 + dp*128 + dn]
                        + P[4096 + 2*640 + dp*128 + dn] + P[4096 + 3*640 + dp*128 + dn];
                float s2 = P[4096 + 0*640 + 512 + dn] + P[4096 + 1*640 + 512 + dn]
                         + P[4096 + 2*640 + 512 + dn] + P[4096 + 3*640 + 512 + dn];
                float mn = sqrtf(s2);
                float raw = act[dp]*(d/(act[156+dp]*mn + EPSF));
                crs[dp*128 + dn] = expf(raw);
            }
            __syncthreads();
            if (tid < 128){
                int r = tid>>5, ln = tid&31;
                float s = crs[r*N_+ln] + crs[r*N_+ln+32] + crs[r*N_+ln+64] + crs[r*N_+ln+96];
                #pragma unroll
                for (int o=16;o;o>>=1) s += __shfl_xor_sync(0xffffffffu, s, o);
                if (ln==0) act[168+r]=s;
            }
            __syncthreads();
            {
                int i = dp*128 + dn;
                float w = act[144+dp*3]*bwdw[i] + act[145+dp*3]*(crs[i]/act[168+dp]) + act[146+dp*3]*fwdw[i];
                crs[i] = w;
                crsT[dn*4 + dp] = w;
            }
            __syncthreads();
            // ---- rv partials ----
            {
                int w = tid & 63, part = tid >> 6;
                float s0=0.f,s1=0.f,s2v=0.f,s3=0.f;
                const int n0 = part*16;
                #pragma unroll
                for (int n=n0;n<n0+16;n++){
                    float mv = M_s[n*MP+w];
                    float4 c4 = *(const float4*)(crsT + n*4);
                    s0 += c4.x*mv; s1 += c4.y*mv; s2v += c4.z*mv; s3 += c4.w*mv;
                }
                float* rv = P + part*256;
                rv[      w]=s0; rv[ 64+w]=s1; rv[128+w]=s2v; rv[192+w]=s3;
            }
            __syncthreads();
            if (tid < 256){
                int r = tid >> 6, w = tid & 63;
                float s = 0.f;
                #pragma unroll
                for (int part=0;part<8;part++) s += P[part*256 + r*64 + w];
                int idx = r*WD_ + w;
                g_rvT[idx*B_ + b] = s;
                size_t btrow = (size_t)b*T_ + t;
                __nv_bfloat16 sh = __float2bfloat16(s);
                g_Uhi[btrow*KU + H_ + idx] = sh;
                g_Ulo[btrow*KU + H_ + idx] = __float2bfloat16(s - __bfloat162float(sh));
            }
            __syncthreads();
            wr_s[tid] = crs[tid];
            if (tid < N_){ u_s[tid]=unew[tid]; ww_s[tid]=wwn[tid]; }
        }
        gridbar(++ep);
    }
}

// ---------------- launcher ----------------
extern "C" void kernel_launch(void* const* d_in, const int* in_sizes, int n_in,
                              void* d_out, int out_size){
    const int*   tokens  = (const int*)  d_in[0];
    const float* emb     = (const float*)d_in[1];
    const float* w_ih    = (const float*)d_in[2];
    const float* w_hh    = (const float*)d_in[3];
    const float* b_lstm  = (const float*)d_in[4];
    const float* W_iface = (const float*)d_in[5];
    const float* b_iface = (const float*)d_in[6];
    const float* W_out   = (const float*)d_in[7];
    const float* b_out   = (const float*)d_in[8];
    float* out = (float*)d_out;

    const int loop_smem = LOOP_SMEM_FLOATS * (int)sizeof(float);
    cudaFuncSetAttribute(loop_kernel, cudaFuncAttributeMaxDynamicSharedMemorySize, loop_smem);
    const int gout_smem = 8 * TILE_BF * (int)sizeof(__nv_bfloat16);
    cudaFuncSetAttribute(gemm_out, cudaFuncAttributeMaxDynamicSharedMemorySize, gout_smem);

    void *pX, *pG0, *pWihT, *pBl;
    cudaGetSymbolAddress(&pX, g_X);
    cudaGetSymbolAddress(&pG0, g_G0);
    cudaGetSymbolAddress(&pWihT, g_WihT);
    cudaGetSymbolAddress(&pBl, g_bl);

    embed_kernel<<<(BT_*E_ + 255)/256, 256>>>(tokens, emb);
    prep_w<<<(KU*G4H + 255)/256, 256>>>(w_ih, w_hh, b_lstm);
    sgemm128<<<dim3(G4H/128, BT_/128), 256>>>((const float*)pX, (const float*)pWihT,
                                              (const float*)pBl, (float*)pG0, BT_, G4H, E_);
    loop_kernel<<<NBLK, THR, loop_smem>>>(W_iface, b_iface);
    prep_outT<<<dim3(VPAD/32, KU/32), dim3(32,8)>>>(W_out);
    gemm_out<<<dim3((V_+127)/128, BT_/128), 256, gout_smem>>>(b_out, out);
}